// round 1
// baseline (speedup 1.0000x reference)
#include <cuda_runtime.h>
#include <cuda_bf16.h>
#include <math.h>

// Problem constants
#define E_DIM   1024
#define N_HEADS 16
#define H_DIM   64
#define BATCH   4
#define SQ      1024
#define SKV     2048
#define MQ      (BATCH * SQ)    // 4096
#define MKV     (BATCH * SKV)   // 8192

// Scratch (allocation-free rule: __device__ globals)
__device__ float g_q[MQ * E_DIM];
__device__ float g_k[MKV * E_DIM];
__device__ float g_v[MKV * E_DIM];
__device__ float g_attn[MQ * E_DIM];

// ---------------------------------------------------------------------------
// SGEMM: C[M,1024] = A[M,1024] @ W[1024,1024]^T + bias
// Both A and W are row-major with K (=1024) contiguous -> NT GEMM.
// 128x128 tile, BK=8, 256 threads, 8x8 micro-tile per thread.
// ---------------------------------------------------------------------------
__global__ void __launch_bounds__(256) sgemm_bias_nt(
    const float* __restrict__ A, const float* __restrict__ W,
    const float* __restrict__ bias, float* __restrict__ C)
{
    __shared__ float As[8][128];
    __shared__ float Bs[8][128];

    const int tid = threadIdx.x;
    const int m0 = blockIdx.y * 128;
    const int n0 = blockIdx.x * 128;

    const int lr  = tid >> 1;        // 0..127  (row within tile)
    const int lc4 = (tid & 1) * 4;   // 0 or 4  (k offset)

    const float* Ag = A + (size_t)(m0 + lr) * E_DIM + lc4;
    const float* Wg = W + (size_t)(n0 + lr) * E_DIM + lc4;

    const int tx = tid & 15;
    const int ty = tid >> 4;

    float acc[8][8];
#pragma unroll
    for (int i = 0; i < 8; i++)
#pragma unroll
        for (int j = 0; j < 8; j++) acc[i][j] = 0.f;

    float4 a4 = *(const float4*)Ag;
    float4 b4 = *(const float4*)Wg;

    for (int k0 = 0; k0 < E_DIM; k0 += 8) {
        As[lc4 + 0][lr] = a4.x; As[lc4 + 1][lr] = a4.y;
        As[lc4 + 2][lr] = a4.z; As[lc4 + 3][lr] = a4.w;
        Bs[lc4 + 0][lr] = b4.x; Bs[lc4 + 1][lr] = b4.y;
        Bs[lc4 + 2][lr] = b4.z; Bs[lc4 + 3][lr] = b4.w;
        __syncthreads();

        if (k0 < E_DIM - 8) {
            a4 = *(const float4*)(Ag + k0 + 8);
            b4 = *(const float4*)(Wg + k0 + 8);
        }

#pragma unroll
        for (int k = 0; k < 8; k++) {
            float a[8], bb[8];
            *(float4*)&a[0]  = *(const float4*)&As[k][ty * 8];
            *(float4*)&a[4]  = *(const float4*)&As[k][ty * 8 + 4];
            *(float4*)&bb[0] = *(const float4*)&Bs[k][tx * 8];
            *(float4*)&bb[4] = *(const float4*)&Bs[k][tx * 8 + 4];
#pragma unroll
            for (int i = 0; i < 8; i++)
#pragma unroll
                for (int j = 0; j < 8; j++)
                    acc[i][j] = fmaf(a[i], bb[j], acc[i][j]);
        }
        __syncthreads();
    }

    // epilogue: add bias, store
    float bfrag[8];
#pragma unroll
    for (int j = 0; j < 8; j++) bfrag[j] = bias[n0 + tx * 8 + j];

#pragma unroll
    for (int i = 0; i < 8; i++) {
        float* Cg = C + (size_t)(m0 + ty * 8 + i) * E_DIM + n0 + tx * 8;
        float4 r0, r1;
        r0.x = acc[i][0] + bfrag[0]; r0.y = acc[i][1] + bfrag[1];
        r0.z = acc[i][2] + bfrag[2]; r0.w = acc[i][3] + bfrag[3];
        r1.x = acc[i][4] + bfrag[4]; r1.y = acc[i][5] + bfrag[5];
        r1.z = acc[i][6] + bfrag[6]; r1.w = acc[i][7] + bfrag[7];
        *(float4*)(Cg)     = r0;
        *(float4*)(Cg + 4) = r1;
    }
}

// ---------------------------------------------------------------------------
// Flash attention: one CTA per (b, h, 64-row q tile). KV chunks of 64.
// Q pre-scaled by 1/sqrt(64). Online softmax. D = 64.
// Layouts in smem (pitch 68 to dodge bank conflicts):
//   Qt[d][q], Kt[d][kv]  (d-major, so S-compute reads are contiguous)
//   Vs[kv][d]            (for PV, b-frag contiguous)
//   Pt[kv][q]            (P transposed, so PV a-frag contiguous)
// ---------------------------------------------------------------------------
#define PITCH 68
#define NEG_BIG (-3.0e38f)

__global__ void __launch_bounds__(256) attn_kernel(
    const float* __restrict__ Q, const float* __restrict__ K,
    const float* __restrict__ V, float* __restrict__ O)
{
    extern __shared__ float sm[];
    float* Qt   = sm;                   // 64*68
    float* Kt   = Qt + 64 * PITCH;      // 64*68
    float* Vs   = Kt + 64 * PITCH;      // 64*68
    float* Pt   = Vs + 64 * PITCH;      // 64*68
    float* m_s  = Pt + 64 * PITCH;      // 64
    float* l_s  = m_s + 64;             // 64
    float* al_s = l_s + 64;             // 64

    const int b  = blockIdx.z;
    const int h  = blockIdx.y;
    const int q0 = blockIdx.x * 64;
    const int tid = threadIdx.x;
    const int tx = tid & 15;
    const int ty = tid >> 4;

    // Load Q tile (scaled, transposed to Qt[d][q])
    {
        const int q  = tid >> 2;           // 0..63
        const int d0 = (tid & 3) * 16;     // 0,16,32,48
        const float* qg = Q + (size_t)(b * SQ + q0 + q) * E_DIM + h * H_DIM + d0;
#pragma unroll
        for (int i = 0; i < 16; i += 4) {
            float4 v4 = *(const float4*)(qg + i);
            Qt[(d0 + i + 0) * PITCH + q] = v4.x * 0.125f;
            Qt[(d0 + i + 1) * PITCH + q] = v4.y * 0.125f;
            Qt[(d0 + i + 2) * PITCH + q] = v4.z * 0.125f;
            Qt[(d0 + i + 3) * PITCH + q] = v4.w * 0.125f;
        }
    }
    if (tid < 64) { m_s[tid] = NEG_BIG; l_s[tid] = 0.f; }

    float o[4][4];
#pragma unroll
    for (int i = 0; i < 4; i++)
#pragma unroll
        for (int j = 0; j < 4; j++) o[i][j] = 0.f;

    for (int c = 0; c < SKV; c += 64) {
        __syncthreads();  // prev iter's Pt/Vs reads done; Qt/m_s init visible

        // Load K chunk (transposed) and V chunk
        {
            const int r  = tid >> 2;
            const int d0 = (tid & 3) * 16;
            const float* kg = K + (size_t)(b * SKV + c + r) * E_DIM + h * H_DIM + d0;
            const float* vg = V + (size_t)(b * SKV + c + r) * E_DIM + h * H_DIM + d0;
#pragma unroll
            for (int i = 0; i < 16; i += 4) {
                float4 k4 = *(const float4*)(kg + i);
                Kt[(d0 + i + 0) * PITCH + r] = k4.x;
                Kt[(d0 + i + 1) * PITCH + r] = k4.y;
                Kt[(d0 + i + 2) * PITCH + r] = k4.z;
                Kt[(d0 + i + 3) * PITCH + r] = k4.w;
                float4 v4 = *(const float4*)(vg + i);
                *(float4*)&Vs[r * PITCH + d0 + i] = v4;
            }
        }
        __syncthreads();

        // S = Q @ K^T  (q = 4*ty+i, kv = 4*tx+j)
        float s[4][4];
#pragma unroll
        for (int i = 0; i < 4; i++)
#pragma unroll
            for (int j = 0; j < 4; j++) s[i][j] = 0.f;

#pragma unroll 4
        for (int d = 0; d < H_DIM; d++) {
            float a[4], bb[4];
            *(float4*)a  = *(const float4*)&Qt[d * PITCH + 4 * ty];
            *(float4*)bb = *(const float4*)&Kt[d * PITCH + 4 * tx];
#pragma unroll
            for (int i = 0; i < 4; i++)
#pragma unroll
                for (int j = 0; j < 4; j++)
                    s[i][j] = fmaf(a[i], bb[j], s[i][j]);
        }

        // write S transposed: Pt[kv][q]
#pragma unroll
        for (int j = 0; j < 4; j++)
#pragma unroll
            for (int i = 0; i < 4; i++)
                Pt[(4 * tx + j) * PITCH + 4 * ty + i] = s[i][j];
        __syncthreads();

        // Online softmax over rows. 4 threads per row, 16 cols each.
        {
            const int q = tid >> 2;
            const int t = tid & 3;
            float mx = NEG_BIG;
#pragma unroll
            for (int kk = 0; kk < 16; kk++)
                mx = fmaxf(mx, Pt[(t * 16 + kk) * PITCH + q]);
            mx = fmaxf(mx, __shfl_xor_sync(0xffffffffu, mx, 1));
            mx = fmaxf(mx, __shfl_xor_sync(0xffffffffu, mx, 2));
            const float m_old = m_s[q];
            const float m_new = fmaxf(m_old, mx);
            const float alpha = __expf(m_old - m_new);
            float lsum = 0.f;
#pragma unroll
            for (int kk = 0; kk < 16; kk++) {
                float* p = &Pt[(t * 16 + kk) * PITCH + q];
                float e = __expf(*p - m_new);
                *p = e;
                lsum += e;
            }
            lsum += __shfl_xor_sync(0xffffffffu, lsum, 1);
            lsum += __shfl_xor_sync(0xffffffffu, lsum, 2);
            if (t == 0) {
                m_s[q]  = m_new;
                l_s[q]  = l_s[q] * alpha + lsum;
                al_s[q] = alpha;
            }
        }
        __syncthreads();

        // Rescale O and accumulate P @ V  (q = 4*ty+i, d = 4*tx+j)
        {
            float alph[4];
#pragma unroll
            for (int i = 0; i < 4; i++) alph[i] = al_s[4 * ty + i];
#pragma unroll
            for (int i = 0; i < 4; i++)
#pragma unroll
                for (int j = 0; j < 4; j++) o[i][j] *= alph[i];

#pragma unroll 4
            for (int kv = 0; kv < 64; kv++) {
                float a[4], bb[4];
                *(float4*)a  = *(const float4*)&Pt[kv * PITCH + 4 * ty];
                *(float4*)bb = *(const float4*)&Vs[kv * PITCH + 4 * tx];
#pragma unroll
                for (int i = 0; i < 4; i++)
#pragma unroll
                    for (int j = 0; j < 4; j++)
                        o[i][j] = fmaf(a[i], bb[j], o[i][j]);
            }
        }
    }
    __syncthreads();

    // Write out: O[b, q0+q, h*64 + d] = o / l
#pragma unroll
    for (int i = 0; i < 4; i++) {
        const int q = 4 * ty + i;
        const float inv = 1.f / l_s[q];
        float4 r;
        r.x = o[i][0] * inv; r.y = o[i][1] * inv;
        r.z = o[i][2] * inv; r.w = o[i][3] * inv;
        float* og = O + (size_t)(b * SQ + q0 + q) * E_DIM + h * H_DIM + 4 * tx;
        *(float4*)og = r;
    }
}

// ---------------------------------------------------------------------------
extern "C" void kernel_launch(void* const* d_in, const int* in_sizes, int n_in,
                              void* d_out, int out_size)
{
    const float* x1 = (const float*)d_in[0];
    const float* x2 = (const float*)d_in[1];
    const float* Wq = (const float*)d_in[2];
    const float* bq = (const float*)d_in[3];
    const float* Wk = (const float*)d_in[4];
    const float* bk = (const float*)d_in[5];
    const float* Wv = (const float*)d_in[6];
    const float* bv = (const float*)d_in[7];
    const float* Wo = (const float*)d_in[8];
    const float* bo = (const float*)d_in[9];
    float* out = (float*)d_out;

    float *q_ptr, *k_ptr, *v_ptr, *attn_ptr;
    cudaGetSymbolAddress((void**)&q_ptr,    g_q);
    cudaGetSymbolAddress((void**)&k_ptr,    g_k);
    cudaGetSymbolAddress((void**)&v_ptr,    g_v);
    cudaGetSymbolAddress((void**)&attn_ptr, g_attn);

    const int attn_smem = (4 * 64 * PITCH + 3 * 64) * sizeof(float);  // ~70.4 KB
    cudaFuncSetAttribute(attn_kernel, cudaFuncAttributeMaxDynamicSharedMemorySize,
                         attn_smem);

    dim3 blk(256);
    // Projections
    sgemm_bias_nt<<<dim3(8, MQ  / 128), blk>>>(x1, Wq, bq, q_ptr);
    sgemm_bias_nt<<<dim3(8, MKV / 128), blk>>>(x2, Wk, bk, k_ptr);
    sgemm_bias_nt<<<dim3(8, MKV / 128), blk>>>(x2, Wv, bv, v_ptr);

    // Attention
    attn_kernel<<<dim3(SQ / 64, N_HEADS, BATCH), blk, attn_smem>>>(
        q_ptr, k_ptr, v_ptr, attn_ptr);

    // Output projection
    sgemm_bias_nt<<<dim3(8, MQ / 128), blk>>>(attn_ptr, Wo, bo, out);
}

// round 3
// speedup vs baseline: 1.3990x; 1.3990x over previous
#include <cuda_runtime.h>
#include <cuda_bf16.h>
#include <cstdint>
#include <math.h>

// Problem constants
#define E_DIM   1024
#define N_HEADS 16
#define H_DIM   64
#define BATCH   4
#define SQ      1024
#define SKV     2048
#define MQ      (BATCH * SQ)    // 4096
#define MKV     (BATCH * SKV)   // 8192

// Scratch (allocation-free rule: __device__ globals)
__device__ float g_q[MQ * E_DIM];
__device__ float g_k[MKV * E_DIM];
__device__ float g_v[MKV * E_DIM];
__device__ float g_attn[MQ * E_DIM];

// ---------------------------------------------------------------------------
// Helpers
// ---------------------------------------------------------------------------
#define SMEM_SWIZZLE_128B(byte_offset) \
    ((byte_offset) ^ (((byte_offset) >> 3) & 0x70))

// packed fp32x2 helpers
#define FMA2(d_,a_,b_,c_) asm("fma.rn.f32x2 %0, %1, %2, %3;" : "=l"(d_) : "l"(a_), "l"(b_), "l"(c_))
#define MUL2(d_,a_,b_)    asm("mul.rn.f32x2 %0, %1, %2;" : "=l"(d_) : "l"(a_), "l"(b_))
#define DUP2(d_,x_)       asm("mov.b64 %0, {%1, %1};" : "=l"(d_) : "r"(__float_as_uint(x_)))
#define UNPK2(lo_,hi_,v_) asm("mov.b64 {%0, %1}, %2;" : "=r"(lo_), "=r"(hi_) : "l"(v_))
#define LDSV2B64(b0_,b1_,addr_) \
    asm volatile("ld.shared.v2.b64 {%0, %1}, [%2];" : "=l"(b0_), "=l"(b1_) : "r"(addr_))

#define LDSM_X4(r0_,r1_,r2_,r3_,addr_) \
    asm volatile("ldmatrix.sync.aligned.m8n8.x4.shared.b16 {%0,%1,%2,%3}, [%4];" \
        : "=r"(r0_), "=r"(r1_), "=r"(r2_), "=r"(r3_) : "r"(addr_))

#define MMA16816(d_,a_,b_) \
    asm volatile("mma.sync.aligned.m16n8k16.row.col.f32.bf16.bf16.f32 " \
        "{%0,%1,%2,%3}, {%4,%5,%6,%7}, {%8,%9}, {%0,%1,%2,%3};" \
        : "+f"((d_)[0]), "+f"((d_)[1]), "+f"((d_)[2]), "+f"((d_)[3]) \
        : "r"((a_)[0]), "r"((a_)[1]), "r"((a_)[2]), "r"((a_)[3]), \
          "r"((b_)[0]), "r"((b_)[1]))

// ---------------------------------------------------------------------------
// bf16x3 tensor-core GEMM via mma.sync (HMMA):
//   C[M,1024] = A[M,1024] @ W[1024,1024]^T + bias  (fp32 in/out)
// A,W row-major K-contiguous -> row.col NT mma.
// 128x128 CTA tile, K-chunk 64 (bf16, SW128 swizzled smem rows of 128B).
// bf16 hi/lo split: D += Ah*Bh + Ah*Bl + Al*Bh  (drop lo*lo ~2^-18)
// 8 warps: 2(M) x 4(N), warp tile 64x32 = 4x4 m16n8k16 atoms.
// ---------------------------------------------------------------------------
#define G_OFF_AHI   0
#define G_OFF_ALO   16384
#define G_OFF_BHI   32768
#define G_OFF_BLO   49152
#define G_SMEM      65536
#define G_NCHUNK    16              // 1024 / 64

__device__ __forceinline__ void cvt8(const float4 f0, const float4 f1,
                                     uint4& hi, uint4& lo) {
    float v[8] = {f0.x, f0.y, f0.z, f0.w, f1.x, f1.y, f1.z, f1.w};
    uint32_t h[8], l[8];
#pragma unroll
    for (int i = 0; i < 8; i++) {
        __nv_bfloat16 hb = __float2bfloat16_rn(v[i]);
        float hf = __bfloat162float(hb);
        __nv_bfloat16 lb = __float2bfloat16_rn(v[i] - hf);
        h[i] = *(unsigned short*)&hb;
        l[i] = *(unsigned short*)&lb;
    }
    hi.x = h[0] | (h[1] << 16); hi.y = h[2] | (h[3] << 16);
    hi.z = h[4] | (h[5] << 16); hi.w = h[6] | (h[7] << 16);
    lo.x = l[0] | (l[1] << 16); lo.y = l[2] | (l[3] << 16);
    lo.z = l[4] | (l[5] << 16); lo.w = l[6] | (l[7] << 16);
}

__global__ void __launch_bounds__(256) gemm_mma(
    const float* __restrict__ A, const float* __restrict__ W,
    const float* __restrict__ bias, float* __restrict__ C)
{
    extern __shared__ char smem[];
    const uint32_t sb = (uint32_t)__cvta_generic_to_shared(smem);
    const int tid  = threadIdx.x;
    const int wid  = tid >> 5;
    const int lane = tid & 31;
    const int m0 = blockIdx.y * 128;
    const int n0 = blockIdx.x * 128;

    const int warp_m = (wid & 1) * 64;
    const int warp_n = (wid >> 1) * 32;

    const int g = lane >> 3;   // ldmatrix group 0..3
    const int r = lane & 7;    // row within 8x8 matrix

    float acc[4][4][4];        // [mi][ni][reg]
#pragma unroll
    for (int mi = 0; mi < 4; mi++)
#pragma unroll
        for (int ni = 0; ni < 4; ni++)
#pragma unroll
            for (int q = 0; q < 4; q++) acc[mi][ni][q] = 0.f;

    // Precompute per-lane ldmatrix byte offsets (within tile, before swizzle k-part)
    // A matrices: m0:rows0-7/k-lo, m1:rows8-15/k-lo, m2:rows0-7/k-hi, m3:rows8-15/k-hi
    const int a_row = warp_m + (g & 1) * 8 + r;       // + mi*16
    const int a_kc  = (g >> 1) * 8;                   // + ks*16   (bf16 cols)
    // B matrices: m0:n0-7/k-lo, m1:n0-7/k-hi, m2:n8-15/k-lo, m3:n8-15/k-hi
    const int b_row = warp_n + (g >> 1) * 8 + r;      // + np*16
    const int b_kc  = (g & 1) * 8;                    // + ks*16

    const float* Abase = A + (size_t)m0 * E_DIM;
    const float* Wbase = W + (size_t)n0 * E_DIM;

    for (int ch = 0; ch < G_NCHUNK; ch++) {
        if (ch) __syncthreads();   // prior reads of smem done

        // ---- load & convert chunk: 128 rows x 64 fp32 -> bf16 hi/lo (swizzled)
        const float* Ap = Abase + ch * 64;
        const float* Wp = Wbase + ch * 64;
#pragma unroll
        for (int it = 0; it < 4; it++) {
            const int gidx = it * 256 + tid;      // 0..1023
            const int row = gidx >> 3;            // 0..127
            const int c8  = (gidx & 7) * 8;       // bf16 col 0..56
            const uint32_t sw = SMEM_SWIZZLE_128B((uint32_t)(row * 128 + c8 * 2));
            {
                float4 a0 = *(const float4*)(Ap + (size_t)row * E_DIM + c8);
                float4 a1 = *(const float4*)(Ap + (size_t)row * E_DIM + c8 + 4);
                uint4 hi, lo; cvt8(a0, a1, hi, lo);
                *(uint4*)(smem + G_OFF_AHI + sw) = hi;
                *(uint4*)(smem + G_OFF_ALO + sw) = lo;
            }
            {
                float4 b0 = *(const float4*)(Wp + (size_t)row * E_DIM + c8);
                float4 b1 = *(const float4*)(Wp + (size_t)row * E_DIM + c8 + 4);
                uint4 hi, lo; cvt8(b0, b1, hi, lo);
                *(uint4*)(smem + G_OFF_BHI + sw) = hi;
                *(uint4*)(smem + G_OFF_BLO + sw) = lo;
            }
        }
        __syncthreads();

        // ---- compute: 4 k-steps of 16
#pragma unroll
        for (int ks = 0; ks < 4; ks++) {
            uint32_t ah[4][4], al[4][4];
#pragma unroll
            for (int mi = 0; mi < 4; mi++) {
                const uint32_t byte = (uint32_t)((a_row + mi * 16) * 128
                                                 + (a_kc + ks * 16) * 2);
                const uint32_t sw = SMEM_SWIZZLE_128B(byte);
                LDSM_X4(ah[mi][0], ah[mi][1], ah[mi][2], ah[mi][3],
                        sb + G_OFF_AHI + sw);
                LDSM_X4(al[mi][0], al[mi][1], al[mi][2], al[mi][3],
                        sb + G_OFF_ALO + sw);
            }
            uint32_t bh[4][2], bl[4][2];
#pragma unroll
            for (int np = 0; np < 2; np++) {
                const uint32_t byte = (uint32_t)((b_row + np * 16) * 128
                                                 + (b_kc + ks * 16) * 2);
                const uint32_t sw = SMEM_SWIZZLE_128B(byte);
                LDSM_X4(bh[2 * np][0], bh[2 * np][1], bh[2 * np + 1][0], bh[2 * np + 1][1],
                        sb + G_OFF_BHI + sw);
                LDSM_X4(bl[2 * np][0], bl[2 * np][1], bl[2 * np + 1][0], bl[2 * np + 1][1],
                        sb + G_OFF_BLO + sw);
            }
#pragma unroll
            for (int mi = 0; mi < 4; mi++)
#pragma unroll
                for (int ni = 0; ni < 4; ni++) {
                    MMA16816(acc[mi][ni], ah[mi], bh[ni]);   // hi*hi
                    MMA16816(acc[mi][ni], ah[mi], bl[ni]);   // hi*lo
                    MMA16816(acc[mi][ni], al[mi], bh[ni]);   // lo*hi
                }
        }
    }

    // ---- epilogue: bias + store
    const int erow = lane >> 2;          // 0..7
    const int ecol = (lane & 3) * 2;     // 0,2,4,6
#pragma unroll
    for (int ni = 0; ni < 4; ni++) {
        const int col = n0 + warp_n + ni * 8 + ecol;
        const float bv0 = __ldg(bias + col);
        const float bv1 = __ldg(bias + col + 1);
#pragma unroll
        for (int mi = 0; mi < 4; mi++) {
            const int row = m0 + warp_m + mi * 16 + erow;
            float2 v0, v1;
            v0.x = acc[mi][ni][0] + bv0; v0.y = acc[mi][ni][1] + bv1;
            v1.x = acc[mi][ni][2] + bv0; v1.y = acc[mi][ni][3] + bv1;
            *(float2*)(C + (size_t)row * E_DIM + col)       = v0;
            *(float2*)(C + (size_t)(row + 8) * E_DIM + col) = v1;
        }
    }
}

// ---------------------------------------------------------------------------
// Flash attention, fp32 with packed f32x2 FFMA2 inner loops.
// One CTA per (b, h, 64-row q tile). KV chunks of 64. Online softmax.
// ---------------------------------------------------------------------------
#define PITCH 68
#define NEG_BIG (-3.0e38f)

__global__ void __launch_bounds__(256) attn_kernel(
    const float* __restrict__ Q, const float* __restrict__ K,
    const float* __restrict__ V, float* __restrict__ O)
{
    extern __shared__ float sm[];
    float* Qt   = sm;                   // [64 d][68]
    float* Kt   = Qt + 64 * PITCH;      // [64 d][68]
    float* Vs   = Kt + 64 * PITCH;      // [64 kv][68]
    float* Pt   = Vs + 64 * PITCH;      // [64 kv][68]
    float* m_s  = Pt + 64 * PITCH;
    float* l_s  = m_s + 64;
    float* al_s = l_s + 64;

    const uint32_t sKt = (uint32_t)__cvta_generic_to_shared(Kt);
    const uint32_t sVs = (uint32_t)__cvta_generic_to_shared(Vs);

    const int b  = blockIdx.z;
    const int h  = blockIdx.y;
    const int q0 = blockIdx.x * 64;
    const int tid = threadIdx.x;
    const int tx = tid & 15;
    const int ty = tid >> 4;

    // Load Q tile (scaled by 1/8, transposed to Qt[d][q])
    {
        const int q  = tid >> 2;
        const int d0 = (tid & 3) * 16;
        const float* qg = Q + (size_t)(b * SQ + q0 + q) * E_DIM + h * H_DIM + d0;
#pragma unroll
        for (int i = 0; i < 16; i += 4) {
            float4 v4 = *(const float4*)(qg + i);
            Qt[(d0 + i + 0) * PITCH + q] = v4.x * 0.125f;
            Qt[(d0 + i + 1) * PITCH + q] = v4.y * 0.125f;
            Qt[(d0 + i + 2) * PITCH + q] = v4.z * 0.125f;
            Qt[(d0 + i + 3) * PITCH + q] = v4.w * 0.125f;
        }
    }
    if (tid < 64) { m_s[tid] = NEG_BIG; l_s[tid] = 0.f; }

    unsigned long long o2[4][2];
#pragma unroll
    for (int i = 0; i < 4; i++) { o2[i][0] = 0ull; o2[i][1] = 0ull; }

    for (int c = 0; c < SKV; c += 64) {
        __syncthreads();

        // Load K chunk (transposed) and V chunk
        {
            const int rr = tid >> 2;
            const int d0 = (tid & 3) * 16;
            const float* kg = K + (size_t)(b * SKV + c + rr) * E_DIM + h * H_DIM + d0;
            const float* vg = V + (size_t)(b * SKV + c + rr) * E_DIM + h * H_DIM + d0;
#pragma unroll
            for (int i = 0; i < 16; i += 4) {
                float4 k4 = *(const float4*)(kg + i);
                Kt[(d0 + i + 0) * PITCH + rr] = k4.x;
                Kt[(d0 + i + 1) * PITCH + rr] = k4.y;
                Kt[(d0 + i + 2) * PITCH + rr] = k4.z;
                Kt[(d0 + i + 3) * PITCH + rr] = k4.w;
                float4 v4 = *(const float4*)(vg + i);
                *(float4*)&Vs[rr * PITCH + d0 + i] = v4;
            }
        }
        __syncthreads();

        // S = Q @ K^T, packed pairs along kv
        unsigned long long s2[4][2];
#pragma unroll
        for (int i = 0; i < 4; i++) { s2[i][0] = 0ull; s2[i][1] = 0ull; }

        {
            uint32_t kaddr = sKt + (uint32_t)(4 * tx) * 4u;
            const float* qa = &Qt[4 * ty];
#pragma unroll 4
            for (int d = 0; d < H_DIM; d++) {
                float4 af = *(const float4*)(qa + d * PITCH);
                unsigned long long b01, b23;
                LDSV2B64(b01, b23, kaddr + (uint32_t)(d * PITCH) * 4u);
                unsigned long long a0, a1, a2, a3;
                DUP2(a0, af.x); DUP2(a1, af.y); DUP2(a2, af.z); DUP2(a3, af.w);
                FMA2(s2[0][0], a0, b01, s2[0][0]); FMA2(s2[0][1], a0, b23, s2[0][1]);
                FMA2(s2[1][0], a1, b01, s2[1][0]); FMA2(s2[1][1], a1, b23, s2[1][1]);
                FMA2(s2[2][0], a2, b01, s2[2][0]); FMA2(s2[2][1], a2, b23, s2[2][1]);
                FMA2(s2[3][0], a3, b01, s2[3][0]); FMA2(s2[3][1], a3, b23, s2[3][1]);
            }
        }

        // unpack and write S transposed: Pt[kv][q]
#pragma unroll
        for (int i = 0; i < 4; i++) {
            uint32_t u0, u1, u2, u3;
            UNPK2(u0, u1, s2[i][0]);
            UNPK2(u2, u3, s2[i][1]);
            Pt[(4 * tx + 0) * PITCH + 4 * ty + i] = __uint_as_float(u0);
            Pt[(4 * tx + 1) * PITCH + 4 * ty + i] = __uint_as_float(u1);
            Pt[(4 * tx + 2) * PITCH + 4 * ty + i] = __uint_as_float(u2);
            Pt[(4 * tx + 3) * PITCH + 4 * ty + i] = __uint_as_float(u3);
        }
        __syncthreads();

        // Online softmax over rows. 4 threads per row, 16 cols each.
        {
            const int q = tid >> 2;
            const int t = tid & 3;
            float mx = NEG_BIG;
#pragma unroll
            for (int kk = 0; kk < 16; kk++)
                mx = fmaxf(mx, Pt[(t * 16 + kk) * PITCH + q]);
            mx = fmaxf(mx, __shfl_xor_sync(0xffffffffu, mx, 1));
            mx = fmaxf(mx, __shfl_xor_sync(0xffffffffu, mx, 2));
            const float m_old = m_s[q];
            const float m_new = fmaxf(m_old, mx);
            const float alpha = __expf(m_old - m_new);
            float lsum = 0.f;
#pragma unroll
            for (int kk = 0; kk < 16; kk++) {
                float* p = &Pt[(t * 16 + kk) * PITCH + q];
                float e = __expf(*p - m_new);
                *p = e;
                lsum += e;
            }
            lsum += __shfl_xor_sync(0xffffffffu, lsum, 1);
            lsum += __shfl_xor_sync(0xffffffffu, lsum, 2);
            if (t == 0) {
                m_s[q]  = m_new;
                l_s[q]  = l_s[q] * alpha + lsum;
                al_s[q] = alpha;
            }
        }
        __syncthreads();

        // Rescale O and accumulate P @ V (packed pairs along d)
        {
#pragma unroll
            for (int i = 0; i < 4; i++) {
                unsigned long long al2;
                DUP2(al2, al_s[4 * ty + i]);
                MUL2(o2[i][0], o2[i][0], al2);
                MUL2(o2[i][1], o2[i][1], al2);
            }
            uint32_t vaddr = sVs + (uint32_t)(4 * tx) * 4u;
            const float* pa = &Pt[4 * ty];
#pragma unroll 4
            for (int kv = 0; kv < 64; kv++) {
                float4 af = *(const float4*)(pa + kv * PITCH);
                unsigned long long b01, b23;
                LDSV2B64(b01, b23, vaddr + (uint32_t)(kv * PITCH) * 4u);
                unsigned long long a0, a1, a2, a3;
                DUP2(a0, af.x); DUP2(a1, af.y); DUP2(a2, af.z); DUP2(a3, af.w);
                FMA2(o2[0][0], a0, b01, o2[0][0]); FMA2(o2[0][1], a0, b23, o2[0][1]);
                FMA2(o2[1][0], a1, b01, o2[1][0]); FMA2(o2[1][1], a1, b23, o2[1][1]);
                FMA2(o2[2][0], a2, b01, o2[2][0]); FMA2(o2[2][1], a2, b23, o2[2][1]);
                FMA2(o2[3][0], a3, b01, o2[3][0]); FMA2(o2[3][1], a3, b23, o2[3][1]);
            }
        }
    }
    __syncthreads();

    // Write out: O[b, q0+q, h*64 + d] = o / l
#pragma unroll
    for (int i = 0; i < 4; i++) {
        const int q = 4 * ty + i;
        const float inv = 1.f / l_s[q];
        uint32_t u0, u1, u2, u3;
        UNPK2(u0, u1, o2[i][0]);
        UNPK2(u2, u3, o2[i][1]);
        float4 rr;
        rr.x = __uint_as_float(u0) * inv;
        rr.y = __uint_as_float(u1) * inv;
        rr.z = __uint_as_float(u2) * inv;
        rr.w = __uint_as_float(u3) * inv;
        float* og = O + (size_t)(b * SQ + q0 + q) * E_DIM + h * H_DIM + 4 * tx;
        *(float4*)og = rr;
    }
}

// ---------------------------------------------------------------------------
extern "C" void kernel_launch(void* const* d_in, const int* in_sizes, int n_in,
                              void* d_out, int out_size)
{
    const float* x1 = (const float*)d_in[0];
    const float* x2 = (const float*)d_in[1];
    const float* Wq = (const float*)d_in[2];
    const float* bq = (const float*)d_in[3];
    const float* Wk = (const float*)d_in[4];
    const float* bk = (const float*)d_in[5];
    const float* Wv = (const float*)d_in[6];
    const float* bv = (const float*)d_in[7];
    const float* Wo = (const float*)d_in[8];
    const float* bo = (const float*)d_in[9];
    float* out = (float*)d_out;

    float *q_ptr, *k_ptr, *v_ptr, *attn_ptr;
    cudaGetSymbolAddress((void**)&q_ptr,    g_q);
    cudaGetSymbolAddress((void**)&k_ptr,    g_k);
    cudaGetSymbolAddress((void**)&v_ptr,    g_v);
    cudaGetSymbolAddress((void**)&attn_ptr, g_attn);

    const int attn_smem = (4 * 64 * PITCH + 3 * 64) * sizeof(float);
    cudaFuncSetAttribute(attn_kernel, cudaFuncAttributeMaxDynamicSharedMemorySize,
                         attn_smem);
    cudaFuncSetAttribute(gemm_mma, cudaFuncAttributeMaxDynamicSharedMemorySize,
                         G_SMEM);

    dim3 blk(256);
    // Projections (HMMA bf16x3)
    gemm_mma<<<dim3(8, MQ  / 128), blk, G_SMEM>>>(x1, Wq, bq, q_ptr);
    gemm_mma<<<dim3(8, MKV / 128), blk, G_SMEM>>>(x2, Wk, bk, k_ptr);
    gemm_mma<<<dim3(8, MKV / 128), blk, G_SMEM>>>(x2, Wv, bv, v_ptr);

    // Attention
    attn_kernel<<<dim3(SQ / 64, N_HEADS, BATCH), blk, attn_smem>>>(
        q_ptr, k_ptr, v_ptr, attn_ptr);

    // Output projection
    gemm_mma<<<dim3(8, MQ / 128), blk, G_SMEM>>>(attn_ptr, Wo, bo, out);
}

// round 4
// speedup vs baseline: 2.3988x; 1.7147x over previous
#include <cuda_runtime.h>
#include <cuda_bf16.h>
#include <cstdint>
#include <math.h>

// Problem constants
#define E_DIM   1024
#define N_HEADS 16
#define H_DIM   64
#define BATCH   4
#define SQ      1024
#define SKV     2048
#define MQ      (BATCH * SQ)    // 4096
#define MKV     (BATCH * SKV)   // 8192

// Scratch (allocation-free rule: __device__ globals)
__device__ float g_q[MQ * E_DIM];
__device__ float g_k[MKV * E_DIM];
__device__ float g_v[MKV * E_DIM];
__device__ float g_attn[MQ * E_DIM];

// ---------------------------------------------------------------------------
// Helpers
// ---------------------------------------------------------------------------
#define SMEM_SWIZZLE_128B(byte_offset) \
    ((byte_offset) ^ (((byte_offset) >> 3) & 0x70))

#define LDSM_X4(r0_,r1_,r2_,r3_,addr_) \
    asm volatile("ldmatrix.sync.aligned.m8n8.x4.shared.b16 {%0,%1,%2,%3}, [%4];" \
        : "=r"(r0_), "=r"(r1_), "=r"(r2_), "=r"(r3_) : "r"(addr_))

#define LDSM_X4_T(r0_,r1_,r2_,r3_,addr_) \
    asm volatile("ldmatrix.sync.aligned.m8n8.x4.trans.shared.b16 {%0,%1,%2,%3}, [%4];" \
        : "=r"(r0_), "=r"(r1_), "=r"(r2_), "=r"(r3_) : "r"(addr_))

#define MMA16816(d_,a_,b_) \
    asm volatile("mma.sync.aligned.m16n8k16.row.col.f32.bf16.bf16.f32 " \
        "{%0,%1,%2,%3}, {%4,%5,%6,%7}, {%8,%9}, {%0,%1,%2,%3};" \
        : "+f"((d_)[0]), "+f"((d_)[1]), "+f"((d_)[2]), "+f"((d_)[3]) \
        : "r"((a_)[0]), "r"((a_)[1]), "r"((a_)[2]), "r"((a_)[3]), \
          "r"((b_)[0]), "r"((b_)[1]))

__device__ __forceinline__ uint32_t packbf2(float x, float y) {
    __nv_bfloat162 t = __floats2bfloat162_rn(x, y);
    return *(uint32_t*)&t;
}

__device__ __forceinline__ void cvt8(const float4 f0, const float4 f1,
                                     uint4& hi, uint4& lo) {
    float v[8] = {f0.x, f0.y, f0.z, f0.w, f1.x, f1.y, f1.z, f1.w};
    uint32_t h[8], l[8];
#pragma unroll
    for (int i = 0; i < 8; i++) {
        __nv_bfloat16 hb = __float2bfloat16_rn(v[i]);
        float hf = __bfloat162float(hb);
        __nv_bfloat16 lb = __float2bfloat16_rn(v[i] - hf);
        h[i] = *(unsigned short*)&hb;
        l[i] = *(unsigned short*)&lb;
    }
    hi.x = h[0] | (h[1] << 16); hi.y = h[2] | (h[3] << 16);
    hi.z = h[4] | (h[5] << 16); hi.w = h[6] | (h[7] << 16);
    lo.x = l[0] | (l[1] << 16); lo.y = l[2] | (l[3] << 16);
    lo.z = l[4] | (l[5] << 16); lo.w = l[6] | (l[7] << 16);
}

// ---------------------------------------------------------------------------
// bf16x3 tensor-core GEMM via mma.sync (HMMA):
//   C[M,1024] = A[M,1024] @ W[1024,1024]^T + bias  (fp32 in/out)
// ---------------------------------------------------------------------------
#define G_OFF_AHI   0
#define G_OFF_ALO   16384
#define G_OFF_BHI   32768
#define G_OFF_BLO   49152
#define G_SMEM      65536
#define G_NCHUNK    16              // 1024 / 64

__global__ void __launch_bounds__(256) gemm_mma(
    const float* __restrict__ A, const float* __restrict__ W,
    const float* __restrict__ bias, float* __restrict__ C)
{
    extern __shared__ char smem[];
    const uint32_t sb = (uint32_t)__cvta_generic_to_shared(smem);
    const int tid  = threadIdx.x;
    const int wid  = tid >> 5;
    const int lane = tid & 31;
    const int m0 = blockIdx.y * 128;
    const int n0 = blockIdx.x * 128;

    const int warp_m = (wid & 1) * 64;
    const int warp_n = (wid >> 1) * 32;

    const int g = lane >> 3;
    const int r = lane & 7;

    float acc[4][4][4];
#pragma unroll
    for (int mi = 0; mi < 4; mi++)
#pragma unroll
        for (int ni = 0; ni < 4; ni++)
#pragma unroll
            for (int q = 0; q < 4; q++) acc[mi][ni][q] = 0.f;

    const int a_row = warp_m + (g & 1) * 8 + r;
    const int a_kc  = (g >> 1) * 8;
    const int b_row = warp_n + (g >> 1) * 8 + r;
    const int b_kc  = (g & 1) * 8;

    const float* Abase = A + (size_t)m0 * E_DIM;
    const float* Wbase = W + (size_t)n0 * E_DIM;

    for (int ch = 0; ch < G_NCHUNK; ch++) {
        if (ch) __syncthreads();

        const float* Ap = Abase + ch * 64;
        const float* Wp = Wbase + ch * 64;
#pragma unroll
        for (int it = 0; it < 4; it++) {
            const int gidx = it * 256 + tid;
            const int row = gidx >> 3;
            const int c8  = (gidx & 7) * 8;
            const uint32_t sw = SMEM_SWIZZLE_128B((uint32_t)(row * 128 + c8 * 2));
            {
                float4 a0 = *(const float4*)(Ap + (size_t)row * E_DIM + c8);
                float4 a1 = *(const float4*)(Ap + (size_t)row * E_DIM + c8 + 4);
                uint4 hi, lo; cvt8(a0, a1, hi, lo);
                *(uint4*)(smem + G_OFF_AHI + sw) = hi;
                *(uint4*)(smem + G_OFF_ALO + sw) = lo;
            }
            {
                float4 b0 = *(const float4*)(Wp + (size_t)row * E_DIM + c8);
                float4 b1 = *(const float4*)(Wp + (size_t)row * E_DIM + c8 + 4);
                uint4 hi, lo; cvt8(b0, b1, hi, lo);
                *(uint4*)(smem + G_OFF_BHI + sw) = hi;
                *(uint4*)(smem + G_OFF_BLO + sw) = lo;
            }
        }
        __syncthreads();

#pragma unroll
        for (int ks = 0; ks < 4; ks++) {
            uint32_t ah[4][4], al[4][4];
#pragma unroll
            for (int mi = 0; mi < 4; mi++) {
                const uint32_t byte = (uint32_t)((a_row + mi * 16) * 128
                                                 + (a_kc + ks * 16) * 2);
                const uint32_t sw = SMEM_SWIZZLE_128B(byte);
                LDSM_X4(ah[mi][0], ah[mi][1], ah[mi][2], ah[mi][3],
                        sb + G_OFF_AHI + sw);
                LDSM_X4(al[mi][0], al[mi][1], al[mi][2], al[mi][3],
                        sb + G_OFF_ALO + sw);
            }
            uint32_t bh[4][2], bl[4][2];
#pragma unroll
            for (int np = 0; np < 2; np++) {
                const uint32_t byte = (uint32_t)((b_row + np * 16) * 128
                                                 + (b_kc + ks * 16) * 2);
                const uint32_t sw = SMEM_SWIZZLE_128B(byte);
                LDSM_X4(bh[2 * np][0], bh[2 * np][1], bh[2 * np + 1][0], bh[2 * np + 1][1],
                        sb + G_OFF_BHI + sw);
                LDSM_X4(bl[2 * np][0], bl[2 * np][1], bl[2 * np + 1][0], bl[2 * np + 1][1],
                        sb + G_OFF_BLO + sw);
            }
#pragma unroll
            for (int mi = 0; mi < 4; mi++)
#pragma unroll
                for (int ni = 0; ni < 4; ni++) {
                    MMA16816(acc[mi][ni], ah[mi], bh[ni]);
                    MMA16816(acc[mi][ni], ah[mi], bl[ni]);
                    MMA16816(acc[mi][ni], al[mi], bh[ni]);
                }
        }
    }

    const int erow = lane >> 2;
    const int ecol = (lane & 3) * 2;
#pragma unroll
    for (int ni = 0; ni < 4; ni++) {
        const int col = n0 + warp_n + ni * 8 + ecol;
        const float bv0 = __ldg(bias + col);
        const float bv1 = __ldg(bias + col + 1);
#pragma unroll
        for (int mi = 0; mi < 4; mi++) {
            const int row = m0 + warp_m + mi * 16 + erow;
            float2 v0, v1;
            v0.x = acc[mi][ni][0] + bv0; v0.y = acc[mi][ni][1] + bv1;
            v1.x = acc[mi][ni][2] + bv0; v1.y = acc[mi][ni][3] + bv1;
            *(float2*)(C + (size_t)row * E_DIM + col)       = v0;
            *(float2*)(C + (size_t)(row + 8) * E_DIM + col) = v1;
        }
    }
}

// ---------------------------------------------------------------------------
// Flash attention v2 on HMMA (bf16 hi/lo x3), fp32 softmax in registers.
// CTA = (b, h, 128 q rows); 8 warps, each owns 16 q rows. KV chunk = 64.
// ---------------------------------------------------------------------------
#define A_KHI   0          // 64*128B
#define A_KLO   8192
#define A_VHI   16384
#define A_VLO   24576
#define A_QHI   32768      // 128*128B
#define A_QLO   49152
#define ATT_SMEM 65536
#define NEG_BIG (-3.0e38f)

__global__ void __launch_bounds__(256) attn_mma(
    const float* __restrict__ Q, const float* __restrict__ K,
    const float* __restrict__ V, float* __restrict__ O)
{
    extern __shared__ char smem[];
    const uint32_t sb = (uint32_t)__cvta_generic_to_shared(smem);
    const int b  = blockIdx.z;
    const int h  = blockIdx.y;
    const int q0 = blockIdx.x * 128;
    const int tid  = threadIdx.x;
    const int wid  = tid >> 5;
    const int lane = tid & 31;
    const int g = lane >> 3;
    const int r = lane & 7;

    // ---- load Q tile 128x64, scale 1/8, convert hi/lo into smem
#pragma unroll
    for (int it = 0; it < 4; it++) {
        const int idx = it * 256 + tid;
        const int row = idx >> 3;
        const int c8  = (idx & 7) * 8;
        const float* qg = Q + (size_t)(b * SQ + q0 + row) * E_DIM + h * H_DIM + c8;
        float4 f0 = *(const float4*)qg;
        float4 f1 = *(const float4*)(qg + 4);
        f0.x *= 0.125f; f0.y *= 0.125f; f0.z *= 0.125f; f0.w *= 0.125f;
        f1.x *= 0.125f; f1.y *= 0.125f; f1.z *= 0.125f; f1.w *= 0.125f;
        uint4 hi, lo; cvt8(f0, f1, hi, lo);
        const uint32_t sw = SMEM_SWIZZLE_128B((uint32_t)(row * 128 + c8 * 2));
        *(uint4*)(smem + A_QHI + sw) = hi;
        *(uint4*)(smem + A_QLO + sw) = lo;
    }
    __syncthreads();

    // ---- per-warp Q fragments (kept in regs for whole kernel)
    const int a_row = wid * 16 + (g & 1) * 8 + r;
    const int a_kc  = (g >> 1) * 8;
    uint32_t qh[4][4], ql[4][4];
#pragma unroll
    for (int ks = 0; ks < 4; ks++) {
        const uint32_t sw = SMEM_SWIZZLE_128B((uint32_t)(a_row * 128 + (a_kc + ks * 16) * 2));
        LDSM_X4(qh[ks][0], qh[ks][1], qh[ks][2], qh[ks][3], sb + A_QHI + sw);
        LDSM_X4(ql[ks][0], ql[ks][1], ql[ks][2], ql[ks][3], sb + A_QLO + sw);
    }

    float o[8][4];
#pragma unroll
    for (int na = 0; na < 8; na++)
#pragma unroll
        for (int q = 0; q < 4; q++) o[na][q] = 0.f;
    float mr0 = NEG_BIG, mr1 = NEG_BIG, lr0 = 0.f, lr1 = 0.f;

    const int kb_row = (g >> 1) * 8 + r;   // + pair*16
    const int kb_kc  = (g & 1) * 8;        // + ks*16

    for (int c = 0; c < SKV; c += 64) {
        __syncthreads();
        // ---- load K,V chunk 64x64, convert hi/lo
#pragma unroll
        for (int it = 0; it < 2; it++) {
            const int idx = it * 256 + tid;
            const int row = idx >> 3;
            const int c8  = (idx & 7) * 8;
            const uint32_t sw = SMEM_SWIZZLE_128B((uint32_t)(row * 128 + c8 * 2));
            {
                const float* kg = K + (size_t)(b * SKV + c + row) * E_DIM + h * H_DIM + c8;
                float4 f0 = *(const float4*)kg;
                float4 f1 = *(const float4*)(kg + 4);
                uint4 hi, lo; cvt8(f0, f1, hi, lo);
                *(uint4*)(smem + A_KHI + sw) = hi;
                *(uint4*)(smem + A_KLO + sw) = lo;
            }
            {
                const float* vg = V + (size_t)(b * SKV + c + row) * E_DIM + h * H_DIM + c8;
                float4 f0 = *(const float4*)vg;
                float4 f1 = *(const float4*)(vg + 4);
                uint4 hi, lo; cvt8(f0, f1, hi, lo);
                *(uint4*)(smem + A_VHI + sw) = hi;
                *(uint4*)(smem + A_VLO + sw) = lo;
            }
        }
        __syncthreads();

        // ---- S = Q @ K^T  (warp: 16 x 64), fp32 acc
        float s[8][4];
#pragma unroll
        for (int na = 0; na < 8; na++)
#pragma unroll
            for (int q = 0; q < 4; q++) s[na][q] = 0.f;

#pragma unroll
        for (int ks = 0; ks < 4; ks++) {
            uint32_t kh[8][2], kl[8][2];
#pragma unroll
            for (int np = 0; np < 4; np++) {
                const uint32_t byte = (uint32_t)((np * 16 + kb_row) * 128
                                                 + (kb_kc + ks * 16) * 2);
                const uint32_t sw = SMEM_SWIZZLE_128B(byte);
                LDSM_X4(kh[2*np][0], kh[2*np][1], kh[2*np+1][0], kh[2*np+1][1],
                        sb + A_KHI + sw);
                LDSM_X4(kl[2*np][0], kl[2*np][1], kl[2*np+1][0], kl[2*np+1][1],
                        sb + A_KLO + sw);
            }
#pragma unroll
            for (int na = 0; na < 8; na++) {
                MMA16816(s[na], qh[ks], kh[na]);
                MMA16816(s[na], qh[ks], kl[na]);
                MMA16816(s[na], ql[ks], kh[na]);
            }
        }

        // ---- online softmax (rows r0 = lane>>2, r1 = r0+8 of warp tile)
        float mx0 = NEG_BIG, mx1 = NEG_BIG;
#pragma unroll
        for (int na = 0; na < 8; na++) {
            mx0 = fmaxf(mx0, fmaxf(s[na][0], s[na][1]));
            mx1 = fmaxf(mx1, fmaxf(s[na][2], s[na][3]));
        }
        mx0 = fmaxf(mx0, __shfl_xor_sync(0xffffffffu, mx0, 1));
        mx0 = fmaxf(mx0, __shfl_xor_sync(0xffffffffu, mx0, 2));
        mx1 = fmaxf(mx1, __shfl_xor_sync(0xffffffffu, mx1, 1));
        mx1 = fmaxf(mx1, __shfl_xor_sync(0xffffffffu, mx1, 2));
        const float mn0 = fmaxf(mr0, mx0);
        const float mn1 = fmaxf(mr1, mx1);
        const float al0 = __expf(mr0 - mn0);
        const float al1 = __expf(mr1 - mn1);
        mr0 = mn0; mr1 = mn1;
        float ls0 = 0.f, ls1 = 0.f;
#pragma unroll
        for (int na = 0; na < 8; na++) {
            s[na][0] = __expf(s[na][0] - mn0);
            s[na][1] = __expf(s[na][1] - mn0);
            s[na][2] = __expf(s[na][2] - mn1);
            s[na][3] = __expf(s[na][3] - mn1);
            ls0 += s[na][0] + s[na][1];
            ls1 += s[na][2] + s[na][3];
        }
        ls0 += __shfl_xor_sync(0xffffffffu, ls0, 1);
        ls0 += __shfl_xor_sync(0xffffffffu, ls0, 2);
        ls1 += __shfl_xor_sync(0xffffffffu, ls1, 1);
        ls1 += __shfl_xor_sync(0xffffffffu, ls1, 2);
        lr0 = lr0 * al0 + ls0;
        lr1 = lr1 * al1 + ls1;
#pragma unroll
        for (int na = 0; na < 8; na++) {
            o[na][0] *= al0; o[na][1] *= al0;
            o[na][2] *= al1; o[na][3] *= al1;
        }

        // ---- P @ V, fragments built in-register from s (hi/lo)
#pragma unroll
        for (int kt = 0; kt < 4; kt++) {
            // pack P fragments for this k-step from accumulator tiles 2kt, 2kt+1
            uint32_t ph[4], pl[4];
            {
                const float p00 = s[2*kt][0],   p01 = s[2*kt][1];
                const float p02 = s[2*kt][2],   p03 = s[2*kt][3];
                const float p10 = s[2*kt+1][0], p11 = s[2*kt+1][1];
                const float p12 = s[2*kt+1][2], p13 = s[2*kt+1][3];
                ph[0] = packbf2(p00, p01);
                ph[1] = packbf2(p02, p03);
                ph[2] = packbf2(p10, p11);
                ph[3] = packbf2(p12, p13);
                pl[0] = packbf2(p00 - __bfloat162float(__float2bfloat16_rn(p00)),
                                p01 - __bfloat162float(__float2bfloat16_rn(p01)));
                pl[1] = packbf2(p02 - __bfloat162float(__float2bfloat16_rn(p02)),
                                p03 - __bfloat162float(__float2bfloat16_rn(p03)));
                pl[2] = packbf2(p10 - __bfloat162float(__float2bfloat16_rn(p10)),
                                p11 - __bfloat162float(__float2bfloat16_rn(p11)));
                pl[3] = packbf2(p12 - __bfloat162float(__float2bfloat16_rn(p12)),
                                p13 - __bfloat162float(__float2bfloat16_rn(p13)));
            }
            // V fragments via ldmatrix.trans: row = kt*16 + (lane&15), colb = dp*32 + (lane>>4)*16
            uint32_t vh[8][2], vl[8][2];
#pragma unroll
            for (int dp = 0; dp < 4; dp++) {
                const uint32_t byte = (uint32_t)((kt * 16 + (lane & 15)) * 128
                                                 + dp * 32 + (lane >> 4) * 16);
                const uint32_t sw = SMEM_SWIZZLE_128B(byte);
                LDSM_X4_T(vh[2*dp][0], vh[2*dp][1], vh[2*dp+1][0], vh[2*dp+1][1],
                          sb + A_VHI + sw);
                LDSM_X4_T(vl[2*dp][0], vl[2*dp][1], vl[2*dp+1][0], vl[2*dp+1][1],
                          sb + A_VLO + sw);
            }
#pragma unroll
            for (int na = 0; na < 8; na++) {
                MMA16816(o[na], ph, vh[na]);
                MMA16816(o[na], ph, vl[na]);
                MMA16816(o[na], pl, vh[na]);
            }
        }
    }

    // ---- epilogue: normalize by l, write O
    const float inv0 = 1.f / lr0;
    const float inv1 = 1.f / lr1;
    const int row0 = q0 + wid * 16 + (lane >> 2);
#pragma unroll
    for (int na = 0; na < 8; na++) {
        const int col = h * H_DIM + na * 8 + (lane & 3) * 2;
        float2 v0, v1;
        v0.x = o[na][0] * inv0; v0.y = o[na][1] * inv0;
        v1.x = o[na][2] * inv1; v1.y = o[na][3] * inv1;
        *(float2*)(O + (size_t)(b * SQ + row0) * E_DIM + col)     = v0;
        *(float2*)(O + (size_t)(b * SQ + row0 + 8) * E_DIM + col) = v1;
    }
}

// ---------------------------------------------------------------------------
extern "C" void kernel_launch(void* const* d_in, const int* in_sizes, int n_in,
                              void* d_out, int out_size)
{
    const float* x1 = (const float*)d_in[0];
    const float* x2 = (const float*)d_in[1];
    const float* Wq = (const float*)d_in[2];
    const float* bq = (const float*)d_in[3];
    const float* Wk = (const float*)d_in[4];
    const float* bk = (const float*)d_in[5];
    const float* Wv = (const float*)d_in[6];
    const float* bv = (const float*)d_in[7];
    const float* Wo = (const float*)d_in[8];
    const float* bo = (const float*)d_in[9];
    float* out = (float*)d_out;

    float *q_ptr, *k_ptr, *v_ptr, *attn_ptr;
    cudaGetSymbolAddress((void**)&q_ptr,    g_q);
    cudaGetSymbolAddress((void**)&k_ptr,    g_k);
    cudaGetSymbolAddress((void**)&v_ptr,    g_v);
    cudaGetSymbolAddress((void**)&attn_ptr, g_attn);

    cudaFuncSetAttribute(gemm_mma, cudaFuncAttributeMaxDynamicSharedMemorySize,
                         G_SMEM);
    cudaFuncSetAttribute(attn_mma, cudaFuncAttributeMaxDynamicSharedMemorySize,
                         ATT_SMEM);

    dim3 blk(256);
    // Projections (HMMA bf16x3)
    gemm_mma<<<dim3(8, MQ  / 128), blk, G_SMEM>>>(x1, Wq, bq, q_ptr);
    gemm_mma<<<dim3(8, MKV / 128), blk, G_SMEM>>>(x2, Wk, bk, k_ptr);
    gemm_mma<<<dim3(8, MKV / 128), blk, G_SMEM>>>(x2, Wv, bv, v_ptr);

    // Attention (HMMA flash)
    attn_mma<<<dim3(SQ / 128, N_HEADS, BATCH), blk, ATT_SMEM>>>(
        q_ptr, k_ptr, v_ptr, attn_ptr);

    // Output projection
    gemm_mma<<<dim3(8, MQ / 128), blk, G_SMEM>>>(attn_ptr, Wo, bo, out);
}

// round 5
// speedup vs baseline: 3.2368x; 1.3493x over previous
#include <cuda_runtime.h>
#include <cuda_bf16.h>
#include <cstdint>
#include <math.h>

// Problem constants
#define E_DIM   1024
#define N_HEADS 16
#define H_DIM   64
#define BATCH   4
#define SQ      1024
#define SKV     2048
#define MQ      (BATCH * SQ)    // 4096
#define MKV     (BATCH * SKV)   // 8192

// ---------------------------------------------------------------------------
// Persistent bf16 hi/lo planes (device globals; allocation-free rule)
// ---------------------------------------------------------------------------
__device__ __align__(16) uint16_t g_x1h[MQ * E_DIM],  g_x1l[MQ * E_DIM];
__device__ __align__(16) uint16_t g_x2h[MKV * E_DIM], g_x2l[MKV * E_DIM];
__device__ __align__(16) uint16_t g_wqh[E_DIM * E_DIM], g_wql[E_DIM * E_DIM];
__device__ __align__(16) uint16_t g_wkh[E_DIM * E_DIM], g_wkl[E_DIM * E_DIM];
__device__ __align__(16) uint16_t g_wvh[E_DIM * E_DIM], g_wvl[E_DIM * E_DIM];
__device__ __align__(16) uint16_t g_woh[E_DIM * E_DIM], g_wol[E_DIM * E_DIM];
__device__ __align__(16) uint16_t g_qh[MQ * E_DIM],  g_ql[MQ * E_DIM];
__device__ __align__(16) uint16_t g_kh[MKV * E_DIM], g_kl[MKV * E_DIM];
__device__ __align__(16) uint16_t g_vh[MKV * E_DIM], g_vl[MKV * E_DIM];
__device__ __align__(16) uint16_t g_ah[MQ * E_DIM],  g_al[MQ * E_DIM];

// ---------------------------------------------------------------------------
// Helpers
// ---------------------------------------------------------------------------
#define SMEM_SWIZZLE_128B(byte_offset) \
    ((byte_offset) ^ (((byte_offset) >> 3) & 0x70))

#define LDSM_X4(r0_,r1_,r2_,r3_,addr_) \
    asm volatile("ldmatrix.sync.aligned.m8n8.x4.shared.b16 {%0,%1,%2,%3}, [%4];" \
        : "=r"(r0_), "=r"(r1_), "=r"(r2_), "=r"(r3_) : "r"(addr_))

#define LDSM_X4_T(r0_,r1_,r2_,r3_,addr_) \
    asm volatile("ldmatrix.sync.aligned.m8n8.x4.trans.shared.b16 {%0,%1,%2,%3}, [%4];" \
        : "=r"(r0_), "=r"(r1_), "=r"(r2_), "=r"(r3_) : "r"(addr_))

#define MMA16816(d_,a_,b_) \
    asm volatile("mma.sync.aligned.m16n8k16.row.col.f32.bf16.bf16.f32 " \
        "{%0,%1,%2,%3}, {%4,%5,%6,%7}, {%8,%9}, {%0,%1,%2,%3};" \
        : "+f"((d_)[0]), "+f"((d_)[1]), "+f"((d_)[2]), "+f"((d_)[3]) \
        : "r"((a_)[0]), "r"((a_)[1]), "r"((a_)[2]), "r"((a_)[3]), \
          "r"((b_)[0]), "r"((b_)[1]))

#define CP_ASYNC16(dst_, src_) \
    asm volatile("cp.async.cg.shared.global [%0], [%1], 16;" \
        :: "r"(dst_), "l"(src_))
#define CP_COMMIT() asm volatile("cp.async.commit_group;" ::: "memory")
#define CP_WAIT1()  asm volatile("cp.async.wait_group 1;" ::: "memory")
#define CP_WAIT0()  asm volatile("cp.async.wait_group 0;" ::: "memory")

__device__ __forceinline__ uint32_t packbf2(float x, float y) {
    __nv_bfloat162 t = __floats2bfloat162_rn(x, y);
    return *(uint32_t*)&t;
}
__device__ __forceinline__ float bflo(float v) {
    return v - __bfloat162float(__float2bfloat16_rn(v));
}

__device__ __forceinline__ void cvt8(const float4 f0, const float4 f1,
                                     uint4& hi, uint4& lo) {
    float v[8] = {f0.x, f0.y, f0.z, f0.w, f1.x, f1.y, f1.z, f1.w};
    uint32_t h[8], l[8];
#pragma unroll
    for (int i = 0; i < 8; i++) {
        __nv_bfloat16 hb = __float2bfloat16_rn(v[i]);
        float hf = __bfloat162float(hb);
        __nv_bfloat16 lb = __float2bfloat16_rn(v[i] - hf);
        h[i] = *(unsigned short*)&hb;
        l[i] = *(unsigned short*)&lb;
    }
    hi.x = h[0] | (h[1] << 16); hi.y = h[2] | (h[3] << 16);
    hi.z = h[4] | (h[5] << 16); hi.w = h[6] | (h[7] << 16);
    lo.x = l[0] | (l[1] << 16); lo.y = l[2] | (l[3] << 16);
    lo.z = l[4] | (l[5] << 16); lo.w = l[6] | (l[7] << 16);
}

// ---------------------------------------------------------------------------
// fp32 -> bf16 hi/lo plane conversion (one-shot, memory bound)
// ---------------------------------------------------------------------------
__global__ void __launch_bounds__(256) cvt_planes(
    const float* __restrict__ in, uint16_t* __restrict__ hi,
    uint16_t* __restrict__ lo, int n8)
{
    const int idx = blockIdx.x * 256 + threadIdx.x;
    if (idx >= n8) return;
    const float4 f0 = ((const float4*)in)[2 * idx];
    const float4 f1 = ((const float4*)in)[2 * idx + 1];
    uint4 h, l;
    cvt8(f0, f1, h, l);
    ((uint4*)hi)[idx] = h;
    ((uint4*)lo)[idx] = l;
}

// ---------------------------------------------------------------------------
// bf16x3 HMMA GEMM, cp.async double-buffered.
//   C[M,1024] = A[M,1024] @ B[1024,1024]^T (+bias) (*scale)
// A,B given as bf16 hi/lo planes (K-contiguous rows).
// WRITE_BF=1: emit bf16 hi/lo planes; else fp32.
// ---------------------------------------------------------------------------
#define GS_AHI  0
#define GS_ALO  16384
#define GS_BHI  32768
#define GS_BLO  49152
#define G_STAGE 65536
#define G_SMEM  131072
#define G_NCHUNK 16

template<int WRITE_BF>
__global__ void __launch_bounds__(256) gemm_bf(
    const uint16_t* __restrict__ Ah, const uint16_t* __restrict__ Al,
    const uint16_t* __restrict__ Bh, const uint16_t* __restrict__ Bl,
    const float* __restrict__ bias, float scale,
    float* __restrict__ Cf, uint16_t* __restrict__ Ch, uint16_t* __restrict__ Cl)
{
    extern __shared__ char smem[];
    const uint32_t sb = (uint32_t)__cvta_generic_to_shared(smem);
    const int tid  = threadIdx.x;
    const int wid  = tid >> 5;
    const int lane = tid & 31;
    const int m0 = blockIdx.y * 128;
    const int n0 = blockIdx.x * 128;

    const int warp_m = (wid & 1) * 64;
    const int warp_n = (wid >> 1) * 32;
    const int g = lane >> 3;
    const int r = lane & 7;

    float acc[4][4][4];
#pragma unroll
    for (int mi = 0; mi < 4; mi++)
#pragma unroll
        for (int ni = 0; ni < 4; ni++)
#pragma unroll
            for (int q = 0; q < 4; q++) acc[mi][ni][q] = 0.f;

    const int a_row = warp_m + (g & 1) * 8 + r;
    const int a_kc  = (g >> 1) * 8;
    const int b_row = warp_n + (g >> 1) * 8 + r;
    const int b_kc  = (g & 1) * 8;

    // ---- async stage loader
    auto load_stage = [&](int stage, int ch) {
        const uint32_t sbase = sb + stage * G_STAGE;
#pragma unroll
        for (int it = 0; it < 4; it++) {
            const int idx = it * 256 + tid;     // 0..1023
            const int row = idx >> 3;
            const int seg = idx & 7;
            const uint32_t sw = SMEM_SWIZZLE_128B((uint32_t)(row * 128 + seg * 16));
            const size_t ga = (size_t)(m0 + row) * E_DIM + ch * 64 + seg * 8;
            const size_t gb = (size_t)(n0 + row) * E_DIM + ch * 64 + seg * 8;
            CP_ASYNC16(sbase + GS_AHI + sw, (const char*)(Ah + ga));
            CP_ASYNC16(sbase + GS_ALO + sw, (const char*)(Al + ga));
            CP_ASYNC16(sbase + GS_BHI + sw, (const char*)(Bh + gb));
            CP_ASYNC16(sbase + GS_BLO + sw, (const char*)(Bl + gb));
        }
    };

    load_stage(0, 0);
    CP_COMMIT();

    for (int ch = 0; ch < G_NCHUNK; ch++) {
        const int buf = ch & 1;
        if (ch + 1 < G_NCHUNK) { load_stage(buf ^ 1, ch + 1); CP_COMMIT(); CP_WAIT1(); }
        else                   { CP_WAIT0(); }
        __syncthreads();

        const uint32_t sbase = sb + buf * G_STAGE;
#pragma unroll
        for (int ks = 0; ks < 4; ks++) {
            uint32_t ah[4][4], al[4][4];
#pragma unroll
            for (int mi = 0; mi < 4; mi++) {
                const uint32_t sw = SMEM_SWIZZLE_128B(
                    (uint32_t)((a_row + mi * 16) * 128 + (a_kc + ks * 16) * 2));
                LDSM_X4(ah[mi][0], ah[mi][1], ah[mi][2], ah[mi][3], sbase + GS_AHI + sw);
                LDSM_X4(al[mi][0], al[mi][1], al[mi][2], al[mi][3], sbase + GS_ALO + sw);
            }
            uint32_t bh[4][2], bl[4][2];
#pragma unroll
            for (int np = 0; np < 2; np++) {
                const uint32_t sw = SMEM_SWIZZLE_128B(
                    (uint32_t)((b_row + np * 16) * 128 + (b_kc + ks * 16) * 2));
                LDSM_X4(bh[2*np][0], bh[2*np][1], bh[2*np+1][0], bh[2*np+1][1],
                        sbase + GS_BHI + sw);
                LDSM_X4(bl[2*np][0], bl[2*np][1], bl[2*np+1][0], bl[2*np+1][1],
                        sbase + GS_BLO + sw);
            }
#pragma unroll
            for (int mi = 0; mi < 4; mi++)
#pragma unroll
                for (int ni = 0; ni < 4; ni++) {
                    MMA16816(acc[mi][ni], ah[mi], bh[ni]);
                    MMA16816(acc[mi][ni], ah[mi], bl[ni]);
                    MMA16816(acc[mi][ni], al[mi], bh[ni]);
                }
        }
        __syncthreads();
    }

    // ---- epilogue
    const int erow = lane >> 2;
    const int ecol = (lane & 3) * 2;
#pragma unroll
    for (int ni = 0; ni < 4; ni++) {
        const int col = n0 + warp_n + ni * 8 + ecol;
        const float bv0 = __ldg(bias + col);
        const float bv1 = __ldg(bias + col + 1);
#pragma unroll
        for (int mi = 0; mi < 4; mi++) {
            const int row = m0 + warp_m + mi * 16 + erow;
            float v00 = (acc[mi][ni][0] + bv0) * scale;
            float v01 = (acc[mi][ni][1] + bv1) * scale;
            float v10 = (acc[mi][ni][2] + bv0) * scale;
            float v11 = (acc[mi][ni][3] + bv1) * scale;
            if (WRITE_BF) {
                *(uint32_t*)(Ch + (size_t)row * E_DIM + col)       = packbf2(v00, v01);
                *(uint32_t*)(Cl + (size_t)row * E_DIM + col)       = packbf2(bflo(v00), bflo(v01));
                *(uint32_t*)(Ch + (size_t)(row + 8) * E_DIM + col) = packbf2(v10, v11);
                *(uint32_t*)(Cl + (size_t)(row + 8) * E_DIM + col) = packbf2(bflo(v10), bflo(v11));
            } else {
                float2 a = {v00, v01}, b = {v10, v11};
                *(float2*)(Cf + (size_t)row * E_DIM + col)       = a;
                *(float2*)(Cf + (size_t)(row + 8) * E_DIM + col) = b;
            }
        }
    }
}

// ---------------------------------------------------------------------------
// Flash attention v2 on HMMA bf16x3, inputs already bf16 hi/lo planes.
// CTA = (b, h, 128 q rows); 8 warps x 16 q rows. KV chunk 64, double-buffered.
// Output written as bf16 hi/lo planes.
// ---------------------------------------------------------------------------
#define AS_QHI  0          // 128*128B
#define AS_QLO  16384
#define AS_KV   32768      // stage base
#define AS_KHI  0          // within stage (64*128B each)
#define AS_KLO  8192
#define AS_VHI  16384
#define AS_VLO  24576
#define A_STAGE 32768
#define ATT_SMEM 98304
#define NEG_BIG (-3.0e38f)

__global__ void __launch_bounds__(256) attn_mma(
    const uint16_t* __restrict__ Qh, const uint16_t* __restrict__ Ql,
    const uint16_t* __restrict__ Kh, const uint16_t* __restrict__ Kl,
    const uint16_t* __restrict__ Vh, const uint16_t* __restrict__ Vl,
    uint16_t* __restrict__ Oh, uint16_t* __restrict__ Ol)
{
    extern __shared__ char smem[];
    const uint32_t sb = (uint32_t)__cvta_generic_to_shared(smem);
    const int b  = blockIdx.z;
    const int h  = blockIdx.y;
    const int q0 = blockIdx.x * 128;
    const int tid  = threadIdx.x;
    const int wid  = tid >> 5;
    const int lane = tid & 31;
    const int g = lane >> 3;
    const int r = lane & 7;

    // ---- Q tile 128x64 (2 planes) via cp.async
#pragma unroll
    for (int it = 0; it < 4; it++) {
        const int idx = it * 256 + tid;     // 0..1023
        const int row = idx >> 3;
        const int seg = idx & 7;
        const uint32_t sw = SMEM_SWIZZLE_128B((uint32_t)(row * 128 + seg * 16));
        const size_t gq = (size_t)(b * SQ + q0 + row) * E_DIM + h * H_DIM + seg * 8;
        if (it < 2) CP_ASYNC16(sb + AS_QHI + ((it == 0) ? sw : 0) + ((it == 1) ? sw : 0), (const char*)(Qh + gq));
    }
    // simpler explicit Q load (both planes, 8 ops/thread)
    {
#pragma unroll
        for (int it = 0; it < 4; it++) {
            const int idx = it * 256 + tid;
            const int row = idx >> 3;
            const int seg = idx & 7;
            const uint32_t sw = SMEM_SWIZZLE_128B((uint32_t)(row * 128 + seg * 16));
            const size_t gq = (size_t)(b * SQ + q0 + row) * E_DIM + h * H_DIM + seg * 8;
            CP_ASYNC16(sb + AS_QHI + sw, (const char*)(Qh + gq));
            CP_ASYNC16(sb + AS_QLO + sw, (const char*)(Ql + gq));
        }
    }
    CP_COMMIT();

    auto load_kv = [&](int stage, int c) {
        const uint32_t sbase = sb + AS_KV + stage * A_STAGE;
#pragma unroll
        for (int it = 0; it < 2; it++) {
            const int idx = it * 256 + tid;     // 0..511
            const int row = idx >> 3;           // 0..63
            const int seg = idx & 7;
            const uint32_t sw = SMEM_SWIZZLE_128B((uint32_t)(row * 128 + seg * 16));
            const size_t gk = (size_t)(b * SKV + c + row) * E_DIM + h * H_DIM + seg * 8;
            CP_ASYNC16(sbase + AS_KHI + sw, (const char*)(Kh + gk));
            CP_ASYNC16(sbase + AS_KLO + sw, (const char*)(Kl + gk));
            CP_ASYNC16(sbase + AS_VHI + sw, (const char*)(Vh + gk));
            CP_ASYNC16(sbase + AS_VLO + sw, (const char*)(Vl + gk));
        }
    };

    load_kv(0, 0);
    CP_COMMIT();
    CP_WAIT1();          // Q ready
    __syncthreads();

    // ---- persistent Q fragments
    const int a_row = wid * 16 + (g & 1) * 8 + r;
    const int a_kc  = (g >> 1) * 8;
    uint32_t qh[4][4], ql[4][4];
#pragma unroll
    for (int ks = 0; ks < 4; ks++) {
        const uint32_t sw = SMEM_SWIZZLE_128B((uint32_t)(a_row * 128 + (a_kc + ks * 16) * 2));
        LDSM_X4(qh[ks][0], qh[ks][1], qh[ks][2], qh[ks][3], sb + AS_QHI + sw);
        LDSM_X4(ql[ks][0], ql[ks][1], ql[ks][2], ql[ks][3], sb + AS_QLO + sw);
    }

    float o[8][4];
#pragma unroll
    for (int na = 0; na < 8; na++)
#pragma unroll
        for (int q = 0; q < 4; q++) o[na][q] = 0.f;
    float mr0 = NEG_BIG, mr1 = NEG_BIG, lr0 = 0.f, lr1 = 0.f;

    const int kb_row = (g >> 1) * 8 + r;
    const int kb_kc  = (g & 1) * 8;

    const int NCH = SKV / 64;   // 32
    for (int cc = 0; cc < NCH; cc++) {
        const int buf = cc & 1;
        if (cc + 1 < NCH) { load_kv(buf ^ 1, (cc + 1) * 64); CP_COMMIT(); CP_WAIT1(); }
        else              { CP_WAIT0(); }
        __syncthreads();
        const uint32_t kvb = sb + AS_KV + buf * A_STAGE;

        // ---- S = Q K^T
        float s[8][4];
#pragma unroll
        for (int na = 0; na < 8; na++)
#pragma unroll
            for (int q = 0; q < 4; q++) s[na][q] = 0.f;

#pragma unroll
        for (int ks = 0; ks < 4; ks++) {
            uint32_t kh[8][2], kl[8][2];
#pragma unroll
            for (int np = 0; np < 4; np++) {
                const uint32_t sw = SMEM_SWIZZLE_128B(
                    (uint32_t)((np * 16 + kb_row) * 128 + (kb_kc + ks * 16) * 2));
                LDSM_X4(kh[2*np][0], kh[2*np][1], kh[2*np+1][0], kh[2*np+1][1],
                        kvb + AS_KHI + sw);
                LDSM_X4(kl[2*np][0], kl[2*np][1], kl[2*np+1][0], kl[2*np+1][1],
                        kvb + AS_KLO + sw);
            }
#pragma unroll
            for (int na = 0; na < 8; na++) {
                MMA16816(s[na], qh[ks], kh[na]);
                MMA16816(s[na], qh[ks], kl[na]);
                MMA16816(s[na], ql[ks], kh[na]);
            }
        }

        // ---- online softmax
        float mx0 = NEG_BIG, mx1 = NEG_BIG;
#pragma unroll
        for (int na = 0; na < 8; na++) {
            mx0 = fmaxf(mx0, fmaxf(s[na][0], s[na][1]));
            mx1 = fmaxf(mx1, fmaxf(s[na][2], s[na][3]));
        }
        mx0 = fmaxf(mx0, __shfl_xor_sync(0xffffffffu, mx0, 1));
        mx0 = fmaxf(mx0, __shfl_xor_sync(0xffffffffu, mx0, 2));
        mx1 = fmaxf(mx1, __shfl_xor_sync(0xffffffffu, mx1, 1));
        mx1 = fmaxf(mx1, __shfl_xor_sync(0xffffffffu, mx1, 2));
        const float mn0 = fmaxf(mr0, mx0);
        const float mn1 = fmaxf(mr1, mx1);
        const float al0 = __expf(mr0 - mn0);
        const float al1 = __expf(mr1 - mn1);
        mr0 = mn0; mr1 = mn1;
        float ls0 = 0.f, ls1 = 0.f;
#pragma unroll
        for (int na = 0; na < 8; na++) {
            s[na][0] = __expf(s[na][0] - mn0);
            s[na][1] = __expf(s[na][1] - mn0);
            s[na][2] = __expf(s[na][2] - mn1);
            s[na][3] = __expf(s[na][3] - mn1);
            ls0 += s[na][0] + s[na][1];
            ls1 += s[na][2] + s[na][3];
        }
        ls0 += __shfl_xor_sync(0xffffffffu, ls0, 1);
        ls0 += __shfl_xor_sync(0xffffffffu, ls0, 2);
        ls1 += __shfl_xor_sync(0xffffffffu, ls1, 1);
        ls1 += __shfl_xor_sync(0xffffffffu, ls1, 2);
        lr0 = lr0 * al0 + ls0;
        lr1 = lr1 * al1 + ls1;
#pragma unroll
        for (int na = 0; na < 8; na++) {
            o[na][0] *= al0; o[na][1] *= al0;
            o[na][2] *= al1; o[na][3] *= al1;
        }

        // ---- P @ V
#pragma unroll
        for (int kt = 0; kt < 4; kt++) {
            uint32_t ph[4], pl[4];
            {
                const float p00 = s[2*kt][0],   p01 = s[2*kt][1];
                const float p02 = s[2*kt][2],   p03 = s[2*kt][3];
                const float p10 = s[2*kt+1][0], p11 = s[2*kt+1][1];
                const float p12 = s[2*kt+1][2], p13 = s[2*kt+1][3];
                ph[0] = packbf2(p00, p01);
                ph[1] = packbf2(p02, p03);
                ph[2] = packbf2(p10, p11);
                ph[3] = packbf2(p12, p13);
                pl[0] = packbf2(bflo(p00), bflo(p01));
                pl[1] = packbf2(bflo(p02), bflo(p03));
                pl[2] = packbf2(bflo(p10), bflo(p11));
                pl[3] = packbf2(bflo(p12), bflo(p13));
            }
            uint32_t vh[8][2], vl[8][2];
#pragma unroll
            for (int dp = 0; dp < 4; dp++) {
                const uint32_t byte = (uint32_t)((kt * 16 + (lane & 15)) * 128
                                                 + dp * 32 + (lane >> 4) * 16);
                const uint32_t sw = SMEM_SWIZZLE_128B(byte);
                LDSM_X4_T(vh[2*dp][0], vh[2*dp][1], vh[2*dp+1][0], vh[2*dp+1][1],
                          kvb + AS_VHI + sw);
                LDSM_X4_T(vl[2*dp][0], vl[2*dp][1], vl[2*dp+1][0], vl[2*dp+1][1],
                          kvb + AS_VLO + sw);
            }
#pragma unroll
            for (int na = 0; na < 8; na++) {
                MMA16816(o[na], ph, vh[na]);
                MMA16816(o[na], ph, vl[na]);
                MMA16816(o[na], pl, vh[na]);
            }
        }
        __syncthreads();
    }

    // ---- epilogue: normalize, write bf16 hi/lo planes
    const float inv0 = 1.f / lr0;
    const float inv1 = 1.f / lr1;
    const int row0 = q0 + wid * 16 + (lane >> 2);
#pragma unroll
    for (int na = 0; na < 8; na++) {
        const int col = h * H_DIM + na * 8 + (lane & 3) * 2;
        const float v00 = o[na][0] * inv0, v01 = o[na][1] * inv0;
        const float v10 = o[na][2] * inv1, v11 = o[na][3] * inv1;
        const size_t i0 = (size_t)(b * SQ + row0) * E_DIM + col;
        const size_t i1 = (size_t)(b * SQ + row0 + 8) * E_DIM + col;
        *(uint32_t*)(Oh + i0) = packbf2(v00, v01);
        *(uint32_t*)(Ol + i0) = packbf2(bflo(v00), bflo(v01));
        *(uint32_t*)(Oh + i1) = packbf2(v10, v11);
        *(uint32_t*)(Ol + i1) = packbf2(bflo(v10), bflo(v11));
    }
}

// ---------------------------------------------------------------------------
extern "C" void kernel_launch(void* const* d_in, const int* in_sizes, int n_in,
                              void* d_out, int out_size)
{
    const float* x1 = (const float*)d_in[0];
    const float* x2 = (const float*)d_in[1];
    const float* Wq = (const float*)d_in[2];
    const float* bq = (const float*)d_in[3];
    const float* Wk = (const float*)d_in[4];
    const float* bk = (const float*)d_in[5];
    const float* Wv = (const float*)d_in[6];
    const float* bv = (const float*)d_in[7];
    const float* Wo = (const float*)d_in[8];
    const float* bo = (const float*)d_in[9];
    float* out = (float*)d_out;

    uint16_t *x1h, *x1l, *x2h, *x2l;
    uint16_t *wqh, *wql, *wkh, *wkl, *wvh, *wvl, *woh, *wol;
    uint16_t *qh, *ql, *kh, *kl, *vh, *vl, *ah, *al;
    cudaGetSymbolAddress((void**)&x1h, g_x1h); cudaGetSymbolAddress((void**)&x1l, g_x1l);
    cudaGetSymbolAddress((void**)&x2h, g_x2h); cudaGetSymbolAddress((void**)&x2l, g_x2l);
    cudaGetSymbolAddress((void**)&wqh, g_wqh); cudaGetSymbolAddress((void**)&wql, g_wql);
    cudaGetSymbolAddress((void**)&wkh, g_wkh); cudaGetSymbolAddress((void**)&wkl, g_wkl);
    cudaGetSymbolAddress((void**)&wvh, g_wvh); cudaGetSymbolAddress((void**)&wvl, g_wvl);
    cudaGetSymbolAddress((void**)&woh, g_woh); cudaGetSymbolAddress((void**)&wol, g_wol);
    cudaGetSymbolAddress((void**)&qh,  g_qh);  cudaGetSymbolAddress((void**)&ql,  g_ql);
    cudaGetSymbolAddress((void**)&kh,  g_kh);  cudaGetSymbolAddress((void**)&kl,  g_kl);
    cudaGetSymbolAddress((void**)&vh,  g_vh);  cudaGetSymbolAddress((void**)&vl,  g_vl);
    cudaGetSymbolAddress((void**)&ah,  g_ah);  cudaGetSymbolAddress((void**)&al,  g_al);

    cudaFuncSetAttribute(gemm_bf<0>, cudaFuncAttributeMaxDynamicSharedMemorySize, G_SMEM);
    cudaFuncSetAttribute(gemm_bf<1>, cudaFuncAttributeMaxDynamicSharedMemorySize, G_SMEM);
    cudaFuncSetAttribute(attn_mma,  cudaFuncAttributeMaxDynamicSharedMemorySize, ATT_SMEM);

    dim3 blk(256);

    // ---- stage 1: fp32 -> bf16 hi/lo planes
    cvt_planes<<<(MQ  * E_DIM / 8 + 255) / 256, blk>>>(x1, x1h, x1l, MQ  * E_DIM / 8);
    cvt_planes<<<(MKV * E_DIM / 8 + 255) / 256, blk>>>(x2, x2h, x2l, MKV * E_DIM / 8);
    cvt_planes<<<(E_DIM * E_DIM / 8 + 255) / 256, blk>>>(Wq, wqh, wql, E_DIM * E_DIM / 8);
    cvt_planes<<<(E_DIM * E_DIM / 8 + 255) / 256, blk>>>(Wk, wkh, wkl, E_DIM * E_DIM / 8);
    cvt_planes<<<(E_DIM * E_DIM / 8 + 255) / 256, blk>>>(Wv, wvh, wvl, E_DIM * E_DIM / 8);
    cvt_planes<<<(E_DIM * E_DIM / 8 + 255) / 256, blk>>>(Wo, woh, wol, E_DIM * E_DIM / 8);

    // ---- stage 2: projections (write bf16 hi/lo; Q pre-scaled by 1/8)
    gemm_bf<1><<<dim3(8, MQ  / 128), blk, G_SMEM>>>(x1h, x1l, wqh, wql, bq, 0.125f,
                                                    nullptr, qh, ql);
    gemm_bf<1><<<dim3(8, MKV / 128), blk, G_SMEM>>>(x2h, x2l, wkh, wkl, bk, 1.0f,
                                                    nullptr, kh, kl);
    gemm_bf<1><<<dim3(8, MKV / 128), blk, G_SMEM>>>(x2h, x2l, wvh, wvl, bv, 1.0f,
                                                    nullptr, vh, vl);

    // ---- stage 3: attention
    attn_mma<<<dim3(SQ / 128, N_HEADS, BATCH), blk, ATT_SMEM>>>(
        qh, ql, kh, kl, vh, vl, ah, al);

    // ---- stage 4: output projection (fp32 out)
    gemm_bf<0><<<dim3(8, MQ / 128), blk, G_SMEM>>>(ah, al, woh, wol, bo, 1.0f,
                                                   out, nullptr, nullptr);
}

// round 6
// speedup vs baseline: 3.3964x; 1.0493x over previous
#include <cuda_runtime.h>
#include <cuda_bf16.h>
#include <cstdint>
#include <math.h>

// Problem constants
#define E_DIM   1024
#define N_HEADS 16
#define H_DIM   64
#define BATCH   4
#define SQ      1024
#define SKV     2048
#define MQ      (BATCH * SQ)    // 4096
#define MKV     (BATCH * SKV)   // 8192

// ---------------------------------------------------------------------------
// Persistent bf16 hi/lo planes (device globals; allocation-free rule)
// ---------------------------------------------------------------------------
__device__ __align__(16) uint16_t g_x1h[MQ * E_DIM],  g_x1l[MQ * E_DIM];
__device__ __align__(16) uint16_t g_x2h[MKV * E_DIM], g_x2l[MKV * E_DIM];
__device__ __align__(16) uint16_t g_wqh[E_DIM * E_DIM], g_wql[E_DIM * E_DIM];
__device__ __align__(16) uint16_t g_wkh[E_DIM * E_DIM], g_wkl[E_DIM * E_DIM];
__device__ __align__(16) uint16_t g_wvh[E_DIM * E_DIM], g_wvl[E_DIM * E_DIM];
__device__ __align__(16) uint16_t g_woh[E_DIM * E_DIM], g_wol[E_DIM * E_DIM];
__device__ __align__(16) uint16_t g_qh[MQ * E_DIM],  g_ql[MQ * E_DIM];
__device__ __align__(16) uint16_t g_kh[MKV * E_DIM], g_kl[MKV * E_DIM];
__device__ __align__(16) uint16_t g_vh[MKV * E_DIM], g_vl[MKV * E_DIM];
__device__ __align__(16) uint16_t g_ah[MQ * E_DIM],  g_al[MQ * E_DIM];

// ---------------------------------------------------------------------------
// Helpers
// ---------------------------------------------------------------------------
#define SMEM_SWIZZLE_128B(off) ((off) ^ (((off) >> 3) & 0x70))
#define SMEM_SWIZZLE_64B(off)  ((off) ^ (((off) >> 3) & 0x30))

#define LDSM_X4(r0_,r1_,r2_,r3_,addr_) \
    asm volatile("ldmatrix.sync.aligned.m8n8.x4.shared.b16 {%0,%1,%2,%3}, [%4];" \
        : "=r"(r0_), "=r"(r1_), "=r"(r2_), "=r"(r3_) : "r"(addr_))

#define LDSM_X4_T(r0_,r1_,r2_,r3_,addr_) \
    asm volatile("ldmatrix.sync.aligned.m8n8.x4.trans.shared.b16 {%0,%1,%2,%3}, [%4];" \
        : "=r"(r0_), "=r"(r1_), "=r"(r2_), "=r"(r3_) : "r"(addr_))

#define MMA16816(d_,a_,b_) \
    asm volatile("mma.sync.aligned.m16n8k16.row.col.f32.bf16.bf16.f32 " \
        "{%0,%1,%2,%3}, {%4,%5,%6,%7}, {%8,%9}, {%0,%1,%2,%3};" \
        : "+f"((d_)[0]), "+f"((d_)[1]), "+f"((d_)[2]), "+f"((d_)[3]) \
        : "r"((a_)[0]), "r"((a_)[1]), "r"((a_)[2]), "r"((a_)[3]), \
          "r"((b_)[0]), "r"((b_)[1]))

#define CP_ASYNC16(dst_, src_) \
    asm volatile("cp.async.cg.shared.global [%0], [%1], 16;" \
        :: "r"(dst_), "l"(src_))
#define CP_COMMIT() asm volatile("cp.async.commit_group;" ::: "memory")
#define CP_WAIT1()  asm volatile("cp.async.wait_group 1;" ::: "memory")
#define CP_WAIT0()  asm volatile("cp.async.wait_group 0;" ::: "memory")

__device__ __forceinline__ uint32_t packbf2(float x, float y) {
    __nv_bfloat162 t = __floats2bfloat162_rn(x, y);
    return *(uint32_t*)&t;
}
__device__ __forceinline__ float bflo(float v) {
    return v - __bfloat162float(__float2bfloat16_rn(v));
}

__device__ __forceinline__ void cvt8(const float4 f0, const float4 f1,
                                     uint4& hi, uint4& lo) {
    float v[8] = {f0.x, f0.y, f0.z, f0.w, f1.x, f1.y, f1.z, f1.w};
    uint32_t h[8], l[8];
#pragma unroll
    for (int i = 0; i < 8; i++) {
        __nv_bfloat16 hb = __float2bfloat16_rn(v[i]);
        float hf = __bfloat162float(hb);
        __nv_bfloat16 lb = __float2bfloat16_rn(v[i] - hf);
        h[i] = *(unsigned short*)&hb;
        l[i] = *(unsigned short*)&lb;
    }
    hi.x = h[0] | (h[1] << 16); hi.y = h[2] | (h[3] << 16);
    hi.z = h[4] | (h[5] << 16); hi.w = h[6] | (h[7] << 16);
    lo.x = l[0] | (l[1] << 16); lo.y = l[2] | (l[3] << 16);
    lo.z = l[4] | (l[5] << 16); lo.w = l[6] | (l[7] << 16);
}

// ---------------------------------------------------------------------------
// fp32 -> bf16 hi/lo plane conversion
// ---------------------------------------------------------------------------
__global__ void __launch_bounds__(256) cvt_planes(
    const float* __restrict__ in, uint16_t* __restrict__ hi,
    uint16_t* __restrict__ lo, int n8)
{
    const int idx = blockIdx.x * 256 + threadIdx.x;
    if (idx >= n8) return;
    const float4 f0 = ((const float4*)in)[2 * idx];
    const float4 f1 = ((const float4*)in)[2 * idx + 1];
    uint4 h, l;
    cvt8(f0, f1, h, l);
    ((uint4*)hi)[idx] = h;
    ((uint4*)lo)[idx] = l;
}

// all four weight matrices in one launch (same size E_DIM*E_DIM)
__global__ void __launch_bounds__(256) cvt_w4(
    const float* __restrict__ w0, const float* __restrict__ w1,
    const float* __restrict__ w2, const float* __restrict__ w3,
    uint16_t* __restrict__ h0, uint16_t* __restrict__ h1,
    uint16_t* __restrict__ h2, uint16_t* __restrict__ h3,
    uint16_t* __restrict__ l0, uint16_t* __restrict__ l1,
    uint16_t* __restrict__ l2, uint16_t* __restrict__ l3)
{
    const int m = blockIdx.y;
    const float* in = (m == 0) ? w0 : (m == 1) ? w1 : (m == 2) ? w2 : w3;
    uint16_t* hi = (m == 0) ? h0 : (m == 1) ? h1 : (m == 2) ? h2 : h3;
    uint16_t* lo = (m == 0) ? l0 : (m == 1) ? l1 : (m == 2) ? l2 : l3;
    const int idx = blockIdx.x * 256 + threadIdx.x;   // n8 = E*E/8 = 131072
    const float4 f0 = ((const float4*)in)[2 * idx];
    const float4 f1 = ((const float4*)in)[2 * idx + 1];
    uint4 h, l;
    cvt8(f0, f1, h, l);
    ((uint4*)hi)[idx] = h;
    ((uint4*)lo)[idx] = l;
}

// ---------------------------------------------------------------------------
// bf16x3 HMMA GEMM, 3-stage cp.async ring, 2 CTAs/SM.
//   C[M,1024] = A[M,1024] @ B[1024,1024]^T (+bias) (*scale)
// K-chunk 32 (64B rows, SW64). Stage 32KB; 3 stages = 96KB.
// ---------------------------------------------------------------------------
#define GS_AHI  0
#define GS_ALO  8192
#define GS_BHI  16384
#define GS_BLO  24576
#define G_STAGE 32768
#define G_SMEM  98304
#define G_NCHUNK 32

template<int WRITE_BF>
__global__ void __launch_bounds__(256, 2) gemm_bf(
    const uint16_t* __restrict__ Ah, const uint16_t* __restrict__ Al,
    const uint16_t* __restrict__ Bh, const uint16_t* __restrict__ Bl,
    const float* __restrict__ bias, float scale,
    float* __restrict__ Cf, uint16_t* __restrict__ Ch, uint16_t* __restrict__ Cl)
{
    extern __shared__ char smem[];
    const uint32_t sb = (uint32_t)__cvta_generic_to_shared(smem);
    const int tid  = threadIdx.x;
    const int wid  = tid >> 5;
    const int lane = tid & 31;
    const int m0 = blockIdx.y * 128;
    const int n0 = blockIdx.x * 128;

    const int warp_m = (wid & 1) * 64;
    const int warp_n = (wid >> 1) * 32;
    const int g = lane >> 3;
    const int r = lane & 7;

    float acc[4][4][4];
#pragma unroll
    for (int mi = 0; mi < 4; mi++)
#pragma unroll
        for (int ni = 0; ni < 4; ni++)
#pragma unroll
            for (int q = 0; q < 4; q++) acc[mi][ni][q] = 0.f;

    const int a_row = warp_m + (g & 1) * 8 + r;
    const int a_kc  = (g >> 1) * 8;
    const int b_row = warp_n + (g >> 1) * 8 + r;
    const int b_kc  = (g & 1) * 8;

    auto load_stage = [&](int stage, int ch) {
        const uint32_t sbase = sb + stage * G_STAGE;
#pragma unroll
        for (int it = 0; it < 2; it++) {
            const int idx = it * 256 + tid;     // 0..511
            const int row = idx >> 2;           // 0..127
            const int seg = idx & 3;            // 16B segment
            const uint32_t sw = SMEM_SWIZZLE_64B((uint32_t)(row * 64 + seg * 16));
            const size_t ga = (size_t)(m0 + row) * E_DIM + ch * 32 + seg * 8;
            const size_t gb = (size_t)(n0 + row) * E_DIM + ch * 32 + seg * 8;
            CP_ASYNC16(sbase + GS_AHI + sw, (const char*)(Ah + ga));
            CP_ASYNC16(sbase + GS_ALO + sw, (const char*)(Al + ga));
            CP_ASYNC16(sbase + GS_BHI + sw, (const char*)(Bh + gb));
            CP_ASYNC16(sbase + GS_BLO + sw, (const char*)(Bl + gb));
        }
    };

    load_stage(0, 0); CP_COMMIT();
    load_stage(1, 1); CP_COMMIT();

    for (int ch = 0; ch < G_NCHUNK; ch++) {
        if (ch < G_NCHUNK - 1) CP_WAIT1(); else CP_WAIT0();
        __syncthreads();
        if (ch + 2 < G_NCHUNK) { load_stage((ch + 2) % 3, ch + 2); CP_COMMIT(); }

        const uint32_t sbase = sb + (ch % 3) * G_STAGE;
#pragma unroll
        for (int ks = 0; ks < 2; ks++) {
            uint32_t ah[4][4], al[4][4];
#pragma unroll
            for (int mi = 0; mi < 4; mi++) {
                const uint32_t sw = SMEM_SWIZZLE_64B(
                    (uint32_t)((a_row + mi * 16) * 64 + (a_kc + ks * 16) * 2));
                LDSM_X4(ah[mi][0], ah[mi][1], ah[mi][2], ah[mi][3], sbase + GS_AHI + sw);
                LDSM_X4(al[mi][0], al[mi][1], al[mi][2], al[mi][3], sbase + GS_ALO + sw);
            }
            uint32_t bh[4][2], bl[4][2];
#pragma unroll
            for (int np = 0; np < 2; np++) {
                const uint32_t sw = SMEM_SWIZZLE_64B(
                    (uint32_t)((b_row + np * 16) * 64 + (b_kc + ks * 16) * 2));
                LDSM_X4(bh[2*np][0], bh[2*np][1], bh[2*np+1][0], bh[2*np+1][1],
                        sbase + GS_BHI + sw);
                LDSM_X4(bl[2*np][0], bl[2*np][1], bl[2*np+1][0], bl[2*np+1][1],
                        sbase + GS_BLO + sw);
            }
#pragma unroll
            for (int mi = 0; mi < 4; mi++)
#pragma unroll
                for (int ni = 0; ni < 4; ni++) {
                    MMA16816(acc[mi][ni], ah[mi], bh[ni]);
                    MMA16816(acc[mi][ni], ah[mi], bl[ni]);
                    MMA16816(acc[mi][ni], al[mi], bh[ni]);
                }
        }
    }

    // ---- epilogue
    const int erow = lane >> 2;
    const int ecol = (lane & 3) * 2;
#pragma unroll
    for (int ni = 0; ni < 4; ni++) {
        const int col = n0 + warp_n + ni * 8 + ecol;
        const float bv0 = __ldg(bias + col);
        const float bv1 = __ldg(bias + col + 1);
#pragma unroll
        for (int mi = 0; mi < 4; mi++) {
            const int row = m0 + warp_m + mi * 16 + erow;
            float v00 = (acc[mi][ni][0] + bv0) * scale;
            float v01 = (acc[mi][ni][1] + bv1) * scale;
            float v10 = (acc[mi][ni][2] + bv0) * scale;
            float v11 = (acc[mi][ni][3] + bv1) * scale;
            if (WRITE_BF) {
                *(uint32_t*)(Ch + (size_t)row * E_DIM + col)       = packbf2(v00, v01);
                *(uint32_t*)(Cl + (size_t)row * E_DIM + col)       = packbf2(bflo(v00), bflo(v01));
                *(uint32_t*)(Ch + (size_t)(row + 8) * E_DIM + col) = packbf2(v10, v11);
                *(uint32_t*)(Cl + (size_t)(row + 8) * E_DIM + col) = packbf2(bflo(v10), bflo(v11));
            } else {
                float2 a = {v00, v01}, b = {v10, v11};
                *(float2*)(Cf + (size_t)row * E_DIM + col)       = a;
                *(float2*)(Cf + (size_t)(row + 8) * E_DIM + col) = b;
            }
        }
    }
}

// ---------------------------------------------------------------------------
// Flash attention v2 on HMMA bf16x3, bf16 hi/lo plane I/O.
// CTA = (b, h, 128 q rows); 8 warps x 16 q rows. KV chunk 64, double-buffered.
// ---------------------------------------------------------------------------
#define AS_QHI  0          // 128*128B
#define AS_QLO  16384
#define AS_KV   32768      // stage base
#define AS_KHI  0
#define AS_KLO  8192
#define AS_VHI  16384
#define AS_VLO  24576
#define A_STAGE 32768
#define ATT_SMEM 98304
#define NEG_BIG (-3.0e38f)

__global__ void __launch_bounds__(256, 2) attn_mma(
    const uint16_t* __restrict__ Qh, const uint16_t* __restrict__ Ql,
    const uint16_t* __restrict__ Kh, const uint16_t* __restrict__ Kl,
    const uint16_t* __restrict__ Vh, const uint16_t* __restrict__ Vl,
    uint16_t* __restrict__ Oh, uint16_t* __restrict__ Ol)
{
    extern __shared__ char smem[];
    const uint32_t sb = (uint32_t)__cvta_generic_to_shared(smem);
    const int b  = blockIdx.z;
    const int h  = blockIdx.y;
    const int q0 = blockIdx.x * 128;
    const int tid  = threadIdx.x;
    const int wid  = tid >> 5;
    const int lane = tid & 31;
    const int g = lane >> 3;
    const int r = lane & 7;

    // ---- Q tile 128x64 (both planes) via cp.async
#pragma unroll
    for (int it = 0; it < 4; it++) {
        const int idx = it * 256 + tid;
        const int row = idx >> 3;
        const int seg = idx & 7;
        const uint32_t sw = SMEM_SWIZZLE_128B((uint32_t)(row * 128 + seg * 16));
        const size_t gq = (size_t)(b * SQ + q0 + row) * E_DIM + h * H_DIM + seg * 8;
        CP_ASYNC16(sb + AS_QHI + sw, (const char*)(Qh + gq));
        CP_ASYNC16(sb + AS_QLO + sw, (const char*)(Ql + gq));
    }
    CP_COMMIT();

    auto load_kv = [&](int stage, int c) {
        const uint32_t sbase = sb + AS_KV + stage * A_STAGE;
#pragma unroll
        for (int it = 0; it < 2; it++) {
            const int idx = it * 256 + tid;
            const int row = idx >> 3;
            const int seg = idx & 7;
            const uint32_t sw = SMEM_SWIZZLE_128B((uint32_t)(row * 128 + seg * 16));
            const size_t gk = (size_t)(b * SKV + c + row) * E_DIM + h * H_DIM + seg * 8;
            CP_ASYNC16(sbase + AS_KHI + sw, (const char*)(Kh + gk));
            CP_ASYNC16(sbase + AS_KLO + sw, (const char*)(Kl + gk));
            CP_ASYNC16(sbase + AS_VHI + sw, (const char*)(Vh + gk));
            CP_ASYNC16(sbase + AS_VLO + sw, (const char*)(Vl + gk));
        }
    };

    load_kv(0, 0);
    CP_COMMIT();
    CP_WAIT1();          // Q ready
    __syncthreads();

    // ---- persistent Q fragments
    const int a_row = wid * 16 + (g & 1) * 8 + r;
    const int a_kc  = (g >> 1) * 8;
    uint32_t qh[4][4], ql[4][4];
#pragma unroll
    for (int ks = 0; ks < 4; ks++) {
        const uint32_t sw = SMEM_SWIZZLE_128B((uint32_t)(a_row * 128 + (a_kc + ks * 16) * 2));
        LDSM_X4(qh[ks][0], qh[ks][1], qh[ks][2], qh[ks][3], sb + AS_QHI + sw);
        LDSM_X4(ql[ks][0], ql[ks][1], ql[ks][2], ql[ks][3], sb + AS_QLO + sw);
    }

    float o[8][4];
#pragma unroll
    for (int na = 0; na < 8; na++)
#pragma unroll
        for (int q = 0; q < 4; q++) o[na][q] = 0.f;
    float mr0 = NEG_BIG, mr1 = NEG_BIG, lr0 = 0.f, lr1 = 0.f;

    const int kb_row = (g >> 1) * 8 + r;
    const int kb_kc  = (g & 1) * 8;

    const int NCH = SKV / 64;   // 32
    for (int cc = 0; cc < NCH; cc++) {
        const int buf = cc & 1;
        if (cc + 1 < NCH) { load_kv(buf ^ 1, (cc + 1) * 64); CP_COMMIT(); CP_WAIT1(); }
        else              { CP_WAIT0(); }
        __syncthreads();
        const uint32_t kvb = sb + AS_KV + buf * A_STAGE;

        // ---- S = Q K^T
        float s[8][4];
#pragma unroll
        for (int na = 0; na < 8; na++)
#pragma unroll
            for (int q = 0; q < 4; q++) s[na][q] = 0.f;

#pragma unroll
        for (int ks = 0; ks < 4; ks++) {
            uint32_t kh[8][2], kl[8][2];
#pragma unroll
            for (int np = 0; np < 4; np++) {
                const uint32_t sw = SMEM_SWIZZLE_128B(
                    (uint32_t)((np * 16 + kb_row) * 128 + (kb_kc + ks * 16) * 2));
                LDSM_X4(kh[2*np][0], kh[2*np][1], kh[2*np+1][0], kh[2*np+1][1],
                        kvb + AS_KHI + sw);
                LDSM_X4(kl[2*np][0], kl[2*np][1], kl[2*np+1][0], kl[2*np+1][1],
                        kvb + AS_KLO + sw);
            }
#pragma unroll
            for (int na = 0; na < 8; na++) {
                MMA16816(s[na], qh[ks], kh[na]);
                MMA16816(s[na], qh[ks], kl[na]);
                MMA16816(s[na], ql[ks], kh[na]);
            }
        }

        // ---- online softmax
        float mx0 = NEG_BIG, mx1 = NEG_BIG;
#pragma unroll
        for (int na = 0; na < 8; na++) {
            mx0 = fmaxf(mx0, fmaxf(s[na][0], s[na][1]));
            mx1 = fmaxf(mx1, fmaxf(s[na][2], s[na][3]));
        }
        mx0 = fmaxf(mx0, __shfl_xor_sync(0xffffffffu, mx0, 1));
        mx0 = fmaxf(mx0, __shfl_xor_sync(0xffffffffu, mx0, 2));
        mx1 = fmaxf(mx1, __shfl_xor_sync(0xffffffffu, mx1, 1));
        mx1 = fmaxf(mx1, __shfl_xor_sync(0xffffffffu, mx1, 2));
        const float mn0 = fmaxf(mr0, mx0);
        const float mn1 = fmaxf(mr1, mx1);
        const float al0 = __expf(mr0 - mn0);
        const float al1 = __expf(mr1 - mn1);
        mr0 = mn0; mr1 = mn1;
        float ls0 = 0.f, ls1 = 0.f;
#pragma unroll
        for (int na = 0; na < 8; na++) {
            s[na][0] = __expf(s[na][0] - mn0);
            s[na][1] = __expf(s[na][1] - mn0);
            s[na][2] = __expf(s[na][2] - mn1);
            s[na][3] = __expf(s[na][3] - mn1);
            ls0 += s[na][0] + s[na][1];
            ls1 += s[na][2] + s[na][3];
        }
        ls0 += __shfl_xor_sync(0xffffffffu, ls0, 1);
        ls0 += __shfl_xor_sync(0xffffffffu, ls0, 2);
        ls1 += __shfl_xor_sync(0xffffffffu, ls1, 1);
        ls1 += __shfl_xor_sync(0xffffffffu, ls1, 2);
        lr0 = lr0 * al0 + ls0;
        lr1 = lr1 * al1 + ls1;
#pragma unroll
        for (int na = 0; na < 8; na++) {
            o[na][0] *= al0; o[na][1] *= al0;
            o[na][2] *= al1; o[na][3] *= al1;
        }

        // ---- P @ V
#pragma unroll
        for (int kt = 0; kt < 4; kt++) {
            uint32_t ph[4], pl[4];
            {
                const float p00 = s[2*kt][0],   p01 = s[2*kt][1];
                const float p02 = s[2*kt][2],   p03 = s[2*kt][3];
                const float p10 = s[2*kt+1][0], p11 = s[2*kt+1][1];
                const float p12 = s[2*kt+1][2], p13 = s[2*kt+1][3];
                ph[0] = packbf2(p00, p01);
                ph[1] = packbf2(p02, p03);
                ph[2] = packbf2(p10, p11);
                ph[3] = packbf2(p12, p13);
                pl[0] = packbf2(bflo(p00), bflo(p01));
                pl[1] = packbf2(bflo(p02), bflo(p03));
                pl[2] = packbf2(bflo(p10), bflo(p11));
                pl[3] = packbf2(bflo(p12), bflo(p13));
            }
            uint32_t vh[8][2], vl[8][2];
#pragma unroll
            for (int dp = 0; dp < 4; dp++) {
                const uint32_t byte = (uint32_t)((kt * 16 + (lane & 15)) * 128
                                                 + dp * 32 + (lane >> 4) * 16);
                const uint32_t sw = SMEM_SWIZZLE_128B(byte);
                LDSM_X4_T(vh[2*dp][0], vh[2*dp][1], vh[2*dp+1][0], vh[2*dp+1][1],
                          kvb + AS_VHI + sw);
                LDSM_X4_T(vl[2*dp][0], vl[2*dp][1], vl[2*dp+1][0], vl[2*dp+1][1],
                          kvb + AS_VLO + sw);
            }
#pragma unroll
            for (int na = 0; na < 8; na++) {
                MMA16816(o[na], ph, vh[na]);
                MMA16816(o[na], ph, vl[na]);
                MMA16816(o[na], pl, vh[na]);
            }
        }
        __syncthreads();
    }

    // ---- epilogue: normalize, write bf16 hi/lo planes
    const float inv0 = 1.f / lr0;
    const float inv1 = 1.f / lr1;
    const int row0 = q0 + wid * 16 + (lane >> 2);
#pragma unroll
    for (int na = 0; na < 8; na++) {
        const int col = h * H_DIM + na * 8 + (lane & 3) * 2;
        const float v00 = o[na][0] * inv0, v01 = o[na][1] * inv0;
        const float v10 = o[na][2] * inv1, v11 = o[na][3] * inv1;
        const size_t i0 = (size_t)(b * SQ + row0) * E_DIM + col;
        const size_t i1 = (size_t)(b * SQ + row0 + 8) * E_DIM + col;
        *(uint32_t*)(Oh + i0) = packbf2(v00, v01);
        *(uint32_t*)(Ol + i0) = packbf2(bflo(v00), bflo(v01));
        *(uint32_t*)(Oh + i1) = packbf2(v10, v11);
        *(uint32_t*)(Ol + i1) = packbf2(bflo(v10), bflo(v11));
    }
}

// ---------------------------------------------------------------------------
extern "C" void kernel_launch(void* const* d_in, const int* in_sizes, int n_in,
                              void* d_out, int out_size)
{
    const float* x1 = (const float*)d_in[0];
    const float* x2 = (const float*)d_in[1];
    const float* Wq = (const float*)d_in[2];
    const float* bq = (const float*)d_in[3];
    const float* Wk = (const float*)d_in[4];
    const float* bk = (const float*)d_in[5];
    const float* Wv = (const float*)d_in[6];
    const float* bv = (const float*)d_in[7];
    const float* Wo = (const float*)d_in[8];
    const float* bo = (const float*)d_in[9];
    float* out = (float*)d_out;

    uint16_t *x1h, *x1l, *x2h, *x2l;
    uint16_t *wqh, *wql, *wkh, *wkl, *wvh, *wvl, *woh, *wol;
    uint16_t *qh, *ql, *kh, *kl, *vh, *vl, *ah, *al;
    cudaGetSymbolAddress((void**)&x1h, g_x1h); cudaGetSymbolAddress((void**)&x1l, g_x1l);
    cudaGetSymbolAddress((void**)&x2h, g_x2h); cudaGetSymbolAddress((void**)&x2l, g_x2l);
    cudaGetSymbolAddress((void**)&wqh, g_wqh); cudaGetSymbolAddress((void**)&wql, g_wql);
    cudaGetSymbolAddress((void**)&wkh, g_wkh); cudaGetSymbolAddress((void**)&wkl, g_wkl);
    cudaGetSymbolAddress((void**)&wvh, g_wvh); cudaGetSymbolAddress((void**)&wvl, g_wvl);
    cudaGetSymbolAddress((void**)&woh, g_woh); cudaGetSymbolAddress((void**)&wol, g_wol);
    cudaGetSymbolAddress((void**)&qh,  g_qh);  cudaGetSymbolAddress((void**)&ql,  g_ql);
    cudaGetSymbolAddress((void**)&kh,  g_kh);  cudaGetSymbolAddress((void**)&kl,  g_kl);
    cudaGetSymbolAddress((void**)&vh,  g_vh);  cudaGetSymbolAddress((void**)&vl,  g_vl);
    cudaGetSymbolAddress((void**)&ah,  g_ah);  cudaGetSymbolAddress((void**)&al,  g_al);

    cudaFuncSetAttribute(gemm_bf<0>, cudaFuncAttributeMaxDynamicSharedMemorySize, G_SMEM);
    cudaFuncSetAttribute(gemm_bf<1>, cudaFuncAttributeMaxDynamicSharedMemorySize, G_SMEM);
    cudaFuncSetAttribute(attn_mma,  cudaFuncAttributeMaxDynamicSharedMemorySize, ATT_SMEM);

    dim3 blk(256);

    // ---- stage 1: fp32 -> bf16 hi/lo planes
    cvt_planes<<<(MQ  * E_DIM / 8 + 255) / 256, blk>>>(x1, x1h, x1l, MQ  * E_DIM / 8);
    cvt_planes<<<(MKV * E_DIM / 8 + 255) / 256, blk>>>(x2, x2h, x2l, MKV * E_DIM / 8);
    cvt_w4<<<dim3(E_DIM * E_DIM / 8 / 256, 4), blk>>>(
        Wq, Wk, Wv, Wo, wqh, wkh, wvh, woh, wql, wkl, wvl, wol);

    // ---- stage 2: projections (write bf16 hi/lo; Q pre-scaled by 1/8)
    gemm_bf<1><<<dim3(8, MQ  / 128), blk, G_SMEM>>>(x1h, x1l, wqh, wql, bq, 0.125f,
                                                    nullptr, qh, ql);
    gemm_bf<1><<<dim3(8, MKV / 128), blk, G_SMEM>>>(x2h, x2l, wkh, wkl, bk, 1.0f,
                                                    nullptr, kh, kl);
    gemm_bf<1><<<dim3(8, MKV / 128), blk, G_SMEM>>>(x2h, x2l, wvh, wvl, bv, 1.0f,
                                                    nullptr, vh, vl);

    // ---- stage 3: attention
    attn_mma<<<dim3(SQ / 128, N_HEADS, BATCH), blk, ATT_SMEM>>>(
        qh, ql, kh, kl, vh, vl, ah, al);

    // ---- stage 4: output projection (fp32 out)
    gemm_bf<0><<<dim3(8, MQ / 128), blk, G_SMEM>>>(ah, al, woh, wol, bo, 1.0f,
                                                   out, nullptr, nullptr);
}

// round 7
// speedup vs baseline: 3.6064x; 1.0618x over previous
#include <cuda_runtime.h>
#include <cuda_bf16.h>
#include <cstdint>
#include <math.h>

// Problem constants
#define E_DIM   1024
#define N_HEADS 16
#define H_DIM   64
#define BATCH   4
#define SQ      1024
#define SKV     2048
#define MQ      (BATCH * SQ)    // 4096
#define MKV     (BATCH * SKV)   // 8192

// ---------------------------------------------------------------------------
// Persistent bf16 hi/lo planes (device globals; allocation-free rule)
// ---------------------------------------------------------------------------
__device__ __align__(16) uint16_t g_x1h[MQ * E_DIM],  g_x1l[MQ * E_DIM];
__device__ __align__(16) uint16_t g_x2h[MKV * E_DIM], g_x2l[MKV * E_DIM];
__device__ __align__(16) uint16_t g_wqh[E_DIM * E_DIM], g_wql[E_DIM * E_DIM];
__device__ __align__(16) uint16_t g_wkh[E_DIM * E_DIM], g_wkl[E_DIM * E_DIM];
__device__ __align__(16) uint16_t g_wvh[E_DIM * E_DIM], g_wvl[E_DIM * E_DIM];
__device__ __align__(16) uint16_t g_woh[E_DIM * E_DIM], g_wol[E_DIM * E_DIM];
__device__ __align__(16) uint16_t g_qh[MQ * E_DIM],  g_ql[MQ * E_DIM];
__device__ __align__(16) uint16_t g_kh[MKV * E_DIM], g_kl[MKV * E_DIM];
__device__ __align__(16) uint16_t g_vh[MKV * E_DIM], g_vl[MKV * E_DIM];
__device__ __align__(16) uint16_t g_ah[MQ * E_DIM],  g_al[MQ * E_DIM];

// ---------------------------------------------------------------------------
// Helpers
// ---------------------------------------------------------------------------
#define SMEM_SWIZZLE_128B(off) ((off) ^ (((off) >> 3) & 0x70))
#define SMEM_SWIZZLE_64B(off)  ((off) ^ (((off) >> 3) & 0x30))

#define LDSM_X4(r0_,r1_,r2_,r3_,addr_) \
    asm volatile("ldmatrix.sync.aligned.m8n8.x4.shared.b16 {%0,%1,%2,%3}, [%4];" \
        : "=r"(r0_), "=r"(r1_), "=r"(r2_), "=r"(r3_) : "r"(addr_))

#define LDSM_X4_T(r0_,r1_,r2_,r3_,addr_) \
    asm volatile("ldmatrix.sync.aligned.m8n8.x4.trans.shared.b16 {%0,%1,%2,%3}, [%4];" \
        : "=r"(r0_), "=r"(r1_), "=r"(r2_), "=r"(r3_) : "r"(addr_))

#define MMA16816(d_,a_,b_) \
    asm volatile("mma.sync.aligned.m16n8k16.row.col.f32.bf16.bf16.f32 " \
        "{%0,%1,%2,%3}, {%4,%5,%6,%7}, {%8,%9}, {%0,%1,%2,%3};" \
        : "+f"((d_)[0]), "+f"((d_)[1]), "+f"((d_)[2]), "+f"((d_)[3]) \
        : "r"((a_)[0]), "r"((a_)[1]), "r"((a_)[2]), "r"((a_)[3]), \
          "r"((b_)[0]), "r"((b_)[1]))

#define CP_ASYNC16(dst_, src_) \
    asm volatile("cp.async.cg.shared.global [%0], [%1], 16;" \
        :: "r"(dst_), "l"(src_))
#define CP_COMMIT() asm volatile("cp.async.commit_group;" ::: "memory")
#define CP_WAIT1()  asm volatile("cp.async.wait_group 1;" ::: "memory")
#define CP_WAIT0()  asm volatile("cp.async.wait_group 0;" ::: "memory")

__device__ __forceinline__ uint32_t packbf2(float x, float y) {
    __nv_bfloat162 t = __floats2bfloat162_rn(x, y);
    return *(uint32_t*)&t;
}
__device__ __forceinline__ float bflo(float v) {
    return v - __bfloat162float(__float2bfloat16_rn(v));
}

__device__ __forceinline__ void cvt8(const float4 f0, const float4 f1,
                                     uint4& hi, uint4& lo) {
    float v[8] = {f0.x, f0.y, f0.z, f0.w, f1.x, f1.y, f1.z, f1.w};
    uint32_t h[8], l[8];
#pragma unroll
    for (int i = 0; i < 8; i++) {
        __nv_bfloat16 hb = __float2bfloat16_rn(v[i]);
        float hf = __bfloat162float(hb);
        __nv_bfloat16 lb = __float2bfloat16_rn(v[i] - hf);
        h[i] = *(unsigned short*)&hb;
        l[i] = *(unsigned short*)&lb;
    }
    hi.x = h[0] | (h[1] << 16); hi.y = h[2] | (h[3] << 16);
    hi.z = h[4] | (h[5] << 16); hi.w = h[6] | (h[7] << 16);
    lo.x = l[0] | (l[1] << 16); lo.y = l[2] | (l[3] << 16);
    lo.z = l[4] | (l[5] << 16); lo.w = l[6] | (l[7] << 16);
}

// ---------------------------------------------------------------------------
// ALL fp32 -> bf16 hi/lo plane conversions in ONE launch.
// grid.y selects tensor; oversized grid.x CTAs early-exit.
// ---------------------------------------------------------------------------
__global__ void __launch_bounds__(256) cvt_all(
    const float* __restrict__ x1, const float* __restrict__ x2,
    const float* __restrict__ w0, const float* __restrict__ w1,
    const float* __restrict__ w2, const float* __restrict__ w3,
    uint16_t* __restrict__ x1h, uint16_t* __restrict__ x1l,
    uint16_t* __restrict__ x2h, uint16_t* __restrict__ x2l,
    uint16_t* __restrict__ h0, uint16_t* __restrict__ l0,
    uint16_t* __restrict__ h1, uint16_t* __restrict__ l1,
    uint16_t* __restrict__ h2, uint16_t* __restrict__ l2,
    uint16_t* __restrict__ h3, uint16_t* __restrict__ l3)
{
    const int m = blockIdx.y;
    const float* in; uint16_t* hi; uint16_t* lo; int n8;
    switch (m) {
        case 0: in = x1; hi = x1h; lo = x1l; n8 = MQ  * E_DIM / 8; break;
        case 1: in = x2; hi = x2h; lo = x2l; n8 = MKV * E_DIM / 8; break;
        case 2: in = w0; hi = h0;  lo = l0;  n8 = E_DIM * E_DIM / 8; break;
        case 3: in = w1; hi = h1;  lo = l1;  n8 = E_DIM * E_DIM / 8; break;
        case 4: in = w2; hi = h2;  lo = l2;  n8 = E_DIM * E_DIM / 8; break;
        default:in = w3; hi = h3;  lo = l3;  n8 = E_DIM * E_DIM / 8; break;
    }
    const int idx = blockIdx.x * 256 + threadIdx.x;
    if (idx >= n8) return;
    const float4 f0 = ((const float4*)in)[2 * idx];
    const float4 f1 = ((const float4*)in)[2 * idx + 1];
    uint4 h, l;
    cvt8(f0, f1, h, l);
    ((uint4*)hi)[idx] = h;
    ((uint4*)lo)[idx] = l;
}

// ---------------------------------------------------------------------------
// bf16x3 HMMA GEMM body, 3-stage cp.async ring (K-chunk 32, SW64, 96KB smem).
// ---------------------------------------------------------------------------
#define GS_AHI  0
#define GS_ALO  8192
#define GS_BHI  16384
#define GS_BLO  24576
#define G_STAGE 32768
#define G_SMEM  98304
#define G_NCHUNK 32

__device__ __forceinline__ void gemm_body(
    const uint16_t* __restrict__ Ah, const uint16_t* __restrict__ Al,
    const uint16_t* __restrict__ Bh, const uint16_t* __restrict__ Bl,
    const float* __restrict__ bias, float scale,
    float* __restrict__ Cf, uint16_t* __restrict__ Ch, uint16_t* __restrict__ Cl,
    const int write_bf, char* smem, const int m0, const int n0)
{
    const uint32_t sb = (uint32_t)__cvta_generic_to_shared(smem);
    const int tid  = threadIdx.x;
    const int wid  = tid >> 5;
    const int lane = tid & 31;

    const int warp_m = (wid & 1) * 64;
    const int warp_n = (wid >> 1) * 32;
    const int g = lane >> 3;
    const int r = lane & 7;

    float acc[4][4][4];
#pragma unroll
    for (int mi = 0; mi < 4; mi++)
#pragma unroll
        for (int ni = 0; ni < 4; ni++)
#pragma unroll
            for (int q = 0; q < 4; q++) acc[mi][ni][q] = 0.f;

    const int a_row = warp_m + (g & 1) * 8 + r;
    const int a_kc  = (g >> 1) * 8;
    const int b_row = warp_n + (g >> 1) * 8 + r;
    const int b_kc  = (g & 1) * 8;

    auto load_stage = [&](int stage, int ch) {
        const uint32_t sbase = sb + stage * G_STAGE;
#pragma unroll
        for (int it = 0; it < 2; it++) {
            const int idx = it * 256 + tid;     // 0..511
            const int row = idx >> 2;           // 0..127
            const int seg = idx & 3;            // 16B segment
            const uint32_t sw = SMEM_SWIZZLE_64B((uint32_t)(row * 64 + seg * 16));
            const size_t ga = (size_t)(m0 + row) * E_DIM + ch * 32 + seg * 8;
            const size_t gb = (size_t)(n0 + row) * E_DIM + ch * 32 + seg * 8;
            CP_ASYNC16(sbase + GS_AHI + sw, (const char*)(Ah + ga));
            CP_ASYNC16(sbase + GS_ALO + sw, (const char*)(Al + ga));
            CP_ASYNC16(sbase + GS_BHI + sw, (const char*)(Bh + gb));
            CP_ASYNC16(sbase + GS_BLO + sw, (const char*)(Bl + gb));
        }
    };

    load_stage(0, 0); CP_COMMIT();
    load_stage(1, 1); CP_COMMIT();

    for (int ch = 0; ch < G_NCHUNK; ch++) {
        if (ch < G_NCHUNK - 1) CP_WAIT1(); else CP_WAIT0();
        __syncthreads();
        if (ch + 2 < G_NCHUNK) { load_stage((ch + 2) % 3, ch + 2); CP_COMMIT(); }

        const uint32_t sbase = sb + (ch % 3) * G_STAGE;
#pragma unroll
        for (int ks = 0; ks < 2; ks++) {
            uint32_t ah[4][4], al[4][4];
#pragma unroll
            for (int mi = 0; mi < 4; mi++) {
                const uint32_t sw = SMEM_SWIZZLE_64B(
                    (uint32_t)((a_row + mi * 16) * 64 + (a_kc + ks * 16) * 2));
                LDSM_X4(ah[mi][0], ah[mi][1], ah[mi][2], ah[mi][3], sbase + GS_AHI + sw);
                LDSM_X4(al[mi][0], al[mi][1], al[mi][2], al[mi][3], sbase + GS_ALO + sw);
            }
            uint32_t bh[4][2], bl[4][2];
#pragma unroll
            for (int np = 0; np < 2; np++) {
                const uint32_t sw = SMEM_SWIZZLE_64B(
                    (uint32_t)((b_row + np * 16) * 64 + (b_kc + ks * 16) * 2));
                LDSM_X4(bh[2*np][0], bh[2*np][1], bh[2*np+1][0], bh[2*np+1][1],
                        sbase + GS_BHI + sw);
                LDSM_X4(bl[2*np][0], bl[2*np][1], bl[2*np+1][0], bl[2*np+1][1],
                        sbase + GS_BLO + sw);
            }
#pragma unroll
            for (int mi = 0; mi < 4; mi++)
#pragma unroll
                for (int ni = 0; ni < 4; ni++) {
                    MMA16816(acc[mi][ni], ah[mi], bh[ni]);
                    MMA16816(acc[mi][ni], ah[mi], bl[ni]);
                    MMA16816(acc[mi][ni], al[mi], bh[ni]);
                }
        }
    }

    // ---- epilogue
    const int erow = lane >> 2;
    const int ecol = (lane & 3) * 2;
#pragma unroll
    for (int ni = 0; ni < 4; ni++) {
        const int col = n0 + warp_n + ni * 8 + ecol;
        const float bv0 = __ldg(bias + col);
        const float bv1 = __ldg(bias + col + 1);
#pragma unroll
        for (int mi = 0; mi < 4; mi++) {
            const int row = m0 + warp_m + mi * 16 + erow;
            float v00 = (acc[mi][ni][0] + bv0) * scale;
            float v01 = (acc[mi][ni][1] + bv1) * scale;
            float v10 = (acc[mi][ni][2] + bv0) * scale;
            float v11 = (acc[mi][ni][3] + bv1) * scale;
            if (write_bf) {
                *(uint32_t*)(Ch + (size_t)row * E_DIM + col)       = packbf2(v00, v01);
                *(uint32_t*)(Cl + (size_t)row * E_DIM + col)       = packbf2(bflo(v00), bflo(v01));
                *(uint32_t*)(Ch + (size_t)(row + 8) * E_DIM + col) = packbf2(v10, v11);
                *(uint32_t*)(Cl + (size_t)(row + 8) * E_DIM + col) = packbf2(bflo(v10), bflo(v11));
            } else {
                float2 a = {v00, v01}, b = {v10, v11};
                *(float2*)(Cf + (size_t)row * E_DIM + col)       = a;
                *(float2*)(Cf + (size_t)(row + 8) * E_DIM + col) = b;
            }
        }
    }
}

// ---- fused Q/K/V projections: grid (8, 64, 3); z=0 uses only y<32
__global__ void __launch_bounds__(256, 2) gemm_qkv(
    const uint16_t* __restrict__ x1h, const uint16_t* __restrict__ x1l,
    const uint16_t* __restrict__ x2h, const uint16_t* __restrict__ x2l,
    const uint16_t* __restrict__ wqh, const uint16_t* __restrict__ wql,
    const uint16_t* __restrict__ wkh, const uint16_t* __restrict__ wkl,
    const uint16_t* __restrict__ wvh, const uint16_t* __restrict__ wvl,
    const float* __restrict__ bq, const float* __restrict__ bk,
    const float* __restrict__ bv,
    uint16_t* __restrict__ qh, uint16_t* __restrict__ ql,
    uint16_t* __restrict__ kh, uint16_t* __restrict__ kl,
    uint16_t* __restrict__ vh, uint16_t* __restrict__ vl)
{
    extern __shared__ char smem[];
    const int z = blockIdx.z;
    if (z == 0 && blockIdx.y >= MQ / 128) return;
    const uint16_t *Ah, *Al, *Bh, *Bl;
    const float* bias; float scale;
    uint16_t *Ch, *Cl;
    if (z == 0)      { Ah=x1h; Al=x1l; Bh=wqh; Bl=wql; bias=bq; scale=0.125f; Ch=qh; Cl=ql; }
    else if (z == 1) { Ah=x2h; Al=x2l; Bh=wkh; Bl=wkl; bias=bk; scale=1.0f;   Ch=kh; Cl=kl; }
    else             { Ah=x2h; Al=x2l; Bh=wvh; Bl=wvl; bias=bv; scale=1.0f;   Ch=vh; Cl=vl; }
    gemm_body(Ah, Al, Bh, Bl, bias, scale, nullptr, Ch, Cl, 1,
              smem, blockIdx.y * 128, blockIdx.x * 128);
}

// ---- output projection (fp32 out)
__global__ void __launch_bounds__(256, 2) gemm_out(
    const uint16_t* __restrict__ Ah, const uint16_t* __restrict__ Al,
    const uint16_t* __restrict__ Bh, const uint16_t* __restrict__ Bl,
    const float* __restrict__ bias, float* __restrict__ Cf)
{
    extern __shared__ char smem[];
    gemm_body(Ah, Al, Bh, Bl, bias, 1.0f, Cf, nullptr, nullptr, 0,
              smem, blockIdx.y * 128, blockIdx.x * 128);
}

// ---------------------------------------------------------------------------
// Flash attention v2 on HMMA bf16x3, bf16 hi/lo plane I/O.
// CTA = (b, h, 128 q rows); 8 warps x 16 q rows. KV chunk 64, double-buffered.
// ---------------------------------------------------------------------------
#define AS_QHI  0          // 128*128B
#define AS_QLO  16384
#define AS_KV   32768      // stage base
#define AS_KHI  0
#define AS_KLO  8192
#define AS_VHI  16384
#define AS_VLO  24576
#define A_STAGE 32768
#define ATT_SMEM 98304
#define NEG_BIG (-3.0e38f)

__global__ void __launch_bounds__(256, 2) attn_mma(
    const uint16_t* __restrict__ Qh, const uint16_t* __restrict__ Ql,
    const uint16_t* __restrict__ Kh, const uint16_t* __restrict__ Kl,
    const uint16_t* __restrict__ Vh, const uint16_t* __restrict__ Vl,
    uint16_t* __restrict__ Oh, uint16_t* __restrict__ Ol)
{
    extern __shared__ char smem[];
    const uint32_t sb = (uint32_t)__cvta_generic_to_shared(smem);
    const int b  = blockIdx.z;
    const int h  = blockIdx.y;
    const int q0 = blockIdx.x * 128;
    const int tid  = threadIdx.x;
    const int wid  = tid >> 5;
    const int lane = tid & 31;
    const int g = lane >> 3;
    const int r = lane & 7;

    // ---- Q tile 128x64 (both planes) via cp.async
#pragma unroll
    for (int it = 0; it < 4; it++) {
        const int idx = it * 256 + tid;
        const int row = idx >> 3;
        const int seg = idx & 7;
        const uint32_t sw = SMEM_SWIZZLE_128B((uint32_t)(row * 128 + seg * 16));
        const size_t gq = (size_t)(b * SQ + q0 + row) * E_DIM + h * H_DIM + seg * 8;
        CP_ASYNC16(sb + AS_QHI + sw, (const char*)(Qh + gq));
        CP_ASYNC16(sb + AS_QLO + sw, (const char*)(Ql + gq));
    }
    CP_COMMIT();

    auto load_kv = [&](int stage, int c) {
        const uint32_t sbase = sb + AS_KV + stage * A_STAGE;
#pragma unroll
        for (int it = 0; it < 2; it++) {
            const int idx = it * 256 + tid;
            const int row = idx >> 3;
            const int seg = idx & 7;
            const uint32_t sw = SMEM_SWIZZLE_128B((uint32_t)(row * 128 + seg * 16));
            const size_t gk = (size_t)(b * SKV + c + row) * E_DIM + h * H_DIM + seg * 8;
            CP_ASYNC16(sbase + AS_KHI + sw, (const char*)(Kh + gk));
            CP_ASYNC16(sbase + AS_KLO + sw, (const char*)(Kl + gk));
            CP_ASYNC16(sbase + AS_VHI + sw, (const char*)(Vh + gk));
            CP_ASYNC16(sbase + AS_VLO + sw, (const char*)(Vl + gk));
        }
    };

    load_kv(0, 0);
    CP_COMMIT();
    CP_WAIT1();          // Q ready
    __syncthreads();

    // ---- persistent Q fragments
    const int a_row = wid * 16 + (g & 1) * 8 + r;
    const int a_kc  = (g >> 1) * 8;
    uint32_t qh[4][4], ql[4][4];
#pragma unroll
    for (int ks = 0; ks < 4; ks++) {
        const uint32_t sw = SMEM_SWIZZLE_128B((uint32_t)(a_row * 128 + (a_kc + ks * 16) * 2));
        LDSM_X4(qh[ks][0], qh[ks][1], qh[ks][2], qh[ks][3], sb + AS_QHI + sw);
        LDSM_X4(ql[ks][0], ql[ks][1], ql[ks][2], ql[ks][3], sb + AS_QLO + sw);
    }

    float o[8][4];
#pragma unroll
    for (int na = 0; na < 8; na++)
#pragma unroll
        for (int q = 0; q < 4; q++) o[na][q] = 0.f;
    float mr0 = NEG_BIG, mr1 = NEG_BIG, lr0 = 0.f, lr1 = 0.f;

    const int kb_row = (g >> 1) * 8 + r;
    const int kb_kc  = (g & 1) * 8;

    const int NCH = SKV / 64;   // 32
    for (int cc = 0; cc < NCH; cc++) {
        const int buf = cc & 1;
        if (cc + 1 < NCH) { load_kv(buf ^ 1, (cc + 1) * 64); CP_COMMIT(); CP_WAIT1(); }
        else              { CP_WAIT0(); }
        __syncthreads();
        const uint32_t kvb = sb + AS_KV + buf * A_STAGE;

        // ---- S = Q K^T
        float s[8][4];
#pragma unroll
        for (int na = 0; na < 8; na++)
#pragma unroll
            for (int q = 0; q < 4; q++) s[na][q] = 0.f;

#pragma unroll
        for (int ks = 0; ks < 4; ks++) {
            uint32_t kh[8][2], kl[8][2];
#pragma unroll
            for (int np = 0; np < 4; np++) {
                const uint32_t sw = SMEM_SWIZZLE_128B(
                    (uint32_t)((np * 16 + kb_row) * 128 + (kb_kc + ks * 16) * 2));
                LDSM_X4(kh[2*np][0], kh[2*np][1], kh[2*np+1][0], kh[2*np+1][1],
                        kvb + AS_KHI + sw);
                LDSM_X4(kl[2*np][0], kl[2*np][1], kl[2*np+1][0], kl[2*np+1][1],
                        kvb + AS_KLO + sw);
            }
#pragma unroll
            for (int na = 0; na < 8; na++) {
                MMA16816(s[na], qh[ks], kh[na]);
                MMA16816(s[na], qh[ks], kl[na]);
                MMA16816(s[na], ql[ks], kh[na]);
            }
        }

        // ---- online softmax
        float mx0 = NEG_BIG, mx1 = NEG_BIG;
#pragma unroll
        for (int na = 0; na < 8; na++) {
            mx0 = fmaxf(mx0, fmaxf(s[na][0], s[na][1]));
            mx1 = fmaxf(mx1, fmaxf(s[na][2], s[na][3]));
        }
        mx0 = fmaxf(mx0, __shfl_xor_sync(0xffffffffu, mx0, 1));
        mx0 = fmaxf(mx0, __shfl_xor_sync(0xffffffffu, mx0, 2));
        mx1 = fmaxf(mx1, __shfl_xor_sync(0xffffffffu, mx1, 1));
        mx1 = fmaxf(mx1, __shfl_xor_sync(0xffffffffu, mx1, 2));
        const float mn0 = fmaxf(mr0, mx0);
        const float mn1 = fmaxf(mr1, mx1);
        const float al0 = __expf(mr0 - mn0);
        const float al1 = __expf(mr1 - mn1);
        mr0 = mn0; mr1 = mn1;
        float ls0 = 0.f, ls1 = 0.f;
#pragma unroll
        for (int na = 0; na < 8; na++) {
            s[na][0] = __expf(s[na][0] - mn0);
            s[na][1] = __expf(s[na][1] - mn0);
            s[na][2] = __expf(s[na][2] - mn1);
            s[na][3] = __expf(s[na][3] - mn1);
            ls0 += s[na][0] + s[na][1];
            ls1 += s[na][2] + s[na][3];
        }
        ls0 += __shfl_xor_sync(0xffffffffu, ls0, 1);
        ls0 += __shfl_xor_sync(0xffffffffu, ls0, 2);
        ls1 += __shfl_xor_sync(0xffffffffu, ls1, 1);
        ls1 += __shfl_xor_sync(0xffffffffu, ls1, 2);
        lr0 = lr0 * al0 + ls0;
        lr1 = lr1 * al1 + ls1;
#pragma unroll
        for (int na = 0; na < 8; na++) {
            o[na][0] *= al0; o[na][1] *= al0;
            o[na][2] *= al1; o[na][3] *= al1;
        }

        // ---- P @ V
#pragma unroll
        for (int kt = 0; kt < 4; kt++) {
            uint32_t ph[4], pl[4];
            {
                const float p00 = s[2*kt][0],   p01 = s[2*kt][1];
                const float p02 = s[2*kt][2],   p03 = s[2*kt][3];
                const float p10 = s[2*kt+1][0], p11 = s[2*kt+1][1];
                const float p12 = s[2*kt+1][2], p13 = s[2*kt+1][3];
                ph[0] = packbf2(p00, p01);
                ph[1] = packbf2(p02, p03);
                ph[2] = packbf2(p10, p11);
                ph[3] = packbf2(p12, p13);
                pl[0] = packbf2(bflo(p00), bflo(p01));
                pl[1] = packbf2(bflo(p02), bflo(p03));
                pl[2] = packbf2(bflo(p10), bflo(p11));
                pl[3] = packbf2(bflo(p12), bflo(p13));
            }
            uint32_t vh[8][2], vl[8][2];
#pragma unroll
            for (int dp = 0; dp < 4; dp++) {
                const uint32_t byte = (uint32_t)((kt * 16 + (lane & 15)) * 128
                                                 + dp * 32 + (lane >> 4) * 16);
                const uint32_t sw = SMEM_SWIZZLE_128B(byte);
                LDSM_X4_T(vh[2*dp][0], vh[2*dp][1], vh[2*dp+1][0], vh[2*dp+1][1],
                          kvb + AS_VHI + sw);
                LDSM_X4_T(vl[2*dp][0], vl[2*dp][1], vl[2*dp+1][0], vl[2*dp+1][1],
                          kvb + AS_VLO + sw);
            }
#pragma unroll
            for (int na = 0; na < 8; na++) {
                MMA16816(o[na], ph, vh[na]);
                MMA16816(o[na], ph, vl[na]);
                MMA16816(o[na], pl, vh[na]);
            }
        }
        __syncthreads();
    }

    // ---- epilogue: normalize, write bf16 hi/lo planes
    const float inv0 = 1.f / lr0;
    const float inv1 = 1.f / lr1;
    const int row0 = q0 + wid * 16 + (lane >> 2);
#pragma unroll
    for (int na = 0; na < 8; na++) {
        const int col = h * H_DIM + na * 8 + (lane & 3) * 2;
        const float v00 = o[na][0] * inv0, v01 = o[na][1] * inv0;
        const float v10 = o[na][2] * inv1, v11 = o[na][3] * inv1;
        const size_t i0 = (size_t)(b * SQ + row0) * E_DIM + col;
        const size_t i1 = (size_t)(b * SQ + row0 + 8) * E_DIM + col;
        *(uint32_t*)(Oh + i0) = packbf2(v00, v01);
        *(uint32_t*)(Ol + i0) = packbf2(bflo(v00), bflo(v01));
        *(uint32_t*)(Oh + i1) = packbf2(v10, v11);
        *(uint32_t*)(Ol + i1) = packbf2(bflo(v10), bflo(v11));
    }
}

// ---------------------------------------------------------------------------
extern "C" void kernel_launch(void* const* d_in, const int* in_sizes, int n_in,
                              void* d_out, int out_size)
{
    const float* x1 = (const float*)d_in[0];
    const float* x2 = (const float*)d_in[1];
    const float* Wq = (const float*)d_in[2];
    const float* bq = (const float*)d_in[3];
    const float* Wk = (const float*)d_in[4];
    const float* bk = (const float*)d_in[5];
    const float* Wv = (const float*)d_in[6];
    const float* bv = (const float*)d_in[7];
    const float* Wo = (const float*)d_in[8];
    const float* bo = (const float*)d_in[9];
    float* out = (float*)d_out;

    uint16_t *x1h, *x1l, *x2h, *x2l;
    uint16_t *wqh, *wql, *wkh, *wkl, *wvh, *wvl, *woh, *wol;
    uint16_t *qh, *ql, *kh, *kl, *vh, *vl, *ah, *al;
    cudaGetSymbolAddress((void**)&x1h, g_x1h); cudaGetSymbolAddress((void**)&x1l, g_x1l);
    cudaGetSymbolAddress((void**)&x2h, g_x2h); cudaGetSymbolAddress((void**)&x2l, g_x2l);
    cudaGetSymbolAddress((void**)&wqh, g_wqh); cudaGetSymbolAddress((void**)&wql, g_wql);
    cudaGetSymbolAddress((void**)&wkh, g_wkh); cudaGetSymbolAddress((void**)&wkl, g_wkl);
    cudaGetSymbolAddress((void**)&wvh, g_wvh); cudaGetSymbolAddress((void**)&wvl, g_wvl);
    cudaGetSymbolAddress((void**)&woh, g_woh); cudaGetSymbolAddress((void**)&wol, g_wol);
    cudaGetSymbolAddress((void**)&qh,  g_qh);  cudaGetSymbolAddress((void**)&ql,  g_ql);
    cudaGetSymbolAddress((void**)&kh,  g_kh);  cudaGetSymbolAddress((void**)&kl,  g_kl);
    cudaGetSymbolAddress((void**)&vh,  g_vh);  cudaGetSymbolAddress((void**)&vl,  g_vl);
    cudaGetSymbolAddress((void**)&ah,  g_ah);  cudaGetSymbolAddress((void**)&al,  g_al);

    cudaFuncSetAttribute(gemm_qkv, cudaFuncAttributeMaxDynamicSharedMemorySize, G_SMEM);
    cudaFuncSetAttribute(gemm_out, cudaFuncAttributeMaxDynamicSharedMemorySize, G_SMEM);
    cudaFuncSetAttribute(attn_mma, cudaFuncAttributeMaxDynamicSharedMemorySize, ATT_SMEM);

    dim3 blk(256);

    // ---- stage 1: all fp32 -> bf16 hi/lo plane conversions, one launch
    cvt_all<<<dim3(MKV * E_DIM / 8 / 256, 6), blk>>>(
        x1, x2, Wq, Wk, Wv, Wo,
        x1h, x1l, x2h, x2l,
        wqh, wql, wkh, wkl, wvh, wvl, woh, wol);

    // ---- stage 2: fused Q/K/V projections, one launch
    gemm_qkv<<<dim3(8, MKV / 128, 3), blk, G_SMEM>>>(
        x1h, x1l, x2h, x2l,
        wqh, wql, wkh, wkl, wvh, wvl,
        bq, bk, bv,
        qh, ql, kh, kl, vh, vl);

    // ---- stage 3: attention
    attn_mma<<<dim3(SQ / 128, N_HEADS, BATCH), blk, ATT_SMEM>>>(
        qh, ql, kh, kl, vh, vl, ah, al);

    // ---- stage 4: output projection (fp32 out)
    gemm_out<<<dim3(8, MQ / 128), blk, G_SMEM>>>(ah, al, woh, wol, bo, out);
}

// round 8
// speedup vs baseline: 3.6372x; 1.0085x over previous
#include <cuda_runtime.h>
#include <cuda_bf16.h>
#include <cuda_fp16.h>
#include <cstdint>
#include <math.h>

// Problem constants
#define E_DIM   1024
#define N_HEADS 16
#define H_DIM   64
#define BATCH   4
#define SQ      1024
#define SKV     2048
#define MQ      (BATCH * SQ)    // 4096
#define MKV     (BATCH * SKV)   // 8192

// ---------------------------------------------------------------------------
// Persistent bf16/fp16 hi/lo planes (device globals; allocation-free rule)
// ---------------------------------------------------------------------------
__device__ __align__(16) uint16_t g_x1h[MQ * E_DIM],  g_x1l[MQ * E_DIM];
__device__ __align__(16) uint16_t g_x2h[MKV * E_DIM], g_x2l[MKV * E_DIM];
__device__ __align__(16) uint16_t g_wqh[E_DIM * E_DIM], g_wql[E_DIM * E_DIM];
__device__ __align__(16) uint16_t g_wkh[E_DIM * E_DIM], g_wkl[E_DIM * E_DIM];
__device__ __align__(16) uint16_t g_wvh[E_DIM * E_DIM], g_wvl[E_DIM * E_DIM];
__device__ __align__(16) uint16_t g_woh[E_DIM * E_DIM], g_wol[E_DIM * E_DIM];
__device__ __align__(16) uint16_t g_qh[MQ * E_DIM],  g_ql[MQ * E_DIM];
__device__ __align__(16) uint16_t g_kh[MKV * E_DIM], g_kl[MKV * E_DIM];
__device__ __align__(16) uint16_t g_vh[MKV * E_DIM], g_vl[MKV * E_DIM];   // fp16 planes
__device__ __align__(16) uint16_t g_ah[MQ * E_DIM],  g_al[MQ * E_DIM];

// ---------------------------------------------------------------------------
// Helpers
// ---------------------------------------------------------------------------
#define SMEM_SWIZZLE_128B(off) ((off) ^ (((off) >> 3) & 0x70))
#define SMEM_SWIZZLE_64B(off)  ((off) ^ (((off) >> 3) & 0x30))

#define LDSM_X4(r0_,r1_,r2_,r3_,addr_) \
    asm volatile("ldmatrix.sync.aligned.m8n8.x4.shared.b16 {%0,%1,%2,%3}, [%4];" \
        : "=r"(r0_), "=r"(r1_), "=r"(r2_), "=r"(r3_) : "r"(addr_))

#define LDSM_X4_T(r0_,r1_,r2_,r3_,addr_) \
    asm volatile("ldmatrix.sync.aligned.m8n8.x4.trans.shared.b16 {%0,%1,%2,%3}, [%4];" \
        : "=r"(r0_), "=r"(r1_), "=r"(r2_), "=r"(r3_) : "r"(addr_))

#define MMA16816(d_,a_,b_) \
    asm volatile("mma.sync.aligned.m16n8k16.row.col.f32.bf16.bf16.f32 " \
        "{%0,%1,%2,%3}, {%4,%5,%6,%7}, {%8,%9}, {%0,%1,%2,%3};" \
        : "+f"((d_)[0]), "+f"((d_)[1]), "+f"((d_)[2]), "+f"((d_)[3]) \
        : "r"((a_)[0]), "r"((a_)[1]), "r"((a_)[2]), "r"((a_)[3]), \
          "r"((b_)[0]), "r"((b_)[1]))

#define MMAF16(d_,a_,b_) \
    asm volatile("mma.sync.aligned.m16n8k16.row.col.f32.f16.f16.f32 " \
        "{%0,%1,%2,%3}, {%4,%5,%6,%7}, {%8,%9}, {%0,%1,%2,%3};" \
        : "+f"((d_)[0]), "+f"((d_)[1]), "+f"((d_)[2]), "+f"((d_)[3]) \
        : "r"((a_)[0]), "r"((a_)[1]), "r"((a_)[2]), "r"((a_)[3]), \
          "r"((b_)[0]), "r"((b_)[1]))

#define CP_ASYNC16(dst_, src_) \
    asm volatile("cp.async.cg.shared.global [%0], [%1], 16;" \
        :: "r"(dst_), "l"(src_))
#define CP_COMMIT() asm volatile("cp.async.commit_group;" ::: "memory")
#define CP_WAIT2()  asm volatile("cp.async.wait_group 2;" ::: "memory")
#define CP_WAIT1()  asm volatile("cp.async.wait_group 1;" ::: "memory")
#define CP_WAIT0()  asm volatile("cp.async.wait_group 0;" ::: "memory")

__device__ __forceinline__ uint32_t packbf2(float x, float y) {
    __nv_bfloat162 t = __floats2bfloat162_rn(x, y);
    return *(uint32_t*)&t;
}
__device__ __forceinline__ float bflo(float v) {
    return v - __bfloat162float(__float2bfloat16_rn(v));
}
__device__ __forceinline__ uint32_t packh2(float x, float y) {
    __half2 t = __floats2half2_rn(x, y);
    return *(uint32_t*)&t;
}
__device__ __forceinline__ float hlo(float v) {
    return v - __half2float(__float2half_rn(v));
}

__device__ __forceinline__ void cvt8(const float4 f0, const float4 f1,
                                     uint4& hi, uint4& lo) {
    float v[8] = {f0.x, f0.y, f0.z, f0.w, f1.x, f1.y, f1.z, f1.w};
    uint32_t h[8], l[8];
#pragma unroll
    for (int i = 0; i < 8; i++) {
        __nv_bfloat16 hb = __float2bfloat16_rn(v[i]);
        float hf = __bfloat162float(hb);
        __nv_bfloat16 lb = __float2bfloat16_rn(v[i] - hf);
        h[i] = *(unsigned short*)&hb;
        l[i] = *(unsigned short*)&lb;
    }
    hi.x = h[0] | (h[1] << 16); hi.y = h[2] | (h[3] << 16);
    hi.z = h[4] | (h[5] << 16); hi.w = h[6] | (h[7] << 16);
    lo.x = l[0] | (l[1] << 16); lo.y = l[2] | (l[3] << 16);
    lo.z = l[4] | (l[5] << 16); lo.w = l[6] | (l[7] << 16);
}

// ---------------------------------------------------------------------------
// ALL fp32 -> bf16 hi/lo plane conversions in ONE launch.
// ---------------------------------------------------------------------------
__global__ void __launch_bounds__(256) cvt_all(
    const float* __restrict__ x1, const float* __restrict__ x2,
    const float* __restrict__ w0, const float* __restrict__ w1,
    const float* __restrict__ w2, const float* __restrict__ w3,
    uint16_t* __restrict__ x1h, uint16_t* __restrict__ x1l,
    uint16_t* __restrict__ x2h, uint16_t* __restrict__ x2l,
    uint16_t* __restrict__ h0, uint16_t* __restrict__ l0,
    uint16_t* __restrict__ h1, uint16_t* __restrict__ l1,
    uint16_t* __restrict__ h2, uint16_t* __restrict__ l2,
    uint16_t* __restrict__ h3, uint16_t* __restrict__ l3)
{
    const int m = blockIdx.y;
    const float* in; uint16_t* hi; uint16_t* lo; int n8;
    switch (m) {
        case 0: in = x1; hi = x1h; lo = x1l; n8 = MQ  * E_DIM / 8; break;
        case 1: in = x2; hi = x2h; lo = x2l; n8 = MKV * E_DIM / 8; break;
        case 2: in = w0; hi = h0;  lo = l0;  n8 = E_DIM * E_DIM / 8; break;
        case 3: in = w1; hi = h1;  lo = l1;  n8 = E_DIM * E_DIM / 8; break;
        case 4: in = w2; hi = h2;  lo = l2;  n8 = E_DIM * E_DIM / 8; break;
        default:in = w3; hi = h3;  lo = l3;  n8 = E_DIM * E_DIM / 8; break;
    }
    const int idx = blockIdx.x * 256 + threadIdx.x;
    if (idx >= n8) return;
    const float4 f0 = ((const float4*)in)[2 * idx];
    const float4 f1 = ((const float4*)in)[2 * idx + 1];
    uint4 h, l;
    cvt8(f0, f1, h, l);
    ((uint4*)hi)[idx] = h;
    ((uint4*)lo)[idx] = l;
}

// ---------------------------------------------------------------------------
// bf16x3 HMMA GEMM body: 1 CTA/SM, 4-stage cp.async ring (128KB smem),
// unconstrained registers so ptxas can hoist all fragments.
// wmode: 0 = fp32 out, 1 = bf16 hi/lo planes, 2 = fp16 hi/lo planes
// ---------------------------------------------------------------------------
#define GS_AHI  0
#define GS_ALO  8192
#define GS_BHI  16384
#define GS_BLO  24576
#define G_STAGE 32768
#define G_SMEM  131072      // 4 stages
#define G_NCHUNK 32

__device__ __forceinline__ void gemm_body(
    const uint16_t* __restrict__ Ah, const uint16_t* __restrict__ Al,
    const uint16_t* __restrict__ Bh, const uint16_t* __restrict__ Bl,
    const float* __restrict__ bias, float scale,
    float* __restrict__ Cf, uint16_t* __restrict__ Ch, uint16_t* __restrict__ Cl,
    const int wmode, char* smem, const int m0, const int n0)
{
    const uint32_t sb = (uint32_t)__cvta_generic_to_shared(smem);
    const int tid  = threadIdx.x;
    const int wid  = tid >> 5;
    const int lane = tid & 31;

    const int warp_m = (wid & 1) * 64;
    const int warp_n = (wid >> 1) * 32;
    const int g = lane >> 3;
    const int r = lane & 7;

    float acc[4][4][4];
#pragma unroll
    for (int mi = 0; mi < 4; mi++)
#pragma unroll
        for (int ni = 0; ni < 4; ni++)
#pragma unroll
            for (int q = 0; q < 4; q++) acc[mi][ni][q] = 0.f;

    const int a_row = warp_m + (g & 1) * 8 + r;
    const int a_kc  = (g >> 1) * 8;
    const int b_row = warp_n + (g >> 1) * 8 + r;
    const int b_kc  = (g & 1) * 8;

    auto load_stage = [&](int stage, int ch) {
        const uint32_t sbase = sb + stage * G_STAGE;
#pragma unroll
        for (int it = 0; it < 2; it++) {
            const int idx = it * 256 + tid;     // 0..511
            const int row = idx >> 2;           // 0..127
            const int seg = idx & 3;            // 16B segment
            const uint32_t sw = SMEM_SWIZZLE_64B((uint32_t)(row * 64 + seg * 16));
            const size_t ga = (size_t)(m0 + row) * E_DIM + ch * 32 + seg * 8;
            const size_t gb = (size_t)(n0 + row) * E_DIM + ch * 32 + seg * 8;
            CP_ASYNC16(sbase + GS_AHI + sw, (const char*)(Ah + ga));
            CP_ASYNC16(sbase + GS_ALO + sw, (const char*)(Al + ga));
            CP_ASYNC16(sbase + GS_BHI + sw, (const char*)(Bh + gb));
            CP_ASYNC16(sbase + GS_BLO + sw, (const char*)(Bl + gb));
        }
    };

    load_stage(0, 0); CP_COMMIT();
    load_stage(1, 1); CP_COMMIT();
    load_stage(2, 2); CP_COMMIT();

    for (int ch = 0; ch < G_NCHUNK; ch++) {
        if (ch < G_NCHUNK - 2) CP_WAIT2(); else CP_WAIT0();
        __syncthreads();
        if (ch + 3 < G_NCHUNK) { load_stage((ch + 3) & 3, ch + 3); CP_COMMIT(); }

        const uint32_t sbase = sb + (ch & 3) * G_STAGE;
#pragma unroll
        for (int ks = 0; ks < 2; ks++) {
            uint32_t ah[4][4], al[4][4];
#pragma unroll
            for (int mi = 0; mi < 4; mi++) {
                const uint32_t sw = SMEM_SWIZZLE_64B(
                    (uint32_t)((a_row + mi * 16) * 64 + (a_kc + ks * 16) * 2));
                LDSM_X4(ah[mi][0], ah[mi][1], ah[mi][2], ah[mi][3], sbase + GS_AHI + sw);
                LDSM_X4(al[mi][0], al[mi][1], al[mi][2], al[mi][3], sbase + GS_ALO + sw);
            }
            uint32_t bh[4][2], bl[4][2];
#pragma unroll
            for (int np = 0; np < 2; np++) {
                const uint32_t sw = SMEM_SWIZZLE_64B(
                    (uint32_t)((b_row + np * 16) * 64 + (b_kc + ks * 16) * 2));
                LDSM_X4(bh[2*np][0], bh[2*np][1], bh[2*np+1][0], bh[2*np+1][1],
                        sbase + GS_BHI + sw);
                LDSM_X4(bl[2*np][0], bl[2*np][1], bl[2*np+1][0], bl[2*np+1][1],
                        sbase + GS_BLO + sw);
            }
#pragma unroll
            for (int mi = 0; mi < 4; mi++)
#pragma unroll
                for (int ni = 0; ni < 4; ni++) {
                    MMA16816(acc[mi][ni], ah[mi], bh[ni]);
                    MMA16816(acc[mi][ni], ah[mi], bl[ni]);
                    MMA16816(acc[mi][ni], al[mi], bh[ni]);
                }
        }
    }

    // ---- epilogue
    const int erow = lane >> 2;
    const int ecol = (lane & 3) * 2;
#pragma unroll
    for (int ni = 0; ni < 4; ni++) {
        const int col = n0 + warp_n + ni * 8 + ecol;
        const float bv0 = __ldg(bias + col);
        const float bv1 = __ldg(bias + col + 1);
#pragma unroll
        for (int mi = 0; mi < 4; mi++) {
            const int row = m0 + warp_m + mi * 16 + erow;
            float v00 = (acc[mi][ni][0] + bv0) * scale;
            float v01 = (acc[mi][ni][1] + bv1) * scale;
            float v10 = (acc[mi][ni][2] + bv0) * scale;
            float v11 = (acc[mi][ni][3] + bv1) * scale;
            if (wmode == 1) {
                *(uint32_t*)(Ch + (size_t)row * E_DIM + col)       = packbf2(v00, v01);
                *(uint32_t*)(Cl + (size_t)row * E_DIM + col)       = packbf2(bflo(v00), bflo(v01));
                *(uint32_t*)(Ch + (size_t)(row + 8) * E_DIM + col) = packbf2(v10, v11);
                *(uint32_t*)(Cl + (size_t)(row + 8) * E_DIM + col) = packbf2(bflo(v10), bflo(v11));
            } else if (wmode == 2) {
                *(uint32_t*)(Ch + (size_t)row * E_DIM + col)       = packh2(v00, v01);
                *(uint32_t*)(Cl + (size_t)row * E_DIM + col)       = packh2(hlo(v00), hlo(v01));
                *(uint32_t*)(Ch + (size_t)(row + 8) * E_DIM + col) = packh2(v10, v11);
                *(uint32_t*)(Cl + (size_t)(row + 8) * E_DIM + col) = packh2(hlo(v10), hlo(v11));
            } else {
                float2 a = {v00, v01}, b = {v10, v11};
                *(float2*)(Cf + (size_t)row * E_DIM + col)       = a;
                *(float2*)(Cf + (size_t)(row + 8) * E_DIM + col) = b;
            }
        }
    }
}

// ---- fused Q/K/V projections: grid (8, 64, 3); z=0 uses only y<32
__global__ void __launch_bounds__(256, 1) gemm_qkv(
    const uint16_t* __restrict__ x1h, const uint16_t* __restrict__ x1l,
    const uint16_t* __restrict__ x2h, const uint16_t* __restrict__ x2l,
    const uint16_t* __restrict__ wqh, const uint16_t* __restrict__ wql,
    const uint16_t* __restrict__ wkh, const uint16_t* __restrict__ wkl,
    const uint16_t* __restrict__ wvh, const uint16_t* __restrict__ wvl,
    const float* __restrict__ bq, const float* __restrict__ bk,
    const float* __restrict__ bv,
    uint16_t* __restrict__ qh, uint16_t* __restrict__ ql,
    uint16_t* __restrict__ kh, uint16_t* __restrict__ kl,
    uint16_t* __restrict__ vh, uint16_t* __restrict__ vl)
{
    extern __shared__ char smem[];
    const int z = blockIdx.z;
    if (z == 0 && blockIdx.y >= MQ / 128) return;
    if (z == 0) {
        gemm_body(x1h, x1l, wqh, wql, bq, 0.125f, nullptr, qh, ql, 1,
                  smem, blockIdx.y * 128, blockIdx.x * 128);
    } else if (z == 1) {
        gemm_body(x2h, x2l, wkh, wkl, bk, 1.0f, nullptr, kh, kl, 1,
                  smem, blockIdx.y * 128, blockIdx.x * 128);
    } else {
        gemm_body(x2h, x2l, wvh, wvl, bv, 1.0f, nullptr, vh, vl, 2,
                  smem, blockIdx.y * 128, blockIdx.x * 128);
    }
}

// ---- output projection (fp32 out)
__global__ void __launch_bounds__(256, 1) gemm_out(
    const uint16_t* __restrict__ Ah, const uint16_t* __restrict__ Al,
    const uint16_t* __restrict__ Bh, const uint16_t* __restrict__ Bl,
    const float* __restrict__ bias, float* __restrict__ Cf)
{
    extern __shared__ char smem[];
    gemm_body(Ah, Al, Bh, Bl, bias, 1.0f, Cf, nullptr, nullptr, 0,
              smem, blockIdx.y * 128, blockIdx.x * 128);
}

// ---------------------------------------------------------------------------
// Flash attention v2 on HMMA. S-phase bf16x3; PV-phase fp16x2 (P single
// fp16 plane; V fp16 hi/lo planes). bf16 hi/lo plane output.
// CTA = (b, h, 128 q rows); 8 warps x 16 q rows. KV chunk 64, double-buffered.
// ---------------------------------------------------------------------------
#define AS_QHI  0          // 128*128B
#define AS_QLO  16384
#define AS_KV   32768      // stage base
#define AS_KHI  0
#define AS_KLO  8192
#define AS_VHI  16384
#define AS_VLO  24576
#define A_STAGE 32768
#define ATT_SMEM 98304
#define NEG_BIG (-3.0e38f)

__global__ void __launch_bounds__(256, 2) attn_mma(
    const uint16_t* __restrict__ Qh, const uint16_t* __restrict__ Ql,
    const uint16_t* __restrict__ Kh, const uint16_t* __restrict__ Kl,
    const uint16_t* __restrict__ Vh, const uint16_t* __restrict__ Vl,
    uint16_t* __restrict__ Oh, uint16_t* __restrict__ Ol)
{
    extern __shared__ char smem[];
    const uint32_t sb = (uint32_t)__cvta_generic_to_shared(smem);
    const int b  = blockIdx.z;
    const int h  = blockIdx.y;
    const int q0 = blockIdx.x * 128;
    const int tid  = threadIdx.x;
    const int wid  = tid >> 5;
    const int lane = tid & 31;
    const int g = lane >> 3;
    const int r = lane & 7;

    // ---- Q tile 128x64 (both planes) via cp.async
#pragma unroll
    for (int it = 0; it < 4; it++) {
        const int idx = it * 256 + tid;
        const int row = idx >> 3;
        const int seg = idx & 7;
        const uint32_t sw = SMEM_SWIZZLE_128B((uint32_t)(row * 128 + seg * 16));
        const size_t gq = (size_t)(b * SQ + q0 + row) * E_DIM + h * H_DIM + seg * 8;
        CP_ASYNC16(sb + AS_QHI + sw, (const char*)(Qh + gq));
        CP_ASYNC16(sb + AS_QLO + sw, (const char*)(Ql + gq));
    }
    CP_COMMIT();

    auto load_kv = [&](int stage, int c) {
        const uint32_t sbase = sb + AS_KV + stage * A_STAGE;
#pragma unroll
        for (int it = 0; it < 2; it++) {
            const int idx = it * 256 + tid;
            const int row = idx >> 3;
            const int seg = idx & 7;
            const uint32_t sw = SMEM_SWIZZLE_128B((uint32_t)(row * 128 + seg * 16));
            const size_t gk = (size_t)(b * SKV + c + row) * E_DIM + h * H_DIM + seg * 8;
            CP_ASYNC16(sbase + AS_KHI + sw, (const char*)(Kh + gk));
            CP_ASYNC16(sbase + AS_KLO + sw, (const char*)(Kl + gk));
            CP_ASYNC16(sbase + AS_VHI + sw, (const char*)(Vh + gk));
            CP_ASYNC16(sbase + AS_VLO + sw, (const char*)(Vl + gk));
        }
    };

    load_kv(0, 0);
    CP_COMMIT();
    CP_WAIT1();          // Q ready
    __syncthreads();

    // ---- persistent Q fragments
    const int a_row = wid * 16 + (g & 1) * 8 + r;
    const int a_kc  = (g >> 1) * 8;
    uint32_t qh[4][4], ql[4][4];
#pragma unroll
    for (int ks = 0; ks < 4; ks++) {
        const uint32_t sw = SMEM_SWIZZLE_128B((uint32_t)(a_row * 128 + (a_kc + ks * 16) * 2));
        LDSM_X4(qh[ks][0], qh[ks][1], qh[ks][2], qh[ks][3], sb + AS_QHI + sw);
        LDSM_X4(ql[ks][0], ql[ks][1], ql[ks][2], ql[ks][3], sb + AS_QLO + sw);
    }

    float o[8][4];
#pragma unroll
    for (int na = 0; na < 8; na++)
#pragma unroll
        for (int q = 0; q < 4; q++) o[na][q] = 0.f;
    float mr0 = NEG_BIG, mr1 = NEG_BIG, lr0 = 0.f, lr1 = 0.f;

    const int kb_row = (g >> 1) * 8 + r;
    const int kb_kc  = (g & 1) * 8;

    const int NCH = SKV / 64;   // 32
    for (int cc = 0; cc < NCH; cc++) {
        const int buf = cc & 1;
        if (cc + 1 < NCH) { load_kv(buf ^ 1, (cc + 1) * 64); CP_COMMIT(); CP_WAIT1(); }
        else              { CP_WAIT0(); }
        __syncthreads();
        const uint32_t kvb = sb + AS_KV + buf * A_STAGE;

        // ---- S = Q K^T (bf16 x3)
        float s[8][4];
#pragma unroll
        for (int na = 0; na < 8; na++)
#pragma unroll
            for (int q = 0; q < 4; q++) s[na][q] = 0.f;

#pragma unroll
        for (int ks = 0; ks < 4; ks++) {
            uint32_t kh[8][2], kl[8][2];
#pragma unroll
            for (int np = 0; np < 4; np++) {
                const uint32_t sw = SMEM_SWIZZLE_128B(
                    (uint32_t)((np * 16 + kb_row) * 128 + (kb_kc + ks * 16) * 2));
                LDSM_X4(kh[2*np][0], kh[2*np][1], kh[2*np+1][0], kh[2*np+1][1],
                        kvb + AS_KHI + sw);
                LDSM_X4(kl[2*np][0], kl[2*np][1], kl[2*np+1][0], kl[2*np+1][1],
                        kvb + AS_KLO + sw);
            }
#pragma unroll
            for (int na = 0; na < 8; na++) {
                MMA16816(s[na], qh[ks], kh[na]);
                MMA16816(s[na], qh[ks], kl[na]);
                MMA16816(s[na], ql[ks], kh[na]);
            }
        }

        // ---- online softmax
        float mx0 = NEG_BIG, mx1 = NEG_BIG;
#pragma unroll
        for (int na = 0; na < 8; na++) {
            mx0 = fmaxf(mx0, fmaxf(s[na][0], s[na][1]));
            mx1 = fmaxf(mx1, fmaxf(s[na][2], s[na][3]));
        }
        mx0 = fmaxf(mx0, __shfl_xor_sync(0xffffffffu, mx0, 1));
        mx0 = fmaxf(mx0, __shfl_xor_sync(0xffffffffu, mx0, 2));
        mx1 = fmaxf(mx1, __shfl_xor_sync(0xffffffffu, mx1, 1));
        mx1 = fmaxf(mx1, __shfl_xor_sync(0xffffffffu, mx1, 2));
        const float mn0 = fmaxf(mr0, mx0);
        const float mn1 = fmaxf(mr1, mx1);
        const float al0 = __expf(mr0 - mn0);
        const float al1 = __expf(mr1 - mn1);
        mr0 = mn0; mr1 = mn1;
        float ls0 = 0.f, ls1 = 0.f;
#pragma unroll
        for (int na = 0; na < 8; na++) {
            s[na][0] = __expf(s[na][0] - mn0);
            s[na][1] = __expf(s[na][1] - mn0);
            s[na][2] = __expf(s[na][2] - mn1);
            s[na][3] = __expf(s[na][3] - mn1);
            ls0 += s[na][0] + s[na][1];
            ls1 += s[na][2] + s[na][3];
        }
        ls0 += __shfl_xor_sync(0xffffffffu, ls0, 1);
        ls0 += __shfl_xor_sync(0xffffffffu, ls0, 2);
        ls1 += __shfl_xor_sync(0xffffffffu, ls1, 1);
        ls1 += __shfl_xor_sync(0xffffffffu, ls1, 2);
        lr0 = lr0 * al0 + ls0;
        lr1 = lr1 * al1 + ls1;
#pragma unroll
        for (int na = 0; na < 8; na++) {
            o[na][0] *= al0; o[na][1] *= al0;
            o[na][2] *= al1; o[na][3] *= al1;
        }

        // ---- P @ V (fp16 x2: single-plane P, hi/lo V)
#pragma unroll
        for (int kt = 0; kt < 4; kt++) {
            uint32_t ph[4];
            ph[0] = packh2(s[2*kt][0],   s[2*kt][1]);
            ph[1] = packh2(s[2*kt][2],   s[2*kt][3]);
            ph[2] = packh2(s[2*kt+1][0], s[2*kt+1][1]);
            ph[3] = packh2(s[2*kt+1][2], s[2*kt+1][3]);

            uint32_t vh[8][2], vl[8][2];
#pragma unroll
            for (int dp = 0; dp < 4; dp++) {
                const uint32_t byte = (uint32_t)((kt * 16 + (lane & 15)) * 128
                                                 + dp * 32 + (lane >> 4) * 16);
                const uint32_t sw = SMEM_SWIZZLE_128B(byte);
                LDSM_X4_T(vh[2*dp][0], vh[2*dp][1], vh[2*dp+1][0], vh[2*dp+1][1],
                          kvb + AS_VHI + sw);
                LDSM_X4_T(vl[2*dp][0], vl[2*dp][1], vl[2*dp+1][0], vl[2*dp+1][1],
                          kvb + AS_VLO + sw);
            }
#pragma unroll
            for (int na = 0; na < 8; na++) {
                MMAF16(o[na], ph, vh[na]);
                MMAF16(o[na], ph, vl[na]);
            }
        }
        __syncthreads();
    }

    // ---- epilogue: normalize, write bf16 hi/lo planes
    const float inv0 = 1.f / lr0;
    const float inv1 = 1.f / lr1;
    const int row0 = q0 + wid * 16 + (lane >> 2);
#pragma unroll
    for (int na = 0; na < 8; na++) {
        const int col = h * H_DIM + na * 8 + (lane & 3) * 2;
        const float v00 = o[na][0] * inv0, v01 = o[na][1] * inv0;
        const float v10 = o[na][2] * inv1, v11 = o[na][3] * inv1;
        const size_t i0 = (size_t)(b * SQ + row0) * E_DIM + col;
        const size_t i1 = (size_t)(b * SQ + row0 + 8) * E_DIM + col;
        *(uint32_t*)(Oh + i0) = packbf2(v00, v01);
        *(uint32_t*)(Ol + i0) = packbf2(bflo(v00), bflo(v01));
        *(uint32_t*)(Oh + i1) = packbf2(v10, v11);
        *(uint32_t*)(Ol + i1) = packbf2(bflo(v10), bflo(v11));
    }
}

// ---------------------------------------------------------------------------
extern "C" void kernel_launch(void* const* d_in, const int* in_sizes, int n_in,
                              void* d_out, int out_size)
{
    const float* x1 = (const float*)d_in[0];
    const float* x2 = (const float*)d_in[1];
    const float* Wq = (const float*)d_in[2];
    const float* bq = (const float*)d_in[3];
    const float* Wk = (const float*)d_in[4];
    const float* bk = (const float*)d_in[5];
    const float* Wv = (const float*)d_in[6];
    const float* bv = (const float*)d_in[7];
    const float* Wo = (const float*)d_in[8];
    const float* bo = (const float*)d_in[9];
    float* out = (float*)d_out;

    uint16_t *x1h, *x1l, *x2h, *x2l;
    uint16_t *wqh, *wql, *wkh, *wkl, *wvh, *wvl, *woh, *wol;
    uint16_t *qh, *ql, *kh, *kl, *vh, *vl, *ah, *al;
    cudaGetSymbolAddress((void**)&x1h, g_x1h); cudaGetSymbolAddress((void**)&x1l, g_x1l);
    cudaGetSymbolAddress((void**)&x2h, g_x2h); cudaGetSymbolAddress((void**)&x2l, g_x2l);
    cudaGetSymbolAddress((void**)&wqh, g_wqh); cudaGetSymbolAddress((void**)&wql, g_wql);
    cudaGetSymbolAddress((void**)&wkh, g_wkh); cudaGetSymbolAddress((void**)&wkl, g_wkl);
    cudaGetSymbolAddress((void**)&wvh, g_wvh); cudaGetSymbolAddress((void**)&wvl, g_wvl);
    cudaGetSymbolAddress((void**)&woh, g_woh); cudaGetSymbolAddress((void**)&wol, g_wol);
    cudaGetSymbolAddress((void**)&qh,  g_qh);  cudaGetSymbolAddress((void**)&ql,  g_ql);
    cudaGetSymbolAddress((void**)&kh,  g_kh);  cudaGetSymbolAddress((void**)&kl,  g_kl);
    cudaGetSymbolAddress((void**)&vh,  g_vh);  cudaGetSymbolAddress((void**)&vl,  g_vl);
    cudaGetSymbolAddress((void**)&ah,  g_ah);  cudaGetSymbolAddress((void**)&al,  g_al);

    cudaFuncSetAttribute(gemm_qkv, cudaFuncAttributeMaxDynamicSharedMemorySize, G_SMEM);
    cudaFuncSetAttribute(gemm_out, cudaFuncAttributeMaxDynamicSharedMemorySize, G_SMEM);
    cudaFuncSetAttribute(attn_mma, cudaFuncAttributeMaxDynamicSharedMemorySize, ATT_SMEM);

    dim3 blk(256);

    // ---- stage 1: all fp32 -> bf16 hi/lo plane conversions, one launch
    cvt_all<<<dim3(MKV * E_DIM / 8 / 256, 6), blk>>>(
        x1, x2, Wq, Wk, Wv, Wo,
        x1h, x1l, x2h, x2l,
        wqh, wql, wkh, wkl, wvh, wvl, woh, wol);

    // ---- stage 2: fused Q/K/V projections, one launch
    gemm_qkv<<<dim3(8, MKV / 128, 3), blk, G_SMEM>>>(
        x1h, x1l, x2h, x2l,
        wqh, wql, wkh, wkl, wvh, wvl,
        bq, bk, bv,
        qh, ql, kh, kl, vh, vl);

    // ---- stage 3: attention
    attn_mma<<<dim3(SQ / 128, N_HEADS, BATCH), blk, ATT_SMEM>>>(
        qh, ql, kh, kl, vh, vl, ah, al);

    // ---- stage 4: output projection (fp32 out)
    gemm_out<<<dim3(8, MQ / 128), blk, G_SMEM>>>(ah, al, woh, wol, bo, out);
}

// round 9
// speedup vs baseline: 4.6641x; 1.2823x over previous
#include <cuda_runtime.h>
#include <cuda_bf16.h>
#include <cuda_fp16.h>
#include <cstdint>
#include <math.h>

// Problem constants
#define E_DIM   1024
#define N_HEADS 16
#define H_DIM   64
#define BATCH   4
#define SQ      1024
#define SKV     2048
#define MQ      (BATCH * SQ)    // 4096
#define MKV     (BATCH * SKV)   // 8192

// ---------------------------------------------------------------------------
// Persistent planes (device globals; allocation-free rule)
//   activations: single fp16 plane      weights: fp16 hi/lo
//   Q,K (attn):  bf16 hi/lo             V (attn): fp16 hi/lo
//   attn out:    single fp16 plane
// ---------------------------------------------------------------------------
__device__ __align__(16) uint16_t g_x1h[MQ * E_DIM];
__device__ __align__(16) uint16_t g_x2h[MKV * E_DIM];
__device__ __align__(16) uint16_t g_wqh[E_DIM * E_DIM], g_wql[E_DIM * E_DIM];
__device__ __align__(16) uint16_t g_wkh[E_DIM * E_DIM], g_wkl[E_DIM * E_DIM];
__device__ __align__(16) uint16_t g_wvh[E_DIM * E_DIM], g_wvl[E_DIM * E_DIM];
__device__ __align__(16) uint16_t g_woh[E_DIM * E_DIM], g_wol[E_DIM * E_DIM];
__device__ __align__(16) uint16_t g_qh[MQ * E_DIM],  g_ql[MQ * E_DIM];    // bf16
__device__ __align__(16) uint16_t g_kh[MKV * E_DIM], g_kl[MKV * E_DIM];   // bf16
__device__ __align__(16) uint16_t g_vh[MKV * E_DIM], g_vl[MKV * E_DIM];   // fp16
__device__ __align__(16) uint16_t g_ah[MQ * E_DIM];                       // fp16

// ---------------------------------------------------------------------------
// Helpers
// ---------------------------------------------------------------------------
#define SMEM_SWIZZLE_128B(off) ((off) ^ (((off) >> 3) & 0x70))
#define SMEM_SWIZZLE_64B(off)  ((off) ^ (((off) >> 3) & 0x30))

#define LDSM_X4(r0_,r1_,r2_,r3_,addr_) \
    asm volatile("ldmatrix.sync.aligned.m8n8.x4.shared.b16 {%0,%1,%2,%3}, [%4];" \
        : "=r"(r0_), "=r"(r1_), "=r"(r2_), "=r"(r3_) : "r"(addr_))

#define LDSM_X4_T(r0_,r1_,r2_,r3_,addr_) \
    asm volatile("ldmatrix.sync.aligned.m8n8.x4.trans.shared.b16 {%0,%1,%2,%3}, [%4];" \
        : "=r"(r0_), "=r"(r1_), "=r"(r2_), "=r"(r3_) : "r"(addr_))

#define MMA16816(d_,a_,b_) \
    asm volatile("mma.sync.aligned.m16n8k16.row.col.f32.bf16.bf16.f32 " \
        "{%0,%1,%2,%3}, {%4,%5,%6,%7}, {%8,%9}, {%0,%1,%2,%3};" \
        : "+f"((d_)[0]), "+f"((d_)[1]), "+f"((d_)[2]), "+f"((d_)[3]) \
        : "r"((a_)[0]), "r"((a_)[1]), "r"((a_)[2]), "r"((a_)[3]), \
          "r"((b_)[0]), "r"((b_)[1]))

#define MMAF16(d_,a_,b_) \
    asm volatile("mma.sync.aligned.m16n8k16.row.col.f32.f16.f16.f32 " \
        "{%0,%1,%2,%3}, {%4,%5,%6,%7}, {%8,%9}, {%0,%1,%2,%3};" \
        : "+f"((d_)[0]), "+f"((d_)[1]), "+f"((d_)[2]), "+f"((d_)[3]) \
        : "r"((a_)[0]), "r"((a_)[1]), "r"((a_)[2]), "r"((a_)[3]), \
          "r"((b_)[0]), "r"((b_)[1]))

#define CP_ASYNC16(dst_, src_) \
    asm volatile("cp.async.cg.shared.global [%0], [%1], 16;" \
        :: "r"(dst_), "l"(src_))
#define CP_COMMIT() asm volatile("cp.async.commit_group;" ::: "memory")
#define CP_WAIT2()  asm volatile("cp.async.wait_group 2;" ::: "memory")
#define CP_WAIT1()  asm volatile("cp.async.wait_group 1;" ::: "memory")
#define CP_WAIT0()  asm volatile("cp.async.wait_group 0;" ::: "memory")

__device__ __forceinline__ uint32_t packbf2(float x, float y) {
    __nv_bfloat162 t = __floats2bfloat162_rn(x, y);
    return *(uint32_t*)&t;
}
__device__ __forceinline__ float bflo(float v) {
    return v - __bfloat162float(__float2bfloat16_rn(v));
}
__device__ __forceinline__ uint32_t packh2(float x, float y) {
    __half2 t = __floats2half2_rn(x, y);
    return *(uint32_t*)&t;
}
__device__ __forceinline__ float hlo(float v) {
    return v - __half2float(__float2half_rn(v));
}

// fp16 hi/lo split of 8 floats (weights)
__device__ __forceinline__ void cvt8h(const float4 f0, const float4 f1,
                                      uint4& hi, uint4& lo) {
    float v[8] = {f0.x, f0.y, f0.z, f0.w, f1.x, f1.y, f1.z, f1.w};
    uint32_t h[8], l[8];
#pragma unroll
    for (int i = 0; i < 8; i++) {
        __half hb = __float2half_rn(v[i]);
        float hf = __half2float(hb);
        __half lb = __float2half_rn(v[i] - hf);
        h[i] = *(unsigned short*)&hb;
        l[i] = *(unsigned short*)&lb;
    }
    hi.x = h[0] | (h[1] << 16); hi.y = h[2] | (h[3] << 16);
    hi.z = h[4] | (h[5] << 16); hi.w = h[6] | (h[7] << 16);
    lo.x = l[0] | (l[1] << 16); lo.y = l[2] | (l[3] << 16);
    lo.z = l[4] | (l[5] << 16); lo.w = l[6] | (l[7] << 16);
}

// ---------------------------------------------------------------------------
// ALL fp32 -> plane conversions in ONE launch.
// m=0,1: activations -> single fp16 plane.  m=2..5: weights -> fp16 hi/lo.
// ---------------------------------------------------------------------------
__global__ void __launch_bounds__(256) cvt_all(
    const float* __restrict__ x1, const float* __restrict__ x2,
    const float* __restrict__ w0, const float* __restrict__ w1,
    const float* __restrict__ w2, const float* __restrict__ w3,
    uint16_t* __restrict__ x1h, uint16_t* __restrict__ x2h,
    uint16_t* __restrict__ h0, uint16_t* __restrict__ l0,
    uint16_t* __restrict__ h1, uint16_t* __restrict__ l1,
    uint16_t* __restrict__ h2, uint16_t* __restrict__ l2,
    uint16_t* __restrict__ h3, uint16_t* __restrict__ l3)
{
    const int m = blockIdx.y;
    const int idx = blockIdx.x * 256 + threadIdx.x;
    if (m == 0 || m == 1) {
        const float* in = (m == 0) ? x1 : x2;
        uint16_t* hi    = (m == 0) ? x1h : x2h;
        const int n8    = (m == 0) ? MQ * E_DIM / 8 : MKV * E_DIM / 8;
        if (idx >= n8) return;
        const float4 f0 = ((const float4*)in)[2 * idx];
        const float4 f1 = ((const float4*)in)[2 * idx + 1];
        uint4 h;
        h.x = packh2(f0.x, f0.y); h.y = packh2(f0.z, f0.w);
        h.z = packh2(f1.x, f1.y); h.w = packh2(f1.z, f1.w);
        ((uint4*)hi)[idx] = h;
        return;
    }
    const float* in; uint16_t* hi; uint16_t* lo;
    switch (m) {
        case 2: in = w0; hi = h0; lo = l0; break;
        case 3: in = w1; hi = h1; lo = l1; break;
        case 4: in = w2; hi = h2; lo = l2; break;
        default:in = w3; hi = h3; lo = l3; break;
    }
    if (idx >= E_DIM * E_DIM / 8) return;
    const float4 f0 = ((const float4*)in)[2 * idx];
    const float4 f1 = ((const float4*)in)[2 * idx + 1];
    uint4 h, l;
    cvt8h(f0, f1, h, l);
    ((uint4*)hi)[idx] = h;
    ((uint4*)lo)[idx] = l;
}

// ---------------------------------------------------------------------------
// fp16 x2 HMMA GEMM body: A single fp16 plane, B fp16 hi/lo.
//   C = A @ B^T (+bias)(*scale);  D = A*Bh + A*Bl  (2 MMAs per k-step)
// 4-stage cp.async ring, 24KB/stage = 96KB smem, 2 CTAs/SM.
// wmode: 0 = fp32 out, 1 = bf16 hi/lo planes, 2 = fp16 hi/lo planes
// ---------------------------------------------------------------------------
#define GS_A    0
#define GS_BHI  8192
#define GS_BLO  16384
#define G_STAGE 24576
#define G_SMEM  98304       // 4 stages
#define G_NCHUNK 32

__device__ __forceinline__ void gemm_body(
    const uint16_t* __restrict__ Ah,
    const uint16_t* __restrict__ Bh, const uint16_t* __restrict__ Bl,
    const float* __restrict__ bias, float scale,
    float* __restrict__ Cf, uint16_t* __restrict__ Ch, uint16_t* __restrict__ Cl,
    const int wmode, char* smem, const int m0, const int n0)
{
    const uint32_t sb = (uint32_t)__cvta_generic_to_shared(smem);
    const int tid  = threadIdx.x;
    const int wid  = tid >> 5;
    const int lane = tid & 31;

    const int warp_m = (wid & 1) * 64;
    const int warp_n = (wid >> 1) * 32;
    const int g = lane >> 3;
    const int r = lane & 7;

    float acc[4][4][4];
#pragma unroll
    for (int mi = 0; mi < 4; mi++)
#pragma unroll
        for (int ni = 0; ni < 4; ni++)
#pragma unroll
            for (int q = 0; q < 4; q++) acc[mi][ni][q] = 0.f;

    const int a_row = warp_m + (g & 1) * 8 + r;
    const int a_kc  = (g >> 1) * 8;
    const int b_row = warp_n + (g >> 1) * 8 + r;
    const int b_kc  = (g & 1) * 8;

    auto load_stage = [&](int stage, int ch) {
        const uint32_t sbase = sb + stage * G_STAGE;
#pragma unroll
        for (int it = 0; it < 2; it++) {
            const int idx = it * 256 + tid;     // 0..511
            const int row = idx >> 2;           // 0..127
            const int seg = idx & 3;            // 16B segment
            const uint32_t sw = SMEM_SWIZZLE_64B((uint32_t)(row * 64 + seg * 16));
            const size_t ga = (size_t)(m0 + row) * E_DIM + ch * 32 + seg * 8;
            const size_t gb = (size_t)(n0 + row) * E_DIM + ch * 32 + seg * 8;
            CP_ASYNC16(sbase + GS_A   + sw, (const char*)(Ah + ga));
            CP_ASYNC16(sbase + GS_BHI + sw, (const char*)(Bh + gb));
            CP_ASYNC16(sbase + GS_BLO + sw, (const char*)(Bl + gb));
        }
    };

    load_stage(0, 0); CP_COMMIT();
    load_stage(1, 1); CP_COMMIT();
    load_stage(2, 2); CP_COMMIT();

    for (int ch = 0; ch < G_NCHUNK; ch++) {
        if (ch < G_NCHUNK - 2) CP_WAIT2(); else CP_WAIT0();
        __syncthreads();
        if (ch + 3 < G_NCHUNK) { load_stage((ch + 3) & 3, ch + 3); CP_COMMIT(); }

        const uint32_t sbase = sb + (ch & 3) * G_STAGE;
#pragma unroll
        for (int ks = 0; ks < 2; ks++) {
            uint32_t ah[4][4];
#pragma unroll
            for (int mi = 0; mi < 4; mi++) {
                const uint32_t sw = SMEM_SWIZZLE_64B(
                    (uint32_t)((a_row + mi * 16) * 64 + (a_kc + ks * 16) * 2));
                LDSM_X4(ah[mi][0], ah[mi][1], ah[mi][2], ah[mi][3], sbase + GS_A + sw);
            }
            uint32_t bh[4][2], bl[4][2];
#pragma unroll
            for (int np = 0; np < 2; np++) {
                const uint32_t sw = SMEM_SWIZZLE_64B(
                    (uint32_t)((b_row + np * 16) * 64 + (b_kc + ks * 16) * 2));
                LDSM_X4(bh[2*np][0], bh[2*np][1], bh[2*np+1][0], bh[2*np+1][1],
                        sbase + GS_BHI + sw);
                LDSM_X4(bl[2*np][0], bl[2*np][1], bl[2*np+1][0], bl[2*np+1][1],
                        sbase + GS_BLO + sw);
            }
#pragma unroll
            for (int mi = 0; mi < 4; mi++)
#pragma unroll
                for (int ni = 0; ni < 4; ni++) {
                    MMAF16(acc[mi][ni], ah[mi], bh[ni]);
                    MMAF16(acc[mi][ni], ah[mi], bl[ni]);
                }
        }
    }

    // ---- epilogue
    const int erow = lane >> 2;
    const int ecol = (lane & 3) * 2;
#pragma unroll
    for (int ni = 0; ni < 4; ni++) {
        const int col = n0 + warp_n + ni * 8 + ecol;
        const float bv0 = __ldg(bias + col);
        const float bv1 = __ldg(bias + col + 1);
#pragma unroll
        for (int mi = 0; mi < 4; mi++) {
            const int row = m0 + warp_m + mi * 16 + erow;
            float v00 = (acc[mi][ni][0] + bv0) * scale;
            float v01 = (acc[mi][ni][1] + bv1) * scale;
            float v10 = (acc[mi][ni][2] + bv0) * scale;
            float v11 = (acc[mi][ni][3] + bv1) * scale;
            if (wmode == 1) {
                *(uint32_t*)(Ch + (size_t)row * E_DIM + col)       = packbf2(v00, v01);
                *(uint32_t*)(Cl + (size_t)row * E_DIM + col)       = packbf2(bflo(v00), bflo(v01));
                *(uint32_t*)(Ch + (size_t)(row + 8) * E_DIM + col) = packbf2(v10, v11);
                *(uint32_t*)(Cl + (size_t)(row + 8) * E_DIM + col) = packbf2(bflo(v10), bflo(v11));
            } else if (wmode == 2) {
                *(uint32_t*)(Ch + (size_t)row * E_DIM + col)       = packh2(v00, v01);
                *(uint32_t*)(Cl + (size_t)row * E_DIM + col)       = packh2(hlo(v00), hlo(v01));
                *(uint32_t*)(Ch + (size_t)(row + 8) * E_DIM + col) = packh2(v10, v11);
                *(uint32_t*)(Cl + (size_t)(row + 8) * E_DIM + col) = packh2(hlo(v10), hlo(v11));
            } else {
                float2 a = {v00, v01}, b = {v10, v11};
                *(float2*)(Cf + (size_t)row * E_DIM + col)       = a;
                *(float2*)(Cf + (size_t)(row + 8) * E_DIM + col) = b;
            }
        }
    }
}

// ---- fused Q/K/V projections: grid (8, 64, 3); z=0 uses only y<32
__global__ void __launch_bounds__(256, 2) gemm_qkv(
    const uint16_t* __restrict__ x1h, const uint16_t* __restrict__ x2h,
    const uint16_t* __restrict__ wqh, const uint16_t* __restrict__ wql,
    const uint16_t* __restrict__ wkh, const uint16_t* __restrict__ wkl,
    const uint16_t* __restrict__ wvh, const uint16_t* __restrict__ wvl,
    const float* __restrict__ bq, const float* __restrict__ bk,
    const float* __restrict__ bv,
    uint16_t* __restrict__ qh, uint16_t* __restrict__ ql,
    uint16_t* __restrict__ kh, uint16_t* __restrict__ kl,
    uint16_t* __restrict__ vh, uint16_t* __restrict__ vl)
{
    extern __shared__ char smem[];
    const int z = blockIdx.z;
    if (z == 0 && blockIdx.y >= MQ / 128) return;
    if (z == 0) {
        gemm_body(x1h, wqh, wql, bq, 0.125f, nullptr, qh, ql, 1,
                  smem, blockIdx.y * 128, blockIdx.x * 128);
    } else if (z == 1) {
        gemm_body(x2h, wkh, wkl, bk, 1.0f, nullptr, kh, kl, 1,
                  smem, blockIdx.y * 128, blockIdx.x * 128);
    } else {
        gemm_body(x2h, wvh, wvl, bv, 1.0f, nullptr, vh, vl, 2,
                  smem, blockIdx.y * 128, blockIdx.x * 128);
    }
}

// ---- output projection (fp32 out)
__global__ void __launch_bounds__(256, 2) gemm_out(
    const uint16_t* __restrict__ Ah,
    const uint16_t* __restrict__ Bh, const uint16_t* __restrict__ Bl,
    const float* __restrict__ bias, float* __restrict__ Cf)
{
    extern __shared__ char smem[];
    gemm_body(Ah, Bh, Bl, bias, 1.0f, Cf, nullptr, nullptr, 0,
              smem, blockIdx.y * 128, blockIdx.x * 128);
}

// ---------------------------------------------------------------------------
// Flash attention v2 on HMMA. S-phase bf16x3; PV-phase fp16x2.
// Output: single fp16 plane (feeds A-side of O projection).
// CTA = (b, h, 128 q rows); 8 warps x 16 q rows. KV chunk 64, double-buffered.
// ---------------------------------------------------------------------------
#define AS_QHI  0          // 128*128B
#define AS_QLO  16384
#define AS_KV   32768      // stage base
#define AS_KHI  0
#define AS_KLO  8192
#define AS_VHI  16384
#define AS_VLO  24576
#define A_STAGE 32768
#define ATT_SMEM 98304
#define NEG_BIG (-3.0e38f)

__global__ void __launch_bounds__(256, 2) attn_mma(
    const uint16_t* __restrict__ Qh, const uint16_t* __restrict__ Ql,
    const uint16_t* __restrict__ Kh, const uint16_t* __restrict__ Kl,
    const uint16_t* __restrict__ Vh, const uint16_t* __restrict__ Vl,
    uint16_t* __restrict__ Oh)
{
    extern __shared__ char smem[];
    const uint32_t sb = (uint32_t)__cvta_generic_to_shared(smem);
    const int b  = blockIdx.z;
    const int h  = blockIdx.y;
    const int q0 = blockIdx.x * 128;
    const int tid  = threadIdx.x;
    const int wid  = tid >> 5;
    const int lane = tid & 31;
    const int g = lane >> 3;
    const int r = lane & 7;

    // ---- Q tile 128x64 (both planes) via cp.async
#pragma unroll
    for (int it = 0; it < 4; it++) {
        const int idx = it * 256 + tid;
        const int row = idx >> 3;
        const int seg = idx & 7;
        const uint32_t sw = SMEM_SWIZZLE_128B((uint32_t)(row * 128 + seg * 16));
        const size_t gq = (size_t)(b * SQ + q0 + row) * E_DIM + h * H_DIM + seg * 8;
        CP_ASYNC16(sb + AS_QHI + sw, (const char*)(Qh + gq));
        CP_ASYNC16(sb + AS_QLO + sw, (const char*)(Ql + gq));
    }
    CP_COMMIT();

    auto load_kv = [&](int stage, int c) {
        const uint32_t sbase = sb + AS_KV + stage * A_STAGE;
#pragma unroll
        for (int it = 0; it < 2; it++) {
            const int idx = it * 256 + tid;
            const int row = idx >> 3;
            const int seg = idx & 7;
            const uint32_t sw = SMEM_SWIZZLE_128B((uint32_t)(row * 128 + seg * 16));
            const size_t gk = (size_t)(b * SKV + c + row) * E_DIM + h * H_DIM + seg * 8;
            CP_ASYNC16(sbase + AS_KHI + sw, (const char*)(Kh + gk));
            CP_ASYNC16(sbase + AS_KLO + sw, (const char*)(Kl + gk));
            CP_ASYNC16(sbase + AS_VHI + sw, (const char*)(Vh + gk));
            CP_ASYNC16(sbase + AS_VLO + sw, (const char*)(Vl + gk));
        }
    };

    load_kv(0, 0);
    CP_COMMIT();
    CP_WAIT1();          // Q ready
    __syncthreads();

    // ---- persistent Q fragments
    const int a_row = wid * 16 + (g & 1) * 8 + r;
    const int a_kc  = (g >> 1) * 8;
    uint32_t qh[4][4], ql[4][4];
#pragma unroll
    for (int ks = 0; ks < 4; ks++) {
        const uint32_t sw = SMEM_SWIZZLE_128B((uint32_t)(a_row * 128 + (a_kc + ks * 16) * 2));
        LDSM_X4(qh[ks][0], qh[ks][1], qh[ks][2], qh[ks][3], sb + AS_QHI + sw);
        LDSM_X4(ql[ks][0], ql[ks][1], ql[ks][2], ql[ks][3], sb + AS_QLO + sw);
    }

    float o[8][4];
#pragma unroll
    for (int na = 0; na < 8; na++)
#pragma unroll
        for (int q = 0; q < 4; q++) o[na][q] = 0.f;
    float mr0 = NEG_BIG, mr1 = NEG_BIG, lr0 = 0.f, lr1 = 0.f;

    const int kb_row = (g >> 1) * 8 + r;
    const int kb_kc  = (g & 1) * 8;

    const int NCH = SKV / 64;   // 32
    for (int cc = 0; cc < NCH; cc++) {
        const int buf = cc & 1;
        if (cc + 1 < NCH) { load_kv(buf ^ 1, (cc + 1) * 64); CP_COMMIT(); CP_WAIT1(); }
        else              { CP_WAIT0(); }
        __syncthreads();
        const uint32_t kvb = sb + AS_KV + buf * A_STAGE;

        // ---- S = Q K^T (bf16 x3)
        float s[8][4];
#pragma unroll
        for (int na = 0; na < 8; na++)
#pragma unroll
            for (int q = 0; q < 4; q++) s[na][q] = 0.f;

#pragma unroll
        for (int ks = 0; ks < 4; ks++) {
            uint32_t kh[8][2], kl[8][2];
#pragma unroll
            for (int np = 0; np < 4; np++) {
                const uint32_t sw = SMEM_SWIZZLE_128B(
                    (uint32_t)((np * 16 + kb_row) * 128 + (kb_kc + ks * 16) * 2));
                LDSM_X4(kh[2*np][0], kh[2*np][1], kh[2*np+1][0], kh[2*np+1][1],
                        kvb + AS_KHI + sw);
                LDSM_X4(kl[2*np][0], kl[2*np][1], kl[2*np+1][0], kl[2*np+1][1],
                        kvb + AS_KLO + sw);
            }
#pragma unroll
            for (int na = 0; na < 8; na++) {
                MMA16816(s[na], qh[ks], kh[na]);
                MMA16816(s[na], qh[ks], kl[na]);
                MMA16816(s[na], ql[ks], kh[na]);
            }
        }

        // ---- online softmax
        float mx0 = NEG_BIG, mx1 = NEG_BIG;
#pragma unroll
        for (int na = 0; na < 8; na++) {
            mx0 = fmaxf(mx0, fmaxf(s[na][0], s[na][1]));
            mx1 = fmaxf(mx1, fmaxf(s[na][2], s[na][3]));
        }
        mx0 = fmaxf(mx0, __shfl_xor_sync(0xffffffffu, mx0, 1));
        mx0 = fmaxf(mx0, __shfl_xor_sync(0xffffffffu, mx0, 2));
        mx1 = fmaxf(mx1, __shfl_xor_sync(0xffffffffu, mx1, 1));
        mx1 = fmaxf(mx1, __shfl_xor_sync(0xffffffffu, mx1, 2));
        const float mn0 = fmaxf(mr0, mx0);
        const float mn1 = fmaxf(mr1, mx1);
        const float al0 = __expf(mr0 - mn0);
        const float al1 = __expf(mr1 - mn1);
        mr0 = mn0; mr1 = mn1;
        float ls0 = 0.f, ls1 = 0.f;
#pragma unroll
        for (int na = 0; na < 8; na++) {
            s[na][0] = __expf(s[na][0] - mn0);
            s[na][1] = __expf(s[na][1] - mn0);
            s[na][2] = __expf(s[na][2] - mn1);
            s[na][3] = __expf(s[na][3] - mn1);
            ls0 += s[na][0] + s[na][1];
            ls1 += s[na][2] + s[na][3];
        }
        ls0 += __shfl_xor_sync(0xffffffffu, ls0, 1);
        ls0 += __shfl_xor_sync(0xffffffffu, ls0, 2);
        ls1 += __shfl_xor_sync(0xffffffffu, ls1, 1);
        ls1 += __shfl_xor_sync(0xffffffffu, ls1, 2);
        lr0 = lr0 * al0 + ls0;
        lr1 = lr1 * al1 + ls1;
#pragma unroll
        for (int na = 0; na < 8; na++) {
            o[na][0] *= al0; o[na][1] *= al0;
            o[na][2] *= al1; o[na][3] *= al1;
        }

        // ---- P @ V (fp16 x2: single-plane P, hi/lo V)
#pragma unroll
        for (int kt = 0; kt < 4; kt++) {
            uint32_t ph[4];
            ph[0] = packh2(s[2*kt][0],   s[2*kt][1]);
            ph[1] = packh2(s[2*kt][2],   s[2*kt][3]);
            ph[2] = packh2(s[2*kt+1][0], s[2*kt+1][1]);
            ph[3] = packh2(s[2*kt+1][2], s[2*kt+1][3]);

            uint32_t vh[8][2], vl[8][2];
#pragma unroll
            for (int dp = 0; dp < 4; dp++) {
                const uint32_t byte = (uint32_t)((kt * 16 + (lane & 15)) * 128
                                                 + dp * 32 + (lane >> 4) * 16);
                const uint32_t sw = SMEM_SWIZZLE_128B(byte);
                LDSM_X4_T(vh[2*dp][0], vh[2*dp][1], vh[2*dp+1][0], vh[2*dp+1][1],
                          kvb + AS_VHI + sw);
                LDSM_X4_T(vl[2*dp][0], vl[2*dp][1], vl[2*dp+1][0], vl[2*dp+1][1],
                          kvb + AS_VLO + sw);
            }
#pragma unroll
            for (int na = 0; na < 8; na++) {
                MMAF16(o[na], ph, vh[na]);
                MMAF16(o[na], ph, vl[na]);
            }
        }
        __syncthreads();
    }

    // ---- epilogue: normalize, write single fp16 plane
    const float inv0 = 1.f / lr0;
    const float inv1 = 1.f / lr1;
    const int row0 = q0 + wid * 16 + (lane >> 2);
#pragma unroll
    for (int na = 0; na < 8; na++) {
        const int col = h * H_DIM + na * 8 + (lane & 3) * 2;
        const size_t i0 = (size_t)(b * SQ + row0) * E_DIM + col;
        const size_t i1 = (size_t)(b * SQ + row0 + 8) * E_DIM + col;
        *(uint32_t*)(Oh + i0) = packh2(o[na][0] * inv0, o[na][1] * inv0);
        *(uint32_t*)(Oh + i1) = packh2(o[na][2] * inv1, o[na][3] * inv1);
    }
}

// ---------------------------------------------------------------------------
extern "C" void kernel_launch(void* const* d_in, const int* in_sizes, int n_in,
                              void* d_out, int out_size)
{
    const float* x1 = (const float*)d_in[0];
    const float* x2 = (const float*)d_in[1];
    const float* Wq = (const float*)d_in[2];
    const float* bq = (const float*)d_in[3];
    const float* Wk = (const float*)d_in[4];
    const float* bk = (const float*)d_in[5];
    const float* Wv = (const float*)d_in[6];
    const float* bv = (const float*)d_in[7];
    const float* Wo = (const float*)d_in[8];
    const float* bo = (const float*)d_in[9];
    float* out = (float*)d_out;

    uint16_t *x1h, *x2h;
    uint16_t *wqh, *wql, *wkh, *wkl, *wvh, *wvl, *woh, *wol;
    uint16_t *qh, *ql, *kh, *kl, *vh, *vl, *ah;
    cudaGetSymbolAddress((void**)&x1h, g_x1h);
    cudaGetSymbolAddress((void**)&x2h, g_x2h);
    cudaGetSymbolAddress((void**)&wqh, g_wqh); cudaGetSymbolAddress((void**)&wql, g_wql);
    cudaGetSymbolAddress((void**)&wkh, g_wkh); cudaGetSymbolAddress((void**)&wkl, g_wkl);
    cudaGetSymbolAddress((void**)&wvh, g_wvh); cudaGetSymbolAddress((void**)&wvl, g_wvl);
    cudaGetSymbolAddress((void**)&woh, g_woh); cudaGetSymbolAddress((void**)&wol, g_wol);
    cudaGetSymbolAddress((void**)&qh,  g_qh);  cudaGetSymbolAddress((void**)&ql,  g_ql);
    cudaGetSymbolAddress((void**)&kh,  g_kh);  cudaGetSymbolAddress((void**)&kl,  g_kl);
    cudaGetSymbolAddress((void**)&vh,  g_vh);  cudaGetSymbolAddress((void**)&vl,  g_vl);
    cudaGetSymbolAddress((void**)&ah,  g_ah);

    cudaFuncSetAttribute(gemm_qkv, cudaFuncAttributeMaxDynamicSharedMemorySize, G_SMEM);
    cudaFuncSetAttribute(gemm_out, cudaFuncAttributeMaxDynamicSharedMemorySize, G_SMEM);
    cudaFuncSetAttribute(attn_mma, cudaFuncAttributeMaxDynamicSharedMemorySize, ATT_SMEM);

    dim3 blk(256);

    // ---- stage 1: all plane conversions, one launch
    cvt_all<<<dim3(MKV * E_DIM / 8 / 256, 6), blk>>>(
        x1, x2, Wq, Wk, Wv, Wo,
        x1h, x2h,
        wqh, wql, wkh, wkl, wvh, wvl, woh, wol);

    // ---- stage 2: fused Q/K/V projections, one launch
    gemm_qkv<<<dim3(8, MKV / 128, 3), blk, G_SMEM>>>(
        x1h, x2h,
        wqh, wql, wkh, wkl, wvh, wvl,
        bq, bk, bv,
        qh, ql, kh, kl, vh, vl);

    // ---- stage 3: attention
    attn_mma<<<dim3(SQ / 128, N_HEADS, BATCH), blk, ATT_SMEM>>>(
        qh, ql, kh, kl, vh, vl, ah);

    // ---- stage 4: output projection (fp32 out)
    gemm_out<<<dim3(8, MQ / 128), blk, G_SMEM>>>(ah, woh, wol, bo, out);
}

// round 10
// speedup vs baseline: 5.4897x; 1.1770x over previous
#include <cuda_runtime.h>
#include <cuda_fp16.h>
#include <cstdint>
#include <math.h>

// Problem constants
#define E_DIM   1024
#define N_HEADS 16
#define H_DIM   64
#define BATCH   4
#define SQ      1024
#define SKV     2048
#define MQ      (BATCH * SQ)    // 4096
#define MKV     (BATCH * SKV)   // 8192

// ---------------------------------------------------------------------------
// Persistent planes (device globals; allocation-free rule). All fp16.
//   activations x1,x2: single plane      weights: hi/lo
//   Q: single plane (pre-scaled 1/8)     K: hi/lo     V: single plane
//   attn out: single plane
// ---------------------------------------------------------------------------
__device__ __align__(16) uint16_t g_x1h[MQ * E_DIM];
__device__ __align__(16) uint16_t g_x2h[MKV * E_DIM];
__device__ __align__(16) uint16_t g_wqh[E_DIM * E_DIM], g_wql[E_DIM * E_DIM];
__device__ __align__(16) uint16_t g_wkh[E_DIM * E_DIM], g_wkl[E_DIM * E_DIM];
__device__ __align__(16) uint16_t g_wvh[E_DIM * E_DIM], g_wvl[E_DIM * E_DIM];
__device__ __align__(16) uint16_t g_woh[E_DIM * E_DIM], g_wol[E_DIM * E_DIM];
__device__ __align__(16) uint16_t g_qh[MQ * E_DIM];
__device__ __align__(16) uint16_t g_kh[MKV * E_DIM], g_kl[MKV * E_DIM];
__device__ __align__(16) uint16_t g_vh[MKV * E_DIM];
__device__ __align__(16) uint16_t g_ah[MQ * E_DIM];

// ---------------------------------------------------------------------------
// Helpers
// ---------------------------------------------------------------------------
#define SMEM_SWIZZLE_128B(off) ((off) ^ (((off) >> 3) & 0x70))
#define SMEM_SWIZZLE_64B(off)  ((off) ^ (((off) >> 3) & 0x30))

#define LDSM_X4(r0_,r1_,r2_,r3_,addr_) \
    asm volatile("ldmatrix.sync.aligned.m8n8.x4.shared.b16 {%0,%1,%2,%3}, [%4];" \
        : "=r"(r0_), "=r"(r1_), "=r"(r2_), "=r"(r3_) : "r"(addr_))

#define LDSM_X4_T(r0_,r1_,r2_,r3_,addr_) \
    asm volatile("ldmatrix.sync.aligned.m8n8.x4.trans.shared.b16 {%0,%1,%2,%3}, [%4];" \
        : "=r"(r0_), "=r"(r1_), "=r"(r2_), "=r"(r3_) : "r"(addr_))

#define MMAF16(d_,a_,b_) \
    asm volatile("mma.sync.aligned.m16n8k16.row.col.f32.f16.f16.f32 " \
        "{%0,%1,%2,%3}, {%4,%5,%6,%7}, {%8,%9}, {%0,%1,%2,%3};" \
        : "+f"((d_)[0]), "+f"((d_)[1]), "+f"((d_)[2]), "+f"((d_)[3]) \
        : "r"((a_)[0]), "r"((a_)[1]), "r"((a_)[2]), "r"((a_)[3]), \
          "r"((b_)[0]), "r"((b_)[1]))

#define CP_ASYNC16(dst_, src_) \
    asm volatile("cp.async.cg.shared.global [%0], [%1], 16;" \
        :: "r"(dst_), "l"(src_))
#define CP_COMMIT() asm volatile("cp.async.commit_group;" ::: "memory")
#define CP_WAIT2()  asm volatile("cp.async.wait_group 2;" ::: "memory")
#define CP_WAIT1()  asm volatile("cp.async.wait_group 1;" ::: "memory")
#define CP_WAIT0()  asm volatile("cp.async.wait_group 0;" ::: "memory")

__device__ __forceinline__ uint32_t packh2(float x, float y) {
    __half2 t = __floats2half2_rn(x, y);
    return *(uint32_t*)&t;
}
__device__ __forceinline__ float hlo(float v) {
    return v - __half2float(__float2half_rn(v));
}

// fp16 hi/lo split of 8 floats (weights)
__device__ __forceinline__ void cvt8h(const float4 f0, const float4 f1,
                                      uint4& hi, uint4& lo) {
    float v[8] = {f0.x, f0.y, f0.z, f0.w, f1.x, f1.y, f1.z, f1.w};
    uint32_t h[8], l[8];
#pragma unroll
    for (int i = 0; i < 8; i++) {
        __half hb = __float2half_rn(v[i]);
        float hf = __half2float(hb);
        __half lb = __float2half_rn(v[i] - hf);
        h[i] = *(unsigned short*)&hb;
        l[i] = *(unsigned short*)&lb;
    }
    hi.x = h[0] | (h[1] << 16); hi.y = h[2] | (h[3] << 16);
    hi.z = h[4] | (h[5] << 16); hi.w = h[6] | (h[7] << 16);
    lo.x = l[0] | (l[1] << 16); lo.y = l[2] | (l[3] << 16);
    lo.z = l[4] | (l[5] << 16); lo.w = l[6] | (l[7] << 16);
}

// ---------------------------------------------------------------------------
// ALL fp32 -> plane conversions in ONE launch.
// m=0,1: activations -> single fp16 plane.  m=2..5: weights -> fp16 hi/lo.
// ---------------------------------------------------------------------------
__global__ void __launch_bounds__(256) cvt_all(
    const float* __restrict__ x1, const float* __restrict__ x2,
    const float* __restrict__ w0, const float* __restrict__ w1,
    const float* __restrict__ w2, const float* __restrict__ w3,
    uint16_t* __restrict__ x1h, uint16_t* __restrict__ x2h,
    uint16_t* __restrict__ h0, uint16_t* __restrict__ l0,
    uint16_t* __restrict__ h1, uint16_t* __restrict__ l1,
    uint16_t* __restrict__ h2, uint16_t* __restrict__ l2,
    uint16_t* __restrict__ h3, uint16_t* __restrict__ l3)
{
    const int m = blockIdx.y;
    const int idx = blockIdx.x * 256 + threadIdx.x;
    if (m == 0 || m == 1) {
        const float* in = (m == 0) ? x1 : x2;
        uint16_t* hi    = (m == 0) ? x1h : x2h;
        const int n8    = (m == 0) ? MQ * E_DIM / 8 : MKV * E_DIM / 8;
        if (idx >= n8) return;
        const float4 f0 = ((const float4*)in)[2 * idx];
        const float4 f1 = ((const float4*)in)[2 * idx + 1];
        uint4 h;
        h.x = packh2(f0.x, f0.y); h.y = packh2(f0.z, f0.w);
        h.z = packh2(f1.x, f1.y); h.w = packh2(f1.z, f1.w);
        ((uint4*)hi)[idx] = h;
        return;
    }
    const float* in; uint16_t* hi; uint16_t* lo;
    switch (m) {
        case 2: in = w0; hi = h0; lo = l0; break;
        case 3: in = w1; hi = h1; lo = l1; break;
        case 4: in = w2; hi = h2; lo = l2; break;
        default:in = w3; hi = h3; lo = l3; break;
    }
    if (idx >= E_DIM * E_DIM / 8) return;
    const float4 f0 = ((const float4*)in)[2 * idx];
    const float4 f1 = ((const float4*)in)[2 * idx + 1];
    uint4 h, l;
    cvt8h(f0, f1, h, l);
    ((uint4*)hi)[idx] = h;
    ((uint4*)lo)[idx] = l;
}

// ---------------------------------------------------------------------------
// fp16 x2 HMMA GEMM body: A single fp16 plane, B fp16 hi/lo.
//   C = A @ B^T (+bias)(*scale);  D = A*Bh + A*Bl  (2 MMAs per k-step)
// 4-stage cp.async ring, 24KB/stage = 96KB smem, 2 CTAs/SM.
// wmode: 0 = fp32 out, 2 = fp16 hi/lo planes, 3 = fp16 single plane
// ---------------------------------------------------------------------------
#define GS_A    0
#define GS_BHI  8192
#define GS_BLO  16384
#define G_STAGE 24576
#define G_SMEM  98304       // 4 stages
#define G_NCHUNK 32

__device__ __forceinline__ void gemm_body(
    const uint16_t* __restrict__ Ah,
    const uint16_t* __restrict__ Bh, const uint16_t* __restrict__ Bl,
    const float* __restrict__ bias, float scale,
    float* __restrict__ Cf, uint16_t* __restrict__ Ch, uint16_t* __restrict__ Cl,
    const int wmode, char* smem, const int m0, const int n0)
{
    const uint32_t sb = (uint32_t)__cvta_generic_to_shared(smem);
    const int tid  = threadIdx.x;
    const int wid  = tid >> 5;
    const int lane = tid & 31;

    const int warp_m = (wid & 1) * 64;
    const int warp_n = (wid >> 1) * 32;
    const int g = lane >> 3;
    const int r = lane & 7;

    float acc[4][4][4];
#pragma unroll
    for (int mi = 0; mi < 4; mi++)
#pragma unroll
        for (int ni = 0; ni < 4; ni++)
#pragma unroll
            for (int q = 0; q < 4; q++) acc[mi][ni][q] = 0.f;

    const int a_row = warp_m + (g & 1) * 8 + r;
    const int a_kc  = (g >> 1) * 8;
    const int b_row = warp_n + (g >> 1) * 8 + r;
    const int b_kc  = (g & 1) * 8;

    auto load_stage = [&](int stage, int ch) {
        const uint32_t sbase = sb + stage * G_STAGE;
#pragma unroll
        for (int it = 0; it < 2; it++) {
            const int idx = it * 256 + tid;     // 0..511
            const int row = idx >> 2;           // 0..127
            const int seg = idx & 3;            // 16B segment
            const uint32_t sw = SMEM_SWIZZLE_64B((uint32_t)(row * 64 + seg * 16));
            const size_t ga = (size_t)(m0 + row) * E_DIM + ch * 32 + seg * 8;
            const size_t gb = (size_t)(n0 + row) * E_DIM + ch * 32 + seg * 8;
            CP_ASYNC16(sbase + GS_A   + sw, (const char*)(Ah + ga));
            CP_ASYNC16(sbase + GS_BHI + sw, (const char*)(Bh + gb));
            CP_ASYNC16(sbase + GS_BLO + sw, (const char*)(Bl + gb));
        }
    };

    load_stage(0, 0); CP_COMMIT();
    load_stage(1, 1); CP_COMMIT();
    load_stage(2, 2); CP_COMMIT();

    for (int ch = 0; ch < G_NCHUNK; ch++) {
        if (ch < G_NCHUNK - 2) CP_WAIT2(); else CP_WAIT0();
        __syncthreads();
        if (ch + 3 < G_NCHUNK) { load_stage((ch + 3) & 3, ch + 3); CP_COMMIT(); }

        const uint32_t sbase = sb + (ch & 3) * G_STAGE;
#pragma unroll
        for (int ks = 0; ks < 2; ks++) {
            uint32_t ah[4][4];
#pragma unroll
            for (int mi = 0; mi < 4; mi++) {
                const uint32_t sw = SMEM_SWIZZLE_64B(
                    (uint32_t)((a_row + mi * 16) * 64 + (a_kc + ks * 16) * 2));
                LDSM_X4(ah[mi][0], ah[mi][1], ah[mi][2], ah[mi][3], sbase + GS_A + sw);
            }
            uint32_t bh[4][2], bl[4][2];
#pragma unroll
            for (int np = 0; np < 2; np++) {
                const uint32_t sw = SMEM_SWIZZLE_64B(
                    (uint32_t)((b_row + np * 16) * 64 + (b_kc + ks * 16) * 2));
                LDSM_X4(bh[2*np][0], bh[2*np][1], bh[2*np+1][0], bh[2*np+1][1],
                        sbase + GS_BHI + sw);
                LDSM_X4(bl[2*np][0], bl[2*np][1], bl[2*np+1][0], bl[2*np+1][1],
                        sbase + GS_BLO + sw);
            }
#pragma unroll
            for (int mi = 0; mi < 4; mi++)
#pragma unroll
                for (int ni = 0; ni < 4; ni++) {
                    MMAF16(acc[mi][ni], ah[mi], bh[ni]);
                    MMAF16(acc[mi][ni], ah[mi], bl[ni]);
                }
        }
    }

    // ---- epilogue
    const int erow = lane >> 2;
    const int ecol = (lane & 3) * 2;
#pragma unroll
    for (int ni = 0; ni < 4; ni++) {
        const int col = n0 + warp_n + ni * 8 + ecol;
        const float bv0 = __ldg(bias + col);
        const float bv1 = __ldg(bias + col + 1);
#pragma unroll
        for (int mi = 0; mi < 4; mi++) {
            const int row = m0 + warp_m + mi * 16 + erow;
            float v00 = (acc[mi][ni][0] + bv0) * scale;
            float v01 = (acc[mi][ni][1] + bv1) * scale;
            float v10 = (acc[mi][ni][2] + bv0) * scale;
            float v11 = (acc[mi][ni][3] + bv1) * scale;
            if (wmode == 2) {
                *(uint32_t*)(Ch + (size_t)row * E_DIM + col)       = packh2(v00, v01);
                *(uint32_t*)(Cl + (size_t)row * E_DIM + col)       = packh2(hlo(v00), hlo(v01));
                *(uint32_t*)(Ch + (size_t)(row + 8) * E_DIM + col) = packh2(v10, v11);
                *(uint32_t*)(Cl + (size_t)(row + 8) * E_DIM + col) = packh2(hlo(v10), hlo(v11));
            } else if (wmode == 3) {
                *(uint32_t*)(Ch + (size_t)row * E_DIM + col)       = packh2(v00, v01);
                *(uint32_t*)(Ch + (size_t)(row + 8) * E_DIM + col) = packh2(v10, v11);
            } else {
                float2 a = {v00, v01}, b = {v10, v11};
                *(float2*)(Cf + (size_t)row * E_DIM + col)       = a;
                *(float2*)(Cf + (size_t)(row + 8) * E_DIM + col) = b;
            }
        }
    }
}

// ---- fused Q/K/V projections: grid (8, 64, 3); z=0 uses only y<32
__global__ void __launch_bounds__(256, 2) gemm_qkv(
    const uint16_t* __restrict__ x1h, const uint16_t* __restrict__ x2h,
    const uint16_t* __restrict__ wqh, const uint16_t* __restrict__ wql,
    const uint16_t* __restrict__ wkh, const uint16_t* __restrict__ wkl,
    const uint16_t* __restrict__ wvh, const uint16_t* __restrict__ wvl,
    const float* __restrict__ bq, const float* __restrict__ bk,
    const float* __restrict__ bv,
    uint16_t* __restrict__ qh,
    uint16_t* __restrict__ kh, uint16_t* __restrict__ kl,
    uint16_t* __restrict__ vh)
{
    extern __shared__ char smem[];
    const int z = blockIdx.z;
    if (z == 0 && blockIdx.y >= MQ / 128) return;
    if (z == 0) {
        gemm_body(x1h, wqh, wql, bq, 0.125f, nullptr, qh, nullptr, 3,
                  smem, blockIdx.y * 128, blockIdx.x * 128);
    } else if (z == 1) {
        gemm_body(x2h, wkh, wkl, bk, 1.0f, nullptr, kh, kl, 2,
                  smem, blockIdx.y * 128, blockIdx.x * 128);
    } else {
        gemm_body(x2h, wvh, wvl, bv, 1.0f, nullptr, vh, nullptr, 3,
                  smem, blockIdx.y * 128, blockIdx.x * 128);
    }
}

// ---- output projection (fp32 out)
__global__ void __launch_bounds__(256, 2) gemm_out(
    const uint16_t* __restrict__ Ah,
    const uint16_t* __restrict__ Bh, const uint16_t* __restrict__ Bl,
    const float* __restrict__ bias, float* __restrict__ Cf)
{
    extern __shared__ char smem[];
    gemm_body(Ah, Bh, Bl, bias, 1.0f, Cf, nullptr, nullptr, 0,
              smem, blockIdx.y * 128, blockIdx.x * 128);
}

// ---------------------------------------------------------------------------
// Flash attention v2 on fp16 HMMA.
//   S = Q*Kh + Q*Kl (2 MMAs); PV = P*V (1 MMA). All fp16 operands, fp32 acc.
// CTA = (b, h, 128 q rows); 8 warps x 16 q rows. KV chunk 64, double-buffered.
// Output: single fp16 plane.
// ---------------------------------------------------------------------------
#define AS_Q    0          // 128 rows x 128B = 16KB (single fp16 plane)
#define AS_KV   16384      // stage base
#define AS_KHI  0
#define AS_KLO  8192
#define AS_V    16384
#define A_STAGE 24576
#define ATT_SMEM 65536     // 16KB Q + 2 x 24KB KV
#define NEG_BIG (-3.0e38f)

__global__ void __launch_bounds__(256, 2) attn_mma(
    const uint16_t* __restrict__ Qh,
    const uint16_t* __restrict__ Kh, const uint16_t* __restrict__ Kl,
    const uint16_t* __restrict__ Vh,
    uint16_t* __restrict__ Oh)
{
    extern __shared__ char smem[];
    const uint32_t sb = (uint32_t)__cvta_generic_to_shared(smem);
    const int b  = blockIdx.z;
    const int h  = blockIdx.y;
    const int q0 = blockIdx.x * 128;
    const int tid  = threadIdx.x;
    const int wid  = tid >> 5;
    const int lane = tid & 31;
    const int g = lane >> 3;
    const int r = lane & 7;

    // ---- Q tile 128x64 (single plane) via cp.async
#pragma unroll
    for (int it = 0; it < 4; it++) {
        const int idx = it * 256 + tid;
        const int row = idx >> 3;
        const int seg = idx & 7;
        const uint32_t sw = SMEM_SWIZZLE_128B((uint32_t)(row * 128 + seg * 16));
        const size_t gq = (size_t)(b * SQ + q0 + row) * E_DIM + h * H_DIM + seg * 8;
        CP_ASYNC16(sb + AS_Q + sw, (const char*)(Qh + gq));
    }
    CP_COMMIT();

    auto load_kv = [&](int stage, int c) {
        const uint32_t sbase = sb + AS_KV + stage * A_STAGE;
#pragma unroll
        for (int it = 0; it < 2; it++) {
            const int idx = it * 256 + tid;
            const int row = idx >> 3;
            const int seg = idx & 7;
            const uint32_t sw = SMEM_SWIZZLE_128B((uint32_t)(row * 128 + seg * 16));
            const size_t gk = (size_t)(b * SKV + c + row) * E_DIM + h * H_DIM + seg * 8;
            CP_ASYNC16(sbase + AS_KHI + sw, (const char*)(Kh + gk));
            CP_ASYNC16(sbase + AS_KLO + sw, (const char*)(Kl + gk));
            CP_ASYNC16(sbase + AS_V   + sw, (const char*)(Vh + gk));
        }
    };

    load_kv(0, 0);
    CP_COMMIT();
    CP_WAIT1();          // Q ready
    __syncthreads();

    // ---- persistent Q fragments
    const int a_row = wid * 16 + (g & 1) * 8 + r;
    const int a_kc  = (g >> 1) * 8;
    uint32_t qf[4][4];
#pragma unroll
    for (int ks = 0; ks < 4; ks++) {
        const uint32_t sw = SMEM_SWIZZLE_128B((uint32_t)(a_row * 128 + (a_kc + ks * 16) * 2));
        LDSM_X4(qf[ks][0], qf[ks][1], qf[ks][2], qf[ks][3], sb + AS_Q + sw);
    }

    float o[8][4];
#pragma unroll
    for (int na = 0; na < 8; na++)
#pragma unroll
        for (int q = 0; q < 4; q++) o[na][q] = 0.f;
    float mr0 = NEG_BIG, mr1 = NEG_BIG, lr0 = 0.f, lr1 = 0.f;

    const int kb_row = (g >> 1) * 8 + r;
    const int kb_kc  = (g & 1) * 8;

    const int NCH = SKV / 64;   // 32
    for (int cc = 0; cc < NCH; cc++) {
        const int buf = cc & 1;
        if (cc + 1 < NCH) { load_kv(buf ^ 1, (cc + 1) * 64); CP_COMMIT(); CP_WAIT1(); }
        else              { CP_WAIT0(); }
        __syncthreads();
        const uint32_t kvb = sb + AS_KV + buf * A_STAGE;

        // ---- S = Q K^T (fp16 x2)
        float s[8][4];
#pragma unroll
        for (int na = 0; na < 8; na++)
#pragma unroll
            for (int q = 0; q < 4; q++) s[na][q] = 0.f;

#pragma unroll
        for (int ks = 0; ks < 4; ks++) {
            uint32_t kh[8][2], kl[8][2];
#pragma unroll
            for (int np = 0; np < 4; np++) {
                const uint32_t sw = SMEM_SWIZZLE_128B(
                    (uint32_t)((np * 16 + kb_row) * 128 + (kb_kc + ks * 16) * 2));
                LDSM_X4(kh[2*np][0], kh[2*np][1], kh[2*np+1][0], kh[2*np+1][1],
                        kvb + AS_KHI + sw);
                LDSM_X4(kl[2*np][0], kl[2*np][1], kl[2*np+1][0], kl[2*np+1][1],
                        kvb + AS_KLO + sw);
            }
#pragma unroll
            for (int na = 0; na < 8; na++) {
                MMAF16(s[na], qf[ks], kh[na]);
                MMAF16(s[na], qf[ks], kl[na]);
            }
        }

        // ---- online softmax
        float mx0 = NEG_BIG, mx1 = NEG_BIG;
#pragma unroll
        for (int na = 0; na < 8; na++) {
            mx0 = fmaxf(mx0, fmaxf(s[na][0], s[na][1]));
            mx1 = fmaxf(mx1, fmaxf(s[na][2], s[na][3]));
        }
        mx0 = fmaxf(mx0, __shfl_xor_sync(0xffffffffu, mx0, 1));
        mx0 = fmaxf(mx0, __shfl_xor_sync(0xffffffffu, mx0, 2));
        mx1 = fmaxf(mx1, __shfl_xor_sync(0xffffffffu, mx1, 1));
        mx1 = fmaxf(mx1, __shfl_xor_sync(0xffffffffu, mx1, 2));
        const float mn0 = fmaxf(mr0, mx0);
        const float mn1 = fmaxf(mr1, mx1);
        const float al0 = __expf(mr0 - mn0);
        const float al1 = __expf(mr1 - mn1);
        mr0 = mn0; mr1 = mn1;
        float ls0 = 0.f, ls1 = 0.f;
#pragma unroll
        for (int na = 0; na < 8; na++) {
            s[na][0] = __expf(s[na][0] - mn0);
            s[na][1] = __expf(s[na][1] - mn0);
            s[na][2] = __expf(s[na][2] - mn1);
            s[na][3] = __expf(s[na][3] - mn1);
            ls0 += s[na][0] + s[na][1];
            ls1 += s[na][2] + s[na][3];
        }
        ls0 += __shfl_xor_sync(0xffffffffu, ls0, 1);
        ls0 += __shfl_xor_sync(0xffffffffu, ls0, 2);
        ls1 += __shfl_xor_sync(0xffffffffu, ls1, 1);
        ls1 += __shfl_xor_sync(0xffffffffu, ls1, 2);
        lr0 = lr0 * al0 + ls0;
        lr1 = lr1 * al1 + ls1;
#pragma unroll
        for (int na = 0; na < 8; na++) {
            o[na][0] *= al0; o[na][1] *= al0;
            o[na][2] *= al1; o[na][3] *= al1;
        }

        // ---- P @ V (fp16 x1: single-plane P and V)
#pragma unroll
        for (int kt = 0; kt < 4; kt++) {
            uint32_t ph[4];
            ph[0] = packh2(s[2*kt][0],   s[2*kt][1]);
            ph[1] = packh2(s[2*kt][2],   s[2*kt][3]);
            ph[2] = packh2(s[2*kt+1][0], s[2*kt+1][1]);
            ph[3] = packh2(s[2*kt+1][2], s[2*kt+1][3]);

            uint32_t vh[8][2];
#pragma unroll
            for (int dp = 0; dp < 4; dp++) {
                const uint32_t byte = (uint32_t)((kt * 16 + (lane & 15)) * 128
                                                 + dp * 32 + (lane >> 4) * 16);
                const uint32_t sw = SMEM_SWIZZLE_128B(byte);
                LDSM_X4_T(vh[2*dp][0], vh[2*dp][1], vh[2*dp+1][0], vh[2*dp+1][1],
                          kvb + AS_V + sw);
            }
#pragma unroll
            for (int na = 0; na < 8; na++) {
                MMAF16(o[na], ph, vh[na]);
            }
        }
        __syncthreads();
    }

    // ---- epilogue: normalize, write single fp16 plane
    const float inv0 = 1.f / lr0;
    const float inv1 = 1.f / lr1;
    const int row0 = q0 + wid * 16 + (lane >> 2);
#pragma unroll
    for (int na = 0; na < 8; na++) {
        const int col = h * H_DIM + na * 8 + (lane & 3) * 2;
        const size_t i0 = (size_t)(b * SQ + row0) * E_DIM + col;
        const size_t i1 = (size_t)(b * SQ + row0 + 8) * E_DIM + col;
        *(uint32_t*)(Oh + i0) = packh2(o[na][0] * inv0, o[na][1] * inv0);
        *(uint32_t*)(Oh + i1) = packh2(o[na][2] * inv1, o[na][3] * inv1);
    }
}

// ---------------------------------------------------------------------------
extern "C" void kernel_launch(void* const* d_in, const int* in_sizes, int n_in,
                              void* d_out, int out_size)
{
    const float* x1 = (const float*)d_in[0];
    const float* x2 = (const float*)d_in[1];
    const float* Wq = (const float*)d_in[2];
    const float* bq = (const float*)d_in[3];
    const float* Wk = (const float*)d_in[4];
    const float* bk = (const float*)d_in[5];
    const float* Wv = (const float*)d_in[6];
    const float* bv = (const float*)d_in[7];
    const float* Wo = (const float*)d_in[8];
    const float* bo = (const float*)d_in[9];
    float* out = (float*)d_out;

    uint16_t *x1h, *x2h;
    uint16_t *wqh, *wql, *wkh, *wkl, *wvh, *wvl, *woh, *wol;
    uint16_t *qh, *kh, *kl, *vh, *ah;
    cudaGetSymbolAddress((void**)&x1h, g_x1h);
    cudaGetSymbolAddress((void**)&x2h, g_x2h);
    cudaGetSymbolAddress((void**)&wqh, g_wqh); cudaGetSymbolAddress((void**)&wql, g_wql);
    cudaGetSymbolAddress((void**)&wkh, g_wkh); cudaGetSymbolAddress((void**)&wkl, g_wkl);
    cudaGetSymbolAddress((void**)&wvh, g_wvh); cudaGetSymbolAddress((void**)&wvl, g_wvl);
    cudaGetSymbolAddress((void**)&woh, g_woh); cudaGetSymbolAddress((void**)&wol, g_wol);
    cudaGetSymbolAddress((void**)&qh,  g_qh);
    cudaGetSymbolAddress((void**)&kh,  g_kh);  cudaGetSymbolAddress((void**)&kl,  g_kl);
    cudaGetSymbolAddress((void**)&vh,  g_vh);
    cudaGetSymbolAddress((void**)&ah,  g_ah);

    cudaFuncSetAttribute(gemm_qkv, cudaFuncAttributeMaxDynamicSharedMemorySize, G_SMEM);
    cudaFuncSetAttribute(gemm_out, cudaFuncAttributeMaxDynamicSharedMemorySize, G_SMEM);
    cudaFuncSetAttribute(attn_mma, cudaFuncAttributeMaxDynamicSharedMemorySize, ATT_SMEM);

    dim3 blk(256);

    // ---- stage 1: all plane conversions, one launch
    cvt_all<<<dim3(MKV * E_DIM / 8 / 256, 6), blk>>>(
        x1, x2, Wq, Wk, Wv, Wo,
        x1h, x2h,
        wqh, wql, wkh, wkl, wvh, wvl, woh, wol);

    // ---- stage 2: fused Q/K/V projections, one launch
    gemm_qkv<<<dim3(8, MKV / 128, 3), blk, G_SMEM>>>(
        x1h, x2h,
        wqh, wql, wkh, wkl, wvh, wvl,
        bq, bk, bv,
        qh, kh, kl, vh);

    // ---- stage 3: attention
    attn_mma<<<dim3(SQ / 128, N_HEADS, BATCH), blk, ATT_SMEM>>>(
        qh, kh, kl, vh, ah);

    // ---- stage 4: output projection (fp32 out)
    gemm_out<<<dim3(8, MQ / 128), blk, G_SMEM>>>(ah, woh, wol, bo, out);
}

// round 11
// speedup vs baseline: 6.3969x; 1.1653x over previous
#include <cuda_runtime.h>
#include <cuda_fp16.h>
#include <cstdint>
#include <math.h>

// Problem constants
#define E_DIM   1024
#define N_HEADS 16
#define H_DIM   64
#define BATCH   4
#define SQ      1024
#define SKV     2048
#define MQ      (BATCH * SQ)    // 4096
#define MKV     (BATCH * SKV)   // 8192

// ---------------------------------------------------------------------------
// Persistent planes (device globals). All fp16.
//   x1,x2: single plane     Wq,Wk: hi/lo     Wv,Wo: single plane
//   Q: single (pre-scaled 1/8)   K: hi/lo    V: single
//   attn out: single plane
// ---------------------------------------------------------------------------
__device__ __align__(16) uint16_t g_x1h[MQ * E_DIM];
__device__ __align__(16) uint16_t g_x2h[MKV * E_DIM];
__device__ __align__(16) uint16_t g_wqh[E_DIM * E_DIM], g_wql[E_DIM * E_DIM];
__device__ __align__(16) uint16_t g_wkh[E_DIM * E_DIM], g_wkl[E_DIM * E_DIM];
__device__ __align__(16) uint16_t g_wvh[E_DIM * E_DIM];
__device__ __align__(16) uint16_t g_woh[E_DIM * E_DIM];
__device__ __align__(16) uint16_t g_qh[MQ * E_DIM];
__device__ __align__(16) uint16_t g_kh[MKV * E_DIM], g_kl[MKV * E_DIM];
__device__ __align__(16) uint16_t g_vh[MKV * E_DIM];
__device__ __align__(16) uint16_t g_ah[MQ * E_DIM];

// ---------------------------------------------------------------------------
// Helpers
// ---------------------------------------------------------------------------
#define SMEM_SWIZZLE_128B(off) ((off) ^ (((off) >> 3) & 0x70))
#define SMEM_SWIZZLE_64B(off)  ((off) ^ (((off) >> 3) & 0x30))

#define LDSM_X4(r0_,r1_,r2_,r3_,addr_) \
    asm volatile("ldmatrix.sync.aligned.m8n8.x4.shared.b16 {%0,%1,%2,%3}, [%4];" \
        : "=r"(r0_), "=r"(r1_), "=r"(r2_), "=r"(r3_) : "r"(addr_))

#define LDSM_X4_T(r0_,r1_,r2_,r3_,addr_) \
    asm volatile("ldmatrix.sync.aligned.m8n8.x4.trans.shared.b16 {%0,%1,%2,%3}, [%4];" \
        : "=r"(r0_), "=r"(r1_), "=r"(r2_), "=r"(r3_) : "r"(addr_))

#define MMAF16(d_,a_,b_) \
    asm volatile("mma.sync.aligned.m16n8k16.row.col.f32.f16.f16.f32 " \
        "{%0,%1,%2,%3}, {%4,%5,%6,%7}, {%8,%9}, {%0,%1,%2,%3};" \
        : "+f"((d_)[0]), "+f"((d_)[1]), "+f"((d_)[2]), "+f"((d_)[3]) \
        : "r"((a_)[0]), "r"((a_)[1]), "r"((a_)[2]), "r"((a_)[3]), \
          "r"((b_)[0]), "r"((b_)[1]))

#define CP_ASYNC16(dst_, src_) \
    asm volatile("cp.async.cg.shared.global [%0], [%1], 16;" \
        :: "r"(dst_), "l"(src_))
#define CP_COMMIT() asm volatile("cp.async.commit_group;" ::: "memory")
#define CP_WAIT2()  asm volatile("cp.async.wait_group 2;" ::: "memory")
#define CP_WAIT1()  asm volatile("cp.async.wait_group 1;" ::: "memory")
#define CP_WAIT0()  asm volatile("cp.async.wait_group 0;" ::: "memory")

__device__ __forceinline__ uint32_t packh2(float x, float y) {
    __half2 t = __floats2half2_rn(x, y);
    return *(uint32_t*)&t;
}
__device__ __forceinline__ float hlo(float v) {
    return v - __half2float(__float2half_rn(v));
}

// fp16 hi/lo split of 8 floats
__device__ __forceinline__ void cvt8h(const float4 f0, const float4 f1,
                                      uint4& hi, uint4& lo) {
    float v[8] = {f0.x, f0.y, f0.z, f0.w, f1.x, f1.y, f1.z, f1.w};
    uint32_t h[8], l[8];
#pragma unroll
    for (int i = 0; i < 8; i++) {
        __half hb = __float2half_rn(v[i]);
        float hf = __half2float(hb);
        __half lb = __float2half_rn(v[i] - hf);
        h[i] = *(unsigned short*)&hb;
        l[i] = *(unsigned short*)&lb;
    }
    hi.x = h[0] | (h[1] << 16); hi.y = h[2] | (h[3] << 16);
    hi.z = h[4] | (h[5] << 16); hi.w = h[6] | (h[7] << 16);
    lo.x = l[0] | (l[1] << 16); lo.y = l[2] | (l[3] << 16);
    lo.z = l[4] | (l[5] << 16); lo.w = l[6] | (l[7] << 16);
}

// ---------------------------------------------------------------------------
// ALL fp32 -> plane conversions in ONE launch.
// m=0,1: x1,x2 -> single plane. m=2,3: Wq,Wk -> hi/lo. m=4,5: Wv,Wo -> single.
// ---------------------------------------------------------------------------
__global__ void __launch_bounds__(256) cvt_all(
    const float* __restrict__ x1, const float* __restrict__ x2,
    const float* __restrict__ w0, const float* __restrict__ w1,
    const float* __restrict__ w2, const float* __restrict__ w3,
    uint16_t* __restrict__ x1h, uint16_t* __restrict__ x2h,
    uint16_t* __restrict__ h0, uint16_t* __restrict__ l0,
    uint16_t* __restrict__ h1, uint16_t* __restrict__ l1,
    uint16_t* __restrict__ h2, uint16_t* __restrict__ h3)
{
    const int m = blockIdx.y;
    const int idx = blockIdx.x * 256 + threadIdx.x;
    if (m == 0 || m == 1 || m == 4 || m == 5) {
        const float* in; uint16_t* hi; int n8;
        switch (m) {
            case 0: in = x1; hi = x1h; n8 = MQ  * E_DIM / 8; break;
            case 1: in = x2; hi = x2h; n8 = MKV * E_DIM / 8; break;
            case 4: in = w2; hi = h2;  n8 = E_DIM * E_DIM / 8; break;
            default:in = w3; hi = h3;  n8 = E_DIM * E_DIM / 8; break;
        }
        if (idx >= n8) return;
        const float4 f0 = ((const float4*)in)[2 * idx];
        const float4 f1 = ((const float4*)in)[2 * idx + 1];
        uint4 h;
        h.x = packh2(f0.x, f0.y); h.y = packh2(f0.z, f0.w);
        h.z = packh2(f1.x, f1.y); h.w = packh2(f1.z, f1.w);
        ((uint4*)hi)[idx] = h;
        return;
    }
    const float* in = (m == 2) ? w0 : w1;
    uint16_t* hi    = (m == 2) ? h0 : h1;
    uint16_t* lo    = (m == 2) ? l0 : l1;
    if (idx >= E_DIM * E_DIM / 8) return;
    const float4 f0 = ((const float4*)in)[2 * idx];
    const float4 f1 = ((const float4*)in)[2 * idx + 1];
    uint4 h, l;
    cvt8h(f0, f1, h, l);
    ((uint4*)hi)[idx] = h;
    ((uint4*)lo)[idx] = l;
}

// ---------------------------------------------------------------------------
// fp16 HMMA GEMM body. TWO_B: B has hi/lo planes (2 MMAs/k-step) or single
// (1 MMA/k-step). 4-stage cp.async ring, 24KB/stage, 96KB smem, 2 CTAs/SM.
// wmode: 0 = fp32 out, 2 = fp16 hi/lo planes, 3 = fp16 single plane
// ---------------------------------------------------------------------------
#define GS_A    0
#define GS_BHI  8192
#define GS_BLO  16384
#define G_STAGE 24576
#define G_SMEM  98304       // 4 stages
#define G_NCHUNK 32

template<int WMODE, bool TWO_B>
__device__ __forceinline__ void gemm_body(
    const uint16_t* __restrict__ Ah,
    const uint16_t* __restrict__ Bh, const uint16_t* __restrict__ Bl,
    const float* __restrict__ bias, float scale,
    float* __restrict__ Cf, uint16_t* __restrict__ Ch, uint16_t* __restrict__ Cl,
    char* smem, const int m0, const int n0)
{
    const uint32_t sb = (uint32_t)__cvta_generic_to_shared(smem);
    const int tid  = threadIdx.x;
    const int wid  = tid >> 5;
    const int lane = tid & 31;

    const int warp_m = (wid & 1) * 64;
    const int warp_n = (wid >> 1) * 32;
    const int g = lane >> 3;
    const int r = lane & 7;

    float acc[4][4][4];
#pragma unroll
    for (int mi = 0; mi < 4; mi++)
#pragma unroll
        for (int ni = 0; ni < 4; ni++)
#pragma unroll
            for (int q = 0; q < 4; q++) acc[mi][ni][q] = 0.f;

    const int a_row = warp_m + (g & 1) * 8 + r;
    const int a_kc  = (g >> 1) * 8;
    const int b_row = warp_n + (g >> 1) * 8 + r;
    const int b_kc  = (g & 1) * 8;

    auto load_stage = [&](int stage, int ch) {
        const uint32_t sbase = sb + stage * G_STAGE;
#pragma unroll
        for (int it = 0; it < 2; it++) {
            const int idx = it * 256 + tid;     // 0..511
            const int row = idx >> 2;           // 0..127
            const int seg = idx & 3;            // 16B segment
            const uint32_t sw = SMEM_SWIZZLE_64B((uint32_t)(row * 64 + seg * 16));
            const size_t ga = (size_t)(m0 + row) * E_DIM + ch * 32 + seg * 8;
            const size_t gb = (size_t)(n0 + row) * E_DIM + ch * 32 + seg * 8;
            CP_ASYNC16(sbase + GS_A   + sw, (const char*)(Ah + ga));
            CP_ASYNC16(sbase + GS_BHI + sw, (const char*)(Bh + gb));
            if (TWO_B)
                CP_ASYNC16(sbase + GS_BLO + sw, (const char*)(Bl + gb));
        }
    };

    load_stage(0, 0); CP_COMMIT();
    load_stage(1, 1); CP_COMMIT();
    load_stage(2, 2); CP_COMMIT();

    for (int ch = 0; ch < G_NCHUNK; ch++) {
        if (ch < G_NCHUNK - 2) CP_WAIT2(); else CP_WAIT0();
        __syncthreads();
        if (ch + 3 < G_NCHUNK) { load_stage((ch + 3) & 3, ch + 3); CP_COMMIT(); }

        const uint32_t sbase = sb + (ch & 3) * G_STAGE;
#pragma unroll
        for (int ks = 0; ks < 2; ks++) {
            uint32_t ah[4][4];
#pragma unroll
            for (int mi = 0; mi < 4; mi++) {
                const uint32_t sw = SMEM_SWIZZLE_64B(
                    (uint32_t)((a_row + mi * 16) * 64 + (a_kc + ks * 16) * 2));
                LDSM_X4(ah[mi][0], ah[mi][1], ah[mi][2], ah[mi][3], sbase + GS_A + sw);
            }
            uint32_t bh[4][2], bl[4][2];
#pragma unroll
            for (int np = 0; np < 2; np++) {
                const uint32_t sw = SMEM_SWIZZLE_64B(
                    (uint32_t)((b_row + np * 16) * 64 + (b_kc + ks * 16) * 2));
                LDSM_X4(bh[2*np][0], bh[2*np][1], bh[2*np+1][0], bh[2*np+1][1],
                        sbase + GS_BHI + sw);
                if (TWO_B)
                    LDSM_X4(bl[2*np][0], bl[2*np][1], bl[2*np+1][0], bl[2*np+1][1],
                            sbase + GS_BLO + sw);
            }
#pragma unroll
            for (int mi = 0; mi < 4; mi++)
#pragma unroll
                for (int ni = 0; ni < 4; ni++) {
                    MMAF16(acc[mi][ni], ah[mi], bh[ni]);
                    if (TWO_B)
                        MMAF16(acc[mi][ni], ah[mi], bl[ni]);
                }
        }
    }

    // ---- epilogue
    const int erow = lane >> 2;
    const int ecol = (lane & 3) * 2;
#pragma unroll
    for (int ni = 0; ni < 4; ni++) {
        const int col = n0 + warp_n + ni * 8 + ecol;
        const float bv0 = __ldg(bias + col);
        const float bv1 = __ldg(bias + col + 1);
#pragma unroll
        for (int mi = 0; mi < 4; mi++) {
            const int row = m0 + warp_m + mi * 16 + erow;
            float v00 = (acc[mi][ni][0] + bv0) * scale;
            float v01 = (acc[mi][ni][1] + bv1) * scale;
            float v10 = (acc[mi][ni][2] + bv0) * scale;
            float v11 = (acc[mi][ni][3] + bv1) * scale;
            if (WMODE == 2) {
                *(uint32_t*)(Ch + (size_t)row * E_DIM + col)       = packh2(v00, v01);
                *(uint32_t*)(Cl + (size_t)row * E_DIM + col)       = packh2(hlo(v00), hlo(v01));
                *(uint32_t*)(Ch + (size_t)(row + 8) * E_DIM + col) = packh2(v10, v11);
                *(uint32_t*)(Cl + (size_t)(row + 8) * E_DIM + col) = packh2(hlo(v10), hlo(v11));
            } else if (WMODE == 3) {
                *(uint32_t*)(Ch + (size_t)row * E_DIM + col)       = packh2(v00, v01);
                *(uint32_t*)(Ch + (size_t)(row + 8) * E_DIM + col) = packh2(v10, v11);
            } else {
                float2 a = {v00, v01}, b = {v10, v11};
                *(float2*)(Cf + (size_t)row * E_DIM + col)       = a;
                *(float2*)(Cf + (size_t)(row + 8) * E_DIM + col) = b;
            }
        }
    }
}

// ---- fused Q/K/V projections: grid (8, 64, 3); z=0 uses only y<32
__global__ void __launch_bounds__(256, 2) gemm_qkv(
    const uint16_t* __restrict__ x1h, const uint16_t* __restrict__ x2h,
    const uint16_t* __restrict__ wqh, const uint16_t* __restrict__ wql,
    const uint16_t* __restrict__ wkh, const uint16_t* __restrict__ wkl,
    const uint16_t* __restrict__ wvh,
    const float* __restrict__ bq, const float* __restrict__ bk,
    const float* __restrict__ bv,
    uint16_t* __restrict__ qh,
    uint16_t* __restrict__ kh, uint16_t* __restrict__ kl,
    uint16_t* __restrict__ vh)
{
    extern __shared__ char smem[];
    const int z = blockIdx.z;
    if (z == 0 && blockIdx.y >= MQ / 128) return;
    if (z == 0) {
        gemm_body<3, true>(x1h, wqh, wql, bq, 0.125f, nullptr, qh, nullptr,
                           smem, blockIdx.y * 128, blockIdx.x * 128);
    } else if (z == 1) {
        gemm_body<2, true>(x2h, wkh, wkl, bk, 1.0f, nullptr, kh, kl,
                           smem, blockIdx.y * 128, blockIdx.x * 128);
    } else {
        gemm_body<3, false>(x2h, wvh, nullptr, bv, 1.0f, nullptr, vh, nullptr,
                            smem, blockIdx.y * 128, blockIdx.x * 128);
    }
}

// ---- output projection (fp32 out, single-B)
__global__ void __launch_bounds__(256, 2) gemm_out(
    const uint16_t* __restrict__ Ah,
    const uint16_t* __restrict__ Bh,
    const float* __restrict__ bias, float* __restrict__ Cf)
{
    extern __shared__ char smem[];
    gemm_body<0, false>(Ah, Bh, nullptr, bias, 1.0f, Cf, nullptr, nullptr,
                        smem, blockIdx.y * 128, blockIdx.x * 128);
}

// ---------------------------------------------------------------------------
// Flash attention v2 on fp16 HMMA.
//   S = Q*Kh + Q*Kl (2 MMAs); PV = P*V (1 MMA). fp32 acc + softmax.
// CTA = (b, h, 128 q rows); 8 warps x 16 q rows. KV chunk 64, double-buffered.
// ---------------------------------------------------------------------------
#define AS_Q    0          // 128 rows x 128B = 16KB (single fp16 plane)
#define AS_KV   16384      // stage base
#define AS_KHI  0
#define AS_KLO  8192
#define AS_V    16384
#define A_STAGE 24576
#define ATT_SMEM 65536     // 16KB Q + 2 x 24KB KV
#define NEG_BIG (-3.0e38f)

__global__ void __launch_bounds__(256, 2) attn_mma(
    const uint16_t* __restrict__ Qh,
    const uint16_t* __restrict__ Kh, const uint16_t* __restrict__ Kl,
    const uint16_t* __restrict__ Vh,
    uint16_t* __restrict__ Oh)
{
    extern __shared__ char smem[];
    const uint32_t sb = (uint32_t)__cvta_generic_to_shared(smem);
    const int b  = blockIdx.z;
    const int h  = blockIdx.y;
    const int q0 = blockIdx.x * 128;
    const int tid  = threadIdx.x;
    const int wid  = tid >> 5;
    const int lane = tid & 31;
    const int g = lane >> 3;
    const int r = lane & 7;

    // ---- Q tile 128x64 (single plane) via cp.async
#pragma unroll
    for (int it = 0; it < 4; it++) {
        const int idx = it * 256 + tid;
        const int row = idx >> 3;
        const int seg = idx & 7;
        const uint32_t sw = SMEM_SWIZZLE_128B((uint32_t)(row * 128 + seg * 16));
        const size_t gq = (size_t)(b * SQ + q0 + row) * E_DIM + h * H_DIM + seg * 8;
        CP_ASYNC16(sb + AS_Q + sw, (const char*)(Qh + gq));
    }
    CP_COMMIT();

    auto load_kv = [&](int stage, int c) {
        const uint32_t sbase = sb + AS_KV + stage * A_STAGE;
#pragma unroll
        for (int it = 0; it < 2; it++) {
            const int idx = it * 256 + tid;
            const int row = idx >> 3;
            const int seg = idx & 7;
            const uint32_t sw = SMEM_SWIZZLE_128B((uint32_t)(row * 128 + seg * 16));
            const size_t gk = (size_t)(b * SKV + c + row) * E_DIM + h * H_DIM + seg * 8;
            CP_ASYNC16(sbase + AS_KHI + sw, (const char*)(Kh + gk));
            CP_ASYNC16(sbase + AS_KLO + sw, (const char*)(Kl + gk));
            CP_ASYNC16(sbase + AS_V   + sw, (const char*)(Vh + gk));
        }
    };

    load_kv(0, 0);
    CP_COMMIT();
    CP_WAIT1();          // Q ready
    __syncthreads();

    // ---- persistent Q fragments
    const int a_row = wid * 16 + (g & 1) * 8 + r;
    const int a_kc  = (g >> 1) * 8;
    uint32_t qf[4][4];
#pragma unroll
    for (int ks = 0; ks < 4; ks++) {
        const uint32_t sw = SMEM_SWIZZLE_128B((uint32_t)(a_row * 128 + (a_kc + ks * 16) * 2));
        LDSM_X4(qf[ks][0], qf[ks][1], qf[ks][2], qf[ks][3], sb + AS_Q + sw);
    }

    float o[8][4];
#pragma unroll
    for (int na = 0; na < 8; na++)
#pragma unroll
        for (int q = 0; q < 4; q++) o[na][q] = 0.f;
    float mr0 = NEG_BIG, mr1 = NEG_BIG, lr0 = 0.f, lr1 = 0.f;

    const int kb_row = (g >> 1) * 8 + r;
    const int kb_kc  = (g & 1) * 8;

    const int NCH = SKV / 64;   // 32
    for (int cc = 0; cc < NCH; cc++) {
        const int buf = cc & 1;
        if (cc + 1 < NCH) { load_kv(buf ^ 1, (cc + 1) * 64); CP_COMMIT(); CP_WAIT1(); }
        else              { CP_WAIT0(); }
        __syncthreads();
        const uint32_t kvb = sb + AS_KV + buf * A_STAGE;

        // ---- S = Q K^T (fp16 x2)
        float s[8][4];
#pragma unroll
        for (int na = 0; na < 8; na++)
#pragma unroll
            for (int q = 0; q < 4; q++) s[na][q] = 0.f;

#pragma unroll
        for (int ks = 0; ks < 4; ks++) {
            uint32_t kh[8][2], kl[8][2];
#pragma unroll
            for (int np = 0; np < 4; np++) {
                const uint32_t sw = SMEM_SWIZZLE_128B(
                    (uint32_t)((np * 16 + kb_row) * 128 + (kb_kc + ks * 16) * 2));
                LDSM_X4(kh[2*np][0], kh[2*np][1], kh[2*np+1][0], kh[2*np+1][1],
                        kvb + AS_KHI + sw);
                LDSM_X4(kl[2*np][0], kl[2*np][1], kl[2*np+1][0], kl[2*np+1][1],
                        kvb + AS_KLO + sw);
            }
#pragma unroll
            for (int na = 0; na < 8; na++) {
                MMAF16(s[na], qf[ks], kh[na]);
                MMAF16(s[na], qf[ks], kl[na]);
            }
        }

        // ---- online softmax
        float mx0 = NEG_BIG, mx1 = NEG_BIG;
#pragma unroll
        for (int na = 0; na < 8; na++) {
            mx0 = fmaxf(mx0, fmaxf(s[na][0], s[na][1]));
            mx1 = fmaxf(mx1, fmaxf(s[na][2], s[na][3]));
        }
        mx0 = fmaxf(mx0, __shfl_xor_sync(0xffffffffu, mx0, 1));
        mx0 = fmaxf(mx0, __shfl_xor_sync(0xffffffffu, mx0, 2));
        mx1 = fmaxf(mx1, __shfl_xor_sync(0xffffffffu, mx1, 1));
        mx1 = fmaxf(mx1, __shfl_xor_sync(0xffffffffu, mx1, 2));
        const float mn0 = fmaxf(mr0, mx0);
        const float mn1 = fmaxf(mr1, mx1);
        const float al0 = __expf(mr0 - mn0);
        const float al1 = __expf(mr1 - mn1);
        mr0 = mn0; mr1 = mn1;
        float ls0 = 0.f, ls1 = 0.f;
#pragma unroll
        for (int na = 0; na < 8; na++) {
            s[na][0] = __expf(s[na][0] - mn0);
            s[na][1] = __expf(s[na][1] - mn0);
            s[na][2] = __expf(s[na][2] - mn1);
            s[na][3] = __expf(s[na][3] - mn1);
            ls0 += s[na][0] + s[na][1];
            ls1 += s[na][2] + s[na][3];
        }
        ls0 += __shfl_xor_sync(0xffffffffu, ls0, 1);
        ls0 += __shfl_xor_sync(0xffffffffu, ls0, 2);
        ls1 += __shfl_xor_sync(0xffffffffu, ls1, 1);
        ls1 += __shfl_xor_sync(0xffffffffu, ls1, 2);
        lr0 = lr0 * al0 + ls0;
        lr1 = lr1 * al1 + ls1;
#pragma unroll
        for (int na = 0; na < 8; na++) {
            o[na][0] *= al0; o[na][1] *= al0;
            o[na][2] *= al1; o[na][3] *= al1;
        }

        // ---- P @ V (fp16 x1)
#pragma unroll
        for (int kt = 0; kt < 4; kt++) {
            uint32_t ph[4];
            ph[0] = packh2(s[2*kt][0],   s[2*kt][1]);
            ph[1] = packh2(s[2*kt][2],   s[2*kt][3]);
            ph[2] = packh2(s[2*kt+1][0], s[2*kt+1][1]);
            ph[3] = packh2(s[2*kt+1][2], s[2*kt+1][3]);

            uint32_t vh[8][2];
#pragma unroll
            for (int dp = 0; dp < 4; dp++) {
                const uint32_t byte = (uint32_t)((kt * 16 + (lane & 15)) * 128
                                                 + dp * 32 + (lane >> 4) * 16);
                const uint32_t sw = SMEM_SWIZZLE_128B(byte);
                LDSM_X4_T(vh[2*dp][0], vh[2*dp][1], vh[2*dp+1][0], vh[2*dp+1][1],
                          kvb + AS_V + sw);
            }
#pragma unroll
            for (int na = 0; na < 8; na++) {
                MMAF16(o[na], ph, vh[na]);
            }
        }
        __syncthreads();
    }

    // ---- epilogue: normalize, write single fp16 plane
    const float inv0 = 1.f / lr0;
    const float inv1 = 1.f / lr1;
    const int row0 = q0 + wid * 16 + (lane >> 2);
#pragma unroll
    for (int na = 0; na < 8; na++) {
        const int col = h * H_DIM + na * 8 + (lane & 3) * 2;
        const size_t i0 = (size_t)(b * SQ + row0) * E_DIM + col;
        const size_t i1 = (size_t)(b * SQ + row0 + 8) * E_DIM + col;
        *(uint32_t*)(Oh + i0) = packh2(o[na][0] * inv0, o[na][1] * inv0);
        *(uint32_t*)(Oh + i1) = packh2(o[na][2] * inv1, o[na][3] * inv1);
    }
}

// ---------------------------------------------------------------------------
extern "C" void kernel_launch(void* const* d_in, const int* in_sizes, int n_in,
                              void* d_out, int out_size)
{
    const float* x1 = (const float*)d_in[0];
    const float* x2 = (const float*)d_in[1];
    const float* Wq = (const float*)d_in[2];
    const float* bq = (const float*)d_in[3];
    const float* Wk = (const float*)d_in[4];
    const float* bk = (const float*)d_in[5];
    const float* Wv = (const float*)d_in[6];
    const float* bv = (const float*)d_in[7];
    const float* Wo = (const float*)d_in[8];
    const float* bo = (const float*)d_in[9];
    float* out = (float*)d_out;

    uint16_t *x1h, *x2h;
    uint16_t *wqh, *wql, *wkh, *wkl, *wvh, *woh;
    uint16_t *qh, *kh, *kl, *vh, *ah;
    cudaGetSymbolAddress((void**)&x1h, g_x1h);
    cudaGetSymbolAddress((void**)&x2h, g_x2h);
    cudaGetSymbolAddress((void**)&wqh, g_wqh); cudaGetSymbolAddress((void**)&wql, g_wql);
    cudaGetSymbolAddress((void**)&wkh, g_wkh); cudaGetSymbolAddress((void**)&wkl, g_wkl);
    cudaGetSymbolAddress((void**)&wvh, g_wvh);
    cudaGetSymbolAddress((void**)&woh, g_woh);
    cudaGetSymbolAddress((void**)&qh,  g_qh);
    cudaGetSymbolAddress((void**)&kh,  g_kh);  cudaGetSymbolAddress((void**)&kl,  g_kl);
    cudaGetSymbolAddress((void**)&vh,  g_vh);
    cudaGetSymbolAddress((void**)&ah,  g_ah);

    cudaFuncSetAttribute(gemm_qkv, cudaFuncAttributeMaxDynamicSharedMemorySize, G_SMEM);
    cudaFuncSetAttribute(gemm_out, cudaFuncAttributeMaxDynamicSharedMemorySize, G_SMEM);
    cudaFuncSetAttribute(attn_mma, cudaFuncAttributeMaxDynamicSharedMemorySize, ATT_SMEM);

    dim3 blk(256);

    // ---- stage 1: all plane conversions, one launch
    cvt_all<<<dim3(MKV * E_DIM / 8 / 256, 6), blk>>>(
        x1, x2, Wq, Wk, Wv, Wo,
        x1h, x2h,
        wqh, wql, wkh, wkl, wvh, woh);

    // ---- stage 2: fused Q/K/V projections, one launch
    gemm_qkv<<<dim3(8, MKV / 128, 3), blk, G_SMEM>>>(
        x1h, x2h,
        wqh, wql, wkh, wkl, wvh,
        bq, bk, bv,
        qh, kh, kl, vh);

    // ---- stage 3: attention
    attn_mma<<<dim3(SQ / 128, N_HEADS, BATCH), blk, ATT_SMEM>>>(
        qh, kh, kl, vh, ah);

    // ---- stage 4: output projection (fp32 out)
    gemm_out<<<dim3(8, MQ / 128), blk, G_SMEM>>>(ah, woh, bo, out);
}

// round 12
// speedup vs baseline: 7.8952x; 1.2342x over previous
#include <cuda_runtime.h>
#include <cuda_fp16.h>
#include <cstdint>
#include <math.h>

// Problem constants
#define E_DIM   1024
#define N_HEADS 16
#define H_DIM   64
#define BATCH   4
#define SQ      1024
#define SKV     2048
#define MQ      (BATCH * SQ)    // 4096
#define MKV     (BATCH * SKV)   // 8192

// ---------------------------------------------------------------------------
// Persistent planes (device globals). All fp16.
//   x1,x2: single plane   Wq: hi/lo   Wk,Wv,Wo: single plane
//   Q: single (pre-scaled 1/8)   K: single   V: single
//   attn out: single plane
// ---------------------------------------------------------------------------
__device__ __align__(16) uint16_t g_x1h[MQ * E_DIM];
__device__ __align__(16) uint16_t g_x2h[MKV * E_DIM];
__device__ __align__(16) uint16_t g_wqh[E_DIM * E_DIM], g_wql[E_DIM * E_DIM];
__device__ __align__(16) uint16_t g_wkh[E_DIM * E_DIM];
__device__ __align__(16) uint16_t g_wvh[E_DIM * E_DIM];
__device__ __align__(16) uint16_t g_woh[E_DIM * E_DIM];
__device__ __align__(16) uint16_t g_qh[MQ * E_DIM];
__device__ __align__(16) uint16_t g_kh[MKV * E_DIM];
__device__ __align__(16) uint16_t g_vh[MKV * E_DIM];
__device__ __align__(16) uint16_t g_ah[MQ * E_DIM];

// ---------------------------------------------------------------------------
// Helpers
// ---------------------------------------------------------------------------
#define SMEM_SWIZZLE_128B(off) ((off) ^ (((off) >> 3) & 0x70))
#define SMEM_SWIZZLE_64B(off)  ((off) ^ (((off) >> 3) & 0x30))

#define LDSM_X4(r0_,r1_,r2_,r3_,addr_) \
    asm volatile("ldmatrix.sync.aligned.m8n8.x4.shared.b16 {%0,%1,%2,%3}, [%4];" \
        : "=r"(r0_), "=r"(r1_), "=r"(r2_), "=r"(r3_) : "r"(addr_))

#define LDSM_X4_T(r0_,r1_,r2_,r3_,addr_) \
    asm volatile("ldmatrix.sync.aligned.m8n8.x4.trans.shared.b16 {%0,%1,%2,%3}, [%4];" \
        : "=r"(r0_), "=r"(r1_), "=r"(r2_), "=r"(r3_) : "r"(addr_))

#define MMAF16(d_,a_,b_) \
    asm volatile("mma.sync.aligned.m16n8k16.row.col.f32.f16.f16.f32 " \
        "{%0,%1,%2,%3}, {%4,%5,%6,%7}, {%8,%9}, {%0,%1,%2,%3};" \
        : "+f"((d_)[0]), "+f"((d_)[1]), "+f"((d_)[2]), "+f"((d_)[3]) \
        : "r"((a_)[0]), "r"((a_)[1]), "r"((a_)[2]), "r"((a_)[3]), \
          "r"((b_)[0]), "r"((b_)[1]))

#define CP_ASYNC16(dst_, src_) \
    asm volatile("cp.async.cg.shared.global [%0], [%1], 16;" \
        :: "r"(dst_), "l"(src_))
#define CP_COMMIT() asm volatile("cp.async.commit_group;" ::: "memory")
#define CP_WAIT2()  asm volatile("cp.async.wait_group 2;" ::: "memory")
#define CP_WAIT1()  asm volatile("cp.async.wait_group 1;" ::: "memory")
#define CP_WAIT0()  asm volatile("cp.async.wait_group 0;" ::: "memory")

__device__ __forceinline__ uint32_t packh2(float x, float y) {
    __half2 t = __floats2half2_rn(x, y);
    return *(uint32_t*)&t;
}
__device__ __forceinline__ float hlo(float v) {
    return v - __half2float(__float2half_rn(v));
}

// fp16 hi/lo split of 8 floats
__device__ __forceinline__ void cvt8h(const float4 f0, const float4 f1,
                                      uint4& hi, uint4& lo) {
    float v[8] = {f0.x, f0.y, f0.z, f0.w, f1.x, f1.y, f1.z, f1.w};
    uint32_t h[8], l[8];
#pragma unroll
    for (int i = 0; i < 8; i++) {
        __half hb = __float2half_rn(v[i]);
        float hf = __half2float(hb);
        __half lb = __float2half_rn(v[i] - hf);
        h[i] = *(unsigned short*)&hb;
        l[i] = *(unsigned short*)&lb;
    }
    hi.x = h[0] | (h[1] << 16); hi.y = h[2] | (h[3] << 16);
    hi.z = h[4] | (h[5] << 16); hi.w = h[6] | (h[7] << 16);
    lo.x = l[0] | (l[1] << 16); lo.y = l[2] | (l[3] << 16);
    lo.z = l[4] | (l[5] << 16); lo.w = l[6] | (l[7] << 16);
}

// ---------------------------------------------------------------------------
// ALL fp32 -> plane conversions in ONE launch.
// m=2: Wq -> hi/lo.  all others -> single fp16 plane.
// ---------------------------------------------------------------------------
__global__ void __launch_bounds__(256) cvt_all(
    const float* __restrict__ x1, const float* __restrict__ x2,
    const float* __restrict__ w0, const float* __restrict__ w1,
    const float* __restrict__ w2, const float* __restrict__ w3,
    uint16_t* __restrict__ x1h, uint16_t* __restrict__ x2h,
    uint16_t* __restrict__ h0, uint16_t* __restrict__ l0,
    uint16_t* __restrict__ h1, uint16_t* __restrict__ h2,
    uint16_t* __restrict__ h3)
{
    const int m = blockIdx.y;
    const int idx = blockIdx.x * 256 + threadIdx.x;
    if (m != 2) {
        const float* in; uint16_t* hi; int n8;
        switch (m) {
            case 0: in = x1; hi = x1h; n8 = MQ  * E_DIM / 8; break;
            case 1: in = x2; hi = x2h; n8 = MKV * E_DIM / 8; break;
            case 3: in = w1; hi = h1;  n8 = E_DIM * E_DIM / 8; break;
            case 4: in = w2; hi = h2;  n8 = E_DIM * E_DIM / 8; break;
            default:in = w3; hi = h3;  n8 = E_DIM * E_DIM / 8; break;
        }
        if (idx >= n8) return;
        const float4 f0 = ((const float4*)in)[2 * idx];
        const float4 f1 = ((const float4*)in)[2 * idx + 1];
        uint4 h;
        h.x = packh2(f0.x, f0.y); h.y = packh2(f0.z, f0.w);
        h.z = packh2(f1.x, f1.y); h.w = packh2(f1.z, f1.w);
        ((uint4*)hi)[idx] = h;
        return;
    }
    if (idx >= E_DIM * E_DIM / 8) return;
    const float4 f0 = ((const float4*)w0)[2 * idx];
    const float4 f1 = ((const float4*)w0)[2 * idx + 1];
    uint4 h, l;
    cvt8h(f0, f1, h, l);
    ((uint4*)h0)[idx] = h;
    ((uint4*)l0)[idx] = l;
}

// ---------------------------------------------------------------------------
// fp16 HMMA GEMM body. TWO_B: B hi/lo (2 MMAs/k-step) or single (1 MMA).
// 4-stage cp.async ring, 24KB/stage, 96KB smem, 2 CTAs/SM.
// wmode: 0 = fp32 out, 3 = fp16 single plane
// ---------------------------------------------------------------------------
#define GS_A    0
#define GS_BHI  8192
#define GS_BLO  16384
#define G_STAGE 24576
#define G_SMEM  98304       // 4 stages
#define G_NCHUNK 32

template<int WMODE, bool TWO_B>
__device__ __forceinline__ void gemm_body(
    const uint16_t* __restrict__ Ah,
    const uint16_t* __restrict__ Bh, const uint16_t* __restrict__ Bl,
    const float* __restrict__ bias, float scale,
    float* __restrict__ Cf, uint16_t* __restrict__ Ch,
    char* smem, const int m0, const int n0)
{
    const uint32_t sb = (uint32_t)__cvta_generic_to_shared(smem);
    const int tid  = threadIdx.x;
    const int wid  = tid >> 5;
    const int lane = tid & 31;

    const int warp_m = (wid & 1) * 64;
    const int warp_n = (wid >> 1) * 32;
    const int g = lane >> 3;
    const int r = lane & 7;

    float acc[4][4][4];
#pragma unroll
    for (int mi = 0; mi < 4; mi++)
#pragma unroll
        for (int ni = 0; ni < 4; ni++)
#pragma unroll
            for (int q = 0; q < 4; q++) acc[mi][ni][q] = 0.f;

    const int a_row = warp_m + (g & 1) * 8 + r;
    const int a_kc  = (g >> 1) * 8;
    const int b_row = warp_n + (g >> 1) * 8 + r;
    const int b_kc  = (g & 1) * 8;

    auto load_stage = [&](int stage, int ch) {
        const uint32_t sbase = sb + stage * G_STAGE;
#pragma unroll
        for (int it = 0; it < 2; it++) {
            const int idx = it * 256 + tid;     // 0..511
            const int row = idx >> 2;           // 0..127
            const int seg = idx & 3;            // 16B segment
            const uint32_t sw = SMEM_SWIZZLE_64B((uint32_t)(row * 64 + seg * 16));
            const size_t ga = (size_t)(m0 + row) * E_DIM + ch * 32 + seg * 8;
            const size_t gb = (size_t)(n0 + row) * E_DIM + ch * 32 + seg * 8;
            CP_ASYNC16(sbase + GS_A   + sw, (const char*)(Ah + ga));
            CP_ASYNC16(sbase + GS_BHI + sw, (const char*)(Bh + gb));
            if (TWO_B)
                CP_ASYNC16(sbase + GS_BLO + sw, (const char*)(Bl + gb));
        }
    };

    load_stage(0, 0); CP_COMMIT();
    load_stage(1, 1); CP_COMMIT();
    load_stage(2, 2); CP_COMMIT();

    for (int ch = 0; ch < G_NCHUNK; ch++) {
        if (ch < G_NCHUNK - 2) CP_WAIT2(); else CP_WAIT0();
        __syncthreads();
        if (ch + 3 < G_NCHUNK) { load_stage((ch + 3) & 3, ch + 3); CP_COMMIT(); }

        const uint32_t sbase = sb + (ch & 3) * G_STAGE;
#pragma unroll
        for (int ks = 0; ks < 2; ks++) {
            uint32_t ah[4][4];
#pragma unroll
            for (int mi = 0; mi < 4; mi++) {
                const uint32_t sw = SMEM_SWIZZLE_64B(
                    (uint32_t)((a_row + mi * 16) * 64 + (a_kc + ks * 16) * 2));
                LDSM_X4(ah[mi][0], ah[mi][1], ah[mi][2], ah[mi][3], sbase + GS_A + sw);
            }
            uint32_t bh[4][2], bl[4][2];
#pragma unroll
            for (int np = 0; np < 2; np++) {
                const uint32_t sw = SMEM_SWIZZLE_64B(
                    (uint32_t)((b_row + np * 16) * 64 + (b_kc + ks * 16) * 2));
                LDSM_X4(bh[2*np][0], bh[2*np][1], bh[2*np+1][0], bh[2*np+1][1],
                        sbase + GS_BHI + sw);
                if (TWO_B)
                    LDSM_X4(bl[2*np][0], bl[2*np][1], bl[2*np+1][0], bl[2*np+1][1],
                            sbase + GS_BLO + sw);
            }
#pragma unroll
            for (int mi = 0; mi < 4; mi++)
#pragma unroll
                for (int ni = 0; ni < 4; ni++) {
                    MMAF16(acc[mi][ni], ah[mi], bh[ni]);
                    if (TWO_B)
                        MMAF16(acc[mi][ni], ah[mi], bl[ni]);
                }
        }
    }

    // ---- epilogue
    const int erow = lane >> 2;
    const int ecol = (lane & 3) * 2;
#pragma unroll
    for (int ni = 0; ni < 4; ni++) {
        const int col = n0 + warp_n + ni * 8 + ecol;
        const float bv0 = __ldg(bias + col);
        const float bv1 = __ldg(bias + col + 1);
#pragma unroll
        for (int mi = 0; mi < 4; mi++) {
            const int row = m0 + warp_m + mi * 16 + erow;
            float v00 = (acc[mi][ni][0] + bv0) * scale;
            float v01 = (acc[mi][ni][1] + bv1) * scale;
            float v10 = (acc[mi][ni][2] + bv0) * scale;
            float v11 = (acc[mi][ni][3] + bv1) * scale;
            if (WMODE == 3) {
                *(uint32_t*)(Ch + (size_t)row * E_DIM + col)       = packh2(v00, v01);
                *(uint32_t*)(Ch + (size_t)(row + 8) * E_DIM + col) = packh2(v10, v11);
            } else {
                float2 a = {v00, v01}, b = {v10, v11};
                *(float2*)(Cf + (size_t)row * E_DIM + col)       = a;
                *(float2*)(Cf + (size_t)(row + 8) * E_DIM + col) = b;
            }
        }
    }
}

// ---- fused Q/K/V projections: grid (8, 64, 3); z=0 uses only y<32
__global__ void __launch_bounds__(256, 2) gemm_qkv(
    const uint16_t* __restrict__ x1h, const uint16_t* __restrict__ x2h,
    const uint16_t* __restrict__ wqh, const uint16_t* __restrict__ wql,
    const uint16_t* __restrict__ wkh, const uint16_t* __restrict__ wvh,
    const float* __restrict__ bq, const float* __restrict__ bk,
    const float* __restrict__ bv,
    uint16_t* __restrict__ qh, uint16_t* __restrict__ kh,
    uint16_t* __restrict__ vh)
{
    extern __shared__ char smem[];
    const int z = blockIdx.z;
    if (z == 0 && blockIdx.y >= MQ / 128) return;
    if (z == 0) {
        gemm_body<3, true>(x1h, wqh, wql, bq, 0.125f, nullptr, qh,
                           smem, blockIdx.y * 128, blockIdx.x * 128);
    } else if (z == 1) {
        gemm_body<3, false>(x2h, wkh, nullptr, bk, 1.0f, nullptr, kh,
                            smem, blockIdx.y * 128, blockIdx.x * 128);
    } else {
        gemm_body<3, false>(x2h, wvh, nullptr, bv, 1.0f, nullptr, vh,
                            smem, blockIdx.y * 128, blockIdx.x * 128);
    }
}

// ---- output projection (fp32 out, single-B)
__global__ void __launch_bounds__(256, 2) gemm_out(
    const uint16_t* __restrict__ Ah,
    const uint16_t* __restrict__ Bh,
    const float* __restrict__ bias, float* __restrict__ Cf)
{
    extern __shared__ char smem[];
    gemm_body<0, false>(Ah, Bh, nullptr, bias, 1.0f, Cf, nullptr,
                        smem, blockIdx.y * 128, blockIdx.x * 128);
}

// ---------------------------------------------------------------------------
// Flash attention v2 on fp16 HMMA. All operands single fp16 planes:
//   S = Q*K (1 MMA); PV = P*V (1 MMA). fp32 acc + softmax.
// CTA = (b, h, 128 q rows); 8 warps x 16 q rows. KV chunk 64, double-buffered.
// ---------------------------------------------------------------------------
#define AS_Q    0          // 128 rows x 128B = 16KB
#define AS_KV   16384      // stage base
#define AS_K    0
#define AS_V    8192
#define A_STAGE 16384
#define ATT_SMEM 49152     // 16KB Q + 2 x 16KB KV
#define NEG_BIG (-3.0e38f)

__global__ void __launch_bounds__(256, 2) attn_mma(
    const uint16_t* __restrict__ Qh,
    const uint16_t* __restrict__ Kh,
    const uint16_t* __restrict__ Vh,
    uint16_t* __restrict__ Oh)
{
    extern __shared__ char smem[];
    const uint32_t sb = (uint32_t)__cvta_generic_to_shared(smem);
    const int b  = blockIdx.z;
    const int h  = blockIdx.y;
    const int q0 = blockIdx.x * 128;
    const int tid  = threadIdx.x;
    const int wid  = tid >> 5;
    const int lane = tid & 31;
    const int g = lane >> 3;
    const int r = lane & 7;

    // ---- Q tile 128x64 via cp.async
#pragma unroll
    for (int it = 0; it < 4; it++) {
        const int idx = it * 256 + tid;
        const int row = idx >> 3;
        const int seg = idx & 7;
        const uint32_t sw = SMEM_SWIZZLE_128B((uint32_t)(row * 128 + seg * 16));
        const size_t gq = (size_t)(b * SQ + q0 + row) * E_DIM + h * H_DIM + seg * 8;
        CP_ASYNC16(sb + AS_Q + sw, (const char*)(Qh + gq));
    }
    CP_COMMIT();

    auto load_kv = [&](int stage, int c) {
        const uint32_t sbase = sb + AS_KV + stage * A_STAGE;
#pragma unroll
        for (int it = 0; it < 2; it++) {
            const int idx = it * 256 + tid;
            const int row = idx >> 3;
            const int seg = idx & 7;
            const uint32_t sw = SMEM_SWIZZLE_128B((uint32_t)(row * 128 + seg * 16));
            const size_t gk = (size_t)(b * SKV + c + row) * E_DIM + h * H_DIM + seg * 8;
            CP_ASYNC16(sbase + AS_K + sw, (const char*)(Kh + gk));
            CP_ASYNC16(sbase + AS_V + sw, (const char*)(Vh + gk));
        }
    };

    load_kv(0, 0);
    CP_COMMIT();
    CP_WAIT1();          // Q ready
    __syncthreads();

    // ---- persistent Q fragments
    const int a_row = wid * 16 + (g & 1) * 8 + r;
    const int a_kc  = (g >> 1) * 8;
    uint32_t qf[4][4];
#pragma unroll
    for (int ks = 0; ks < 4; ks++) {
        const uint32_t sw = SMEM_SWIZZLE_128B((uint32_t)(a_row * 128 + (a_kc + ks * 16) * 2));
        LDSM_X4(qf[ks][0], qf[ks][1], qf[ks][2], qf[ks][3], sb + AS_Q + sw);
    }

    float o[8][4];
#pragma unroll
    for (int na = 0; na < 8; na++)
#pragma unroll
        for (int q = 0; q < 4; q++) o[na][q] = 0.f;
    float mr0 = NEG_BIG, mr1 = NEG_BIG, lr0 = 0.f, lr1 = 0.f;

    const int kb_row = (g >> 1) * 8 + r;
    const int kb_kc  = (g & 1) * 8;

    const int NCH = SKV / 64;   // 32
    for (int cc = 0; cc < NCH; cc++) {
        const int buf = cc & 1;
        if (cc + 1 < NCH) { load_kv(buf ^ 1, (cc + 1) * 64); CP_COMMIT(); CP_WAIT1(); }
        else              { CP_WAIT0(); }
        __syncthreads();
        const uint32_t kvb = sb + AS_KV + buf * A_STAGE;

        // ---- S = Q K^T (fp16 x1)
        float s[8][4];
#pragma unroll
        for (int na = 0; na < 8; na++)
#pragma unroll
            for (int q = 0; q < 4; q++) s[na][q] = 0.f;

#pragma unroll
        for (int ks = 0; ks < 4; ks++) {
            uint32_t kf[8][2];
#pragma unroll
            for (int np = 0; np < 4; np++) {
                const uint32_t sw = SMEM_SWIZZLE_128B(
                    (uint32_t)((np * 16 + kb_row) * 128 + (kb_kc + ks * 16) * 2));
                LDSM_X4(kf[2*np][0], kf[2*np][1], kf[2*np+1][0], kf[2*np+1][1],
                        kvb + AS_K + sw);
            }
#pragma unroll
            for (int na = 0; na < 8; na++) {
                MMAF16(s[na], qf[ks], kf[na]);
            }
        }

        // ---- online softmax
        float mx0 = NEG_BIG, mx1 = NEG_BIG;
#pragma unroll
        for (int na = 0; na < 8; na++) {
            mx0 = fmaxf(mx0, fmaxf(s[na][0], s[na][1]));
            mx1 = fmaxf(mx1, fmaxf(s[na][2], s[na][3]));
        }
        mx0 = fmaxf(mx0, __shfl_xor_sync(0xffffffffu, mx0, 1));
        mx0 = fmaxf(mx0, __shfl_xor_sync(0xffffffffu, mx0, 2));
        mx1 = fmaxf(mx1, __shfl_xor_sync(0xffffffffu, mx1, 1));
        mx1 = fmaxf(mx1, __shfl_xor_sync(0xffffffffu, mx1, 2));
        const float mn0 = fmaxf(mr0, mx0);
        const float mn1 = fmaxf(mr1, mx1);
        const float al0 = __expf(mr0 - mn0);
        const float al1 = __expf(mr1 - mn1);
        mr0 = mn0; mr1 = mn1;
        float ls0 = 0.f, ls1 = 0.f;
#pragma unroll
        for (int na = 0; na < 8; na++) {
            s[na][0] = __expf(s[na][0] - mn0);
            s[na][1] = __expf(s[na][1] - mn0);
            s[na][2] = __expf(s[na][2] - mn1);
            s[na][3] = __expf(s[na][3] - mn1);
            ls0 += s[na][0] + s[na][1];
            ls1 += s[na][2] + s[na][3];
        }
        ls0 += __shfl_xor_sync(0xffffffffu, ls0, 1);
        ls0 += __shfl_xor_sync(0xffffffffu, ls0, 2);
        ls1 += __shfl_xor_sync(0xffffffffu, ls1, 1);
        ls1 += __shfl_xor_sync(0xffffffffu, ls1, 2);
        lr0 = lr0 * al0 + ls0;
        lr1 = lr1 * al1 + ls1;
#pragma unroll
        for (int na = 0; na < 8; na++) {
            o[na][0] *= al0; o[na][1] *= al0;
            o[na][2] *= al1; o[na][3] *= al1;
        }

        // ---- P @ V (fp16 x1)
#pragma unroll
        for (int kt = 0; kt < 4; kt++) {
            uint32_t ph[4];
            ph[0] = packh2(s[2*kt][0],   s[2*kt][1]);
            ph[1] = packh2(s[2*kt][2],   s[2*kt][3]);
            ph[2] = packh2(s[2*kt+1][0], s[2*kt+1][1]);
            ph[3] = packh2(s[2*kt+1][2], s[2*kt+1][3]);

            uint32_t vf[8][2];
#pragma unroll
            for (int dp = 0; dp < 4; dp++) {
                const uint32_t byte = (uint32_t)((kt * 16 + (lane & 15)) * 128
                                                 + dp * 32 + (lane >> 4) * 16);
                const uint32_t sw = SMEM_SWIZZLE_128B(byte);
                LDSM_X4_T(vf[2*dp][0], vf[2*dp][1], vf[2*dp+1][0], vf[2*dp+1][1],
                          kvb + AS_V + sw);
            }
#pragma unroll
            for (int na = 0; na < 8; na++) {
                MMAF16(o[na], ph, vf[na]);
            }
        }
        __syncthreads();
    }

    // ---- epilogue: normalize, write single fp16 plane
    const float inv0 = 1.f / lr0;
    const float inv1 = 1.f / lr1;
    const int row0 = q0 + wid * 16 + (lane >> 2);
#pragma unroll
    for (int na = 0; na < 8; na++) {
        const int col = h * H_DIM + na * 8 + (lane & 3) * 2;
        const size_t i0 = (size_t)(b * SQ + row0) * E_DIM + col;
        const size_t i1 = (size_t)(b * SQ + row0 + 8) * E_DIM + col;
        *(uint32_t*)(Oh + i0) = packh2(o[na][0] * inv0, o[na][1] * inv0);
        *(uint32_t*)(Oh + i1) = packh2(o[na][2] * inv1, o[na][3] * inv1);
    }
}

// ---------------------------------------------------------------------------
extern "C" void kernel_launch(void* const* d_in, const int* in_sizes, int n_in,
                              void* d_out, int out_size)
{
    const float* x1 = (const float*)d_in[0];
    const float* x2 = (const float*)d_in[1];
    const float* Wq = (const float*)d_in[2];
    const float* bq = (const float*)d_in[3];
    const float* Wk = (const float*)d_in[4];
    const float* bk = (const float*)d_in[5];
    const float* Wv = (const float*)d_in[6];
    const float* bv = (const float*)d_in[7];
    const float* Wo = (const float*)d_in[8];
    const float* bo = (const float*)d_in[9];
    float* out = (float*)d_out;

    uint16_t *x1h, *x2h;
    uint16_t *wqh, *wql, *wkh, *wvh, *woh;
    uint16_t *qh, *kh, *vh, *ah;
    cudaGetSymbolAddress((void**)&x1h, g_x1h);
    cudaGetSymbolAddress((void**)&x2h, g_x2h);
    cudaGetSymbolAddress((void**)&wqh, g_wqh); cudaGetSymbolAddress((void**)&wql, g_wql);
    cudaGetSymbolAddress((void**)&wkh, g_wkh);
    cudaGetSymbolAddress((void**)&wvh, g_wvh);
    cudaGetSymbolAddress((void**)&woh, g_woh);
    cudaGetSymbolAddress((void**)&qh,  g_qh);
    cudaGetSymbolAddress((void**)&kh,  g_kh);
    cudaGetSymbolAddress((void**)&vh,  g_vh);
    cudaGetSymbolAddress((void**)&ah,  g_ah);

    cudaFuncSetAttribute(gemm_qkv, cudaFuncAttributeMaxDynamicSharedMemorySize, G_SMEM);
    cudaFuncSetAttribute(gemm_out, cudaFuncAttributeMaxDynamicSharedMemorySize, G_SMEM);
    cudaFuncSetAttribute(attn_mma, cudaFuncAttributeMaxDynamicSharedMemorySize, ATT_SMEM);

    dim3 blk(256);

    // ---- stage 1: all plane conversions, one launch
    cvt_all<<<dim3(MKV * E_DIM / 8 / 256, 6), blk>>>(
        x1, x2, Wq, Wk, Wv, Wo,
        x1h, x2h,
        wqh, wql, wkh, wvh, woh);

    // ---- stage 2: fused Q/K/V projections, one launch
    gemm_qkv<<<dim3(8, MKV / 128, 3), blk, G_SMEM>>>(
        x1h, x2h,
        wqh, wql, wkh, wvh,
        bq, bk, bv,
        qh, kh, vh);

    // ---- stage 3: attention
    attn_mma<<<dim3(SQ / 128, N_HEADS, BATCH), blk, ATT_SMEM>>>(
        qh, kh, vh, ah);

    // ---- stage 4: output projection (fp32 out)
    gemm_out<<<dim3(8, MQ / 128), blk, G_SMEM>>>(ah, woh, bo, out);
}